// round 2
// baseline (speedup 1.0000x reference)
#include <cuda_runtime.h>
#include <cstddef>

// ---------------- problem constants ----------------
#define NTOK 10992          // B*SN = 2*5496
#define DIMM 1024
#define HIDD 4096
#define LRATE 0.1f
#define NS_A 3.4445f
#define NS_B (-4.7750f)
#define NS_C 2.0315f

typedef unsigned long long u64;

// ---------------- device scratch (no allocs allowed) ----------------
__device__ float g_qkv[(size_t)NTOK * 3 * DIMM];   // [NTOK, 3072]  q|k|v
__device__ float g_kg [(size_t)NTOK * HIDD];       // k@G / dkg / q@G
__device__ float g_kv [(size_t)NTOK * HIDD];       // k@V / dkv / q@V
__device__ float g_h  [(size_t)NTOK * HIDD];       // h / dh
__device__ float g_r  [(size_t)NTOK * DIMM];       // pred-v / h@P
__device__ float g_G  [DIMM * HIDD];
__device__ float g_V  [DIMM * HIDD];
__device__ float g_P  [HIDD * DIMM];
__device__ float g_gG [DIMM * HIDD];
__device__ float g_gV [DIMM * HIDD];
__device__ float g_gP [HIDD * DIMM];
__device__ float g_X1 [DIMM * HIDD];
__device__ float g_X2 [DIMM * HIDD];
__device__ float g_Am [DIMM * DIMM];
__device__ float g_A2 [DIMM * DIMM];
__device__ double g_nrm[1];

// ---------------- generic SGEMM: C = alpha*op(A)op(B) + beta*E ----------------
// TA: A stored [K,M] (we use A^T). TB: B stored [N,K] (we use B^T).
// Requirements: K % 8 == 0, N % 128 == 0; M may be ragged.
template<bool TA, bool TB>
__global__ void __launch_bounds__(256, 2) gemm_k(
    const float* __restrict__ A, int lda,
    const float* __restrict__ B, int ldb,
    float* __restrict__ C, int ldc,
    const float* __restrict__ E, int ldE,
    float alpha, float beta, int M, int N, int K)
{
    __shared__ float As[2][8][128];
    __shared__ float Bs[2][8][128];
    const int tid = threadIdx.x;
    const int m0 = blockIdx.y * 128;
    const int n0 = blockIdx.x * 128;
    const int tx = tid & 15;
    const int ty = tid >> 4;

    // load-index precompute
    const int a_i0 = TA ? (tid >> 5) : (tid >> 1);               // TA: kk ; NN: mm
    const int a_i1 = TA ? ((tid & 31) << 2) : ((tid & 1) << 2);  // TA: mg ; NN: kq
    const int b_i0 = TB ? (tid >> 1) : (tid >> 5);               // TB: nn ; NN: kk
    const int b_i1 = TB ? ((tid & 1) << 2) : ((tid & 31) << 2);  // TB: kq ; NN: ng

    float ra[4], rb[4];

#define GK_FETCH(k0) do {                                                          \
    if (!TA) {                                                                     \
        int m_ = m0 + a_i0;                                                        \
        if (m_ < M) {                                                              \
            float4 v_ = *reinterpret_cast<const float4*>(A + (size_t)m_*lda + (k0) + a_i1); \
            ra[0]=v_.x; ra[1]=v_.y; ra[2]=v_.z; ra[3]=v_.w;                        \
        } else { ra[0]=0.f; ra[1]=0.f; ra[2]=0.f; ra[3]=0.f; }                     \
    } else {                                                                       \
        int m_ = m0 + a_i1;                                                        \
        if (m_ + 3 < M) {                                                          \
            float4 v_ = *reinterpret_cast<const float4*>(A + (size_t)((k0)+a_i0)*lda + m_); \
            ra[0]=v_.x; ra[1]=v_.y; ra[2]=v_.z; ra[3]=v_.w;                        \
        } else {                                                                   \
            for (int t_=0;t_<4;t_++) ra[t_] = (m_+t_ < M) ? A[(size_t)((k0)+a_i0)*lda + m_ + t_] : 0.f; \
        }                                                                          \
    }                                                                              \
    if (!TB) {                                                                     \
        float4 v_ = *reinterpret_cast<const float4*>(B + (size_t)((k0)+b_i0)*ldb + n0 + b_i1); \
        rb[0]=v_.x; rb[1]=v_.y; rb[2]=v_.z; rb[3]=v_.w;                            \
    } else {                                                                       \
        float4 v_ = *reinterpret_cast<const float4*>(B + (size_t)(n0 + b_i0)*ldb + (k0) + b_i1); \
        rb[0]=v_.x; rb[1]=v_.y; rb[2]=v_.z; rb[3]=v_.w;                            \
    }                                                                              \
} while (0)

#define GK_STORE(bf) do {                                                          \
    if (!TA) { for (int t_=0;t_<4;t_++) As[bf][a_i1+t_][a_i0] = ra[t_]; }          \
    else     { for (int t_=0;t_<4;t_++) As[bf][a_i0][a_i1+t_] = ra[t_]; }          \
    if (!TB) { for (int t_=0;t_<4;t_++) Bs[bf][b_i0][b_i1+t_] = rb[t_]; }          \
    else     { for (int t_=0;t_<4;t_++) Bs[bf][b_i1+t_][b_i0] = rb[t_]; }          \
} while (0)

    // packed f32x2 accumulators: acc[i][j] holds columns (2j, 2j+1) of row i
    u64 acc[8][4];
#pragma unroll
    for (int i = 0; i < 8; i++)
#pragma unroll
        for (int j = 0; j < 4; j++) acc[i][j] = 0ull;

    const int KT = K >> 3;
    GK_FETCH(0);
    GK_STORE(0);
    __syncthreads();

    int buf = 0;
    for (int kt = 0; kt < KT; ++kt) {
        if (kt + 1 < KT) GK_FETCH((kt + 1) << 3);
#pragma unroll
        for (int kk = 0; kk < 8; ++kk) {
            float4 a0 = *reinterpret_cast<const float4*>(&As[buf][kk][ty << 3]);
            float4 a1 = *reinterpret_cast<const float4*>(&As[buf][kk][(ty << 3) + 4]);
            float4 b0 = *reinterpret_cast<const float4*>(&Bs[buf][kk][tx << 3]);
            float4 b1 = *reinterpret_cast<const float4*>(&Bs[buf][kk][(tx << 3) + 4]);
            u64 bp0, bp1, bp2, bp3;
            asm("mov.b64 %0,{%1,%2};" : "=l"(bp0) : "f"(b0.x), "f"(b0.y));
            asm("mov.b64 %0,{%1,%2};" : "=l"(bp1) : "f"(b0.z), "f"(b0.w));
            asm("mov.b64 %0,{%1,%2};" : "=l"(bp2) : "f"(b1.x), "f"(b1.y));
            asm("mov.b64 %0,{%1,%2};" : "=l"(bp3) : "f"(b1.z), "f"(b1.w));
            float av[8] = {a0.x, a0.y, a0.z, a0.w, a1.x, a1.y, a1.z, a1.w};
#pragma unroll
            for (int i = 0; i < 8; i++) {
                u64 ap;
                asm("mov.b64 %0,{%1,%1};" : "=l"(ap) : "f"(av[i]));
                asm("fma.rn.f32x2 %0,%1,%2,%0;" : "+l"(acc[i][0]) : "l"(ap), "l"(bp0));
                asm("fma.rn.f32x2 %0,%1,%2,%0;" : "+l"(acc[i][1]) : "l"(ap), "l"(bp1));
                asm("fma.rn.f32x2 %0,%1,%2,%0;" : "+l"(acc[i][2]) : "l"(ap), "l"(bp2));
                asm("fma.rn.f32x2 %0,%1,%2,%0;" : "+l"(acc[i][3]) : "l"(ap), "l"(bp3));
            }
        }
        if (kt + 1 < KT) GK_STORE(buf ^ 1);
        __syncthreads();
        buf ^= 1;
    }

#pragma unroll
    for (int i = 0; i < 8; i++) {
        int m = m0 + (ty << 3) + i;
        if (m >= M) continue;
        float cv[8];
#pragma unroll
        for (int j = 0; j < 4; j++)
            asm("mov.b64 {%0,%1},%2;" : "=f"(cv[2 * j]), "=f"(cv[2 * j + 1]) : "l"(acc[i][j]));
        float* crow = C + (size_t)m * ldc + n0 + (tx << 3);
        float4 o0, o1;
        if (beta != 0.f) {
            const float* erow = E + (size_t)m * ldE + n0 + (tx << 3);
            float4 e0 = *reinterpret_cast<const float4*>(erow);
            float4 e1 = *reinterpret_cast<const float4*>(erow + 4);
            o0 = make_float4(alpha * cv[0] + beta * e0.x, alpha * cv[1] + beta * e0.y,
                             alpha * cv[2] + beta * e0.z, alpha * cv[3] + beta * e0.w);
            o1 = make_float4(alpha * cv[4] + beta * e1.x, alpha * cv[5] + beta * e1.y,
                             alpha * cv[6] + beta * e1.z, alpha * cv[7] + beta * e1.w);
        } else {
            o0 = make_float4(alpha * cv[0], alpha * cv[1], alpha * cv[2], alpha * cv[3]);
            o1 = make_float4(alpha * cv[4], alpha * cv[5], alpha * cv[6], alpha * cv[7]);
        }
        *reinterpret_cast<float4*>(crow) = o0;
        *reinterpret_cast<float4*>(crow + 4) = o1;
    }
#undef GK_FETCH
#undef GK_STORE
}

// ---------------- per-head L2 norm + affine (in place) ----------------
// one warp per (token,head); layout stride 3*DIMM, 64 channels per head
__global__ void norm_heads_k(float* __restrict__ base,
                             const float* __restrict__ sc,
                             const float* __restrict__ bi)
{
    int w = (blockIdx.x * blockDim.x + threadIdx.x) >> 5;
    int lane = threadIdx.x & 31;
    if (w >= NTOK * 16) return;
    int row = w >> 4;
    int head = w & 15;
    float* p = base + (size_t)row * (3 * DIMM) + head * 64;
    float x0 = p[lane], x1 = p[lane + 32];
    float ss = x0 * x0 + x1 * x1;
#pragma unroll
    for (int o = 16; o; o >>= 1) ss += __shfl_xor_sync(0xffffffffu, ss, o);
    float inv = 1.f / (sqrtf(ss) + 1e-6f);
    p[lane]      = x0 * inv * sc[lane]      + bi[lane];
    p[lane + 32] = x1 * inv * sc[lane + 32] + bi[lane + 32];
}

// ---------------- elementwise: h = swish(kg) * kv ----------------
__global__ void swish_mul_k(const float4* __restrict__ kg, const float4* __restrict__ kv,
                            float4* __restrict__ h, int n4)
{
    int i = blockIdx.x * blockDim.x + threadIdx.x;
    if (i >= n4) return;
    float4 g = kg[i], u = kv[i], o;
    o.x = g.x / (1.f + __expf(-g.x)) * u.x;
    o.y = g.y / (1.f + __expf(-g.y)) * u.y;
    o.z = g.z / (1.f + __expf(-g.z)) * u.z;
    o.w = g.w / (1.f + __expf(-g.w)) * u.w;
    h[i] = o;
}

// ---------------- backward elementwise ----------------
// dkv = dh*swish(kg);  dkg = dh*kv*s*(1+kg*(1-s)),  s=sigmoid(kg)
__global__ void bw_ew_k(const float4* __restrict__ dh,
                        float4* __restrict__ kg_io, float4* __restrict__ kv_io, int n4)
{
    int i = blockIdx.x * blockDim.x + threadIdx.x;
    if (i >= n4) return;
    float4 d = dh[i], g = kg_io[i], u = kv_io[i], dg, du;
#define BW1(c) { float s = 1.f/(1.f+__expf(-g.c)); float sw = g.c*s;               \
                 du.c = d.c*sw; dg.c = d.c*u.c*s*(1.f + g.c*(1.f-s)); }
    BW1(x) BW1(y) BW1(z) BW1(w)
#undef BW1
    kv_io[i] = du;
    kg_io[i] = dg;
}

// ---------------- reductions / NS helpers ----------------
__global__ void zerod_k(double* p) { *p = 0.0; }

__global__ void sumsq_k(const float* __restrict__ x, int n, double* __restrict__ out)
{
    __shared__ double sm[256];
    double a = 0.0;
    for (int i = blockIdx.x * blockDim.x + threadIdx.x; i < n; i += gridDim.x * blockDim.x) {
        float v = x[i];
        a += (double)v * (double)v;
    }
    sm[threadIdx.x] = a;
    __syncthreads();
    for (int s = 128; s; s >>= 1) {
        if (threadIdx.x < s) sm[threadIdx.x] += sm[threadIdx.x + s];
        __syncthreads();
    }
    if (threadIdx.x == 0) atomicAdd(out, sm[0]);
}

__global__ void scale_k(const float4* __restrict__ g, float4* __restrict__ X, int n4,
                        const double* __restrict__ nrm)
{
    int i = blockIdx.x * blockDim.x + threadIdx.x;
    if (i >= n4) return;
    float inv = (float)(1.0 / (sqrt(*nrm) + 1e-7));
    float4 v = g[i];
    v.x *= inv; v.y *= inv; v.z *= inv; v.w *= inv;
    X[i] = v;
}

// dst[C,R] = src[R,C]^T * (nrm ? 1/(sqrt(*nrm)+1e-7) : 1)
__global__ void transpose_k(const float* __restrict__ src, float* __restrict__ dst,
                            int R, int C, const double* __restrict__ nrm)
{
    __shared__ float t[32][33];
    float inv = nrm ? (float)(1.0 / (sqrt(*nrm) + 1e-7)) : 1.f;
    int c0 = blockIdx.x * 32, r0 = blockIdx.y * 32;
    int x = c0 + threadIdx.x;
#pragma unroll
    for (int j = 0; j < 32; j += 8)
        t[threadIdx.y + j][threadIdx.x] = src[(size_t)(r0 + threadIdx.y + j) * C + x] * inv;
    __syncthreads();
    int x2 = r0 + threadIdx.x;
#pragma unroll
    for (int j = 0; j < 32; j += 8)
        dst[(size_t)(c0 + threadIdx.y + j) * R + x2] = t[threadIdx.x][threadIdx.y + j];
}

__global__ void upd_k(float4* __restrict__ p, const float4* __restrict__ x, int n4)
{
    int i = blockIdx.x * blockDim.x + threadIdx.x;
    if (i >= n4) return;
    float4 a = p[i], b = x[i];
    a.x -= LRATE * b.x; a.y -= LRATE * b.y; a.z -= LRATE * b.z; a.w -= LRATE * b.w;
    p[i] = a;
}

// ---------------- host orchestration ----------------
struct Bufs {
    float *qkv, *kg, *kv, *h, *r, *G, *V, *P, *gG, *gV, *gP, *X1, *X2, *A, *A2;
    double* nrm;
};

static void* symaddr(const void* s)
{
    void* p = nullptr;
    cudaGetSymbolAddress(&p, s);
    return p;
}

static void gemm(int ta, int tb, const float* A, int lda, const float* B, int ldb,
                 float* C, int ldc, int M, int N, int K,
                 float alpha, float beta, const float* E, int ldE)
{
    dim3 gr(N / 128, (M + 127) / 128);
    if (!ta && !tb)      gemm_k<false, false><<<gr, 256>>>(A, lda, B, ldb, C, ldc, E, ldE, alpha, beta, M, N, K);
    else if (ta && !tb)  gemm_k<true,  false><<<gr, 256>>>(A, lda, B, ldb, C, ldc, E, ldE, alpha, beta, M, N, K);
    else if (!ta && tb)  gemm_k<false, true ><<<gr, 256>>>(A, lda, B, ldb, C, ldc, E, ldE, alpha, beta, M, N, K);
}

// Muon / Newton-Schulz on a [DIMM,HIDD] (or transposed [HIDD,DIMM]) gradient; updates theta in place.
static void run_ns(const float* g, float* theta, bool transposed, Bufs& b)
{
    const int NE = DIMM * HIDD;
    zerod_k<<<1, 1>>>(b.nrm);
    sumsq_k<<<1024, 256>>>(g, NE, b.nrm);
    float* X = b.X1;
    float* Y = b.X2;
    if (!transposed) {
        scale_k<<<(NE / 4 + 255) / 256, 256>>>((const float4*)g, (float4*)X, NE / 4, b.nrm);
    } else {
        dim3 gr(DIMM / 32, HIDD / 32);
        transpose_k<<<gr, dim3(32, 8)>>>(g, X, HIDD, DIMM, b.nrm); // [HIDD,DIMM] -> [DIMM,HIDD]
    }
    for (int it = 0; it < 5; ++it) {
        // A = X @ X^T  (NT)
        gemm(0, 1, X, HIDD, X, HIDD, b.A, DIMM, DIMM, DIMM, HIDD, 1.f, 0.f, nullptr, 0);
        // A2 = c*(A@A) + b*A
        gemm(0, 0, b.A, DIMM, b.A, DIMM, b.A2, DIMM, DIMM, DIMM, DIMM, NS_C, NS_B, b.A, DIMM);
        // Y = A2 @ X + a*X
        gemm(0, 0, b.A2, DIMM, X, HIDD, Y, HIDD, DIMM, HIDD, DIMM, 1.f, NS_A, X, HIDD);
        float* t = X; X = Y; Y = t;
    }
    if (!transposed) {
        upd_k<<<(NE / 4 + 255) / 256, 256>>>((float4*)theta, (const float4*)X, NE / 4);
    } else {
        dim3 gr(HIDD / 32, DIMM / 32);
        transpose_k<<<gr, dim3(32, 8)>>>(X, Y, DIMM, HIDD, nullptr); // back to [HIDD,DIMM]
        upd_k<<<(NE / 4 + 255) / 256, 256>>>((float4*)theta, (const float4*)Y, NE / 4);
    }
}

extern "C" void kernel_launch(void* const* d_in, const int* in_sizes, int n_in,
                              void* d_out, int out_size)
{
    const float* x       = (const float*)d_in[0];
    const float* qkv_w   = (const float*)d_in[1];
    const float* qkv_b   = (const float*)d_in[2];
    const float* qn_s    = (const float*)d_in[3];
    const float* qn_b    = (const float*)d_in[4];
    const float* kn_s    = (const float*)d_in[5];
    const float* kn_b    = (const float*)d_in[6];
    const float* ttt_gate = (const float*)d_in[7];
    const float* ttt_val  = (const float*)d_in[8];
    const float* ttt_proj = (const float*)d_in[9];
    const float* proj_w  = (const float*)d_in[10];
    const float* proj_b  = (const float*)d_in[11];
    float* out = (float*)d_out;

    Bufs b;
    b.qkv = (float*)symaddr(g_qkv);
    b.kg  = (float*)symaddr(g_kg);
    b.kv  = (float*)symaddr(g_kv);
    b.h   = (float*)symaddr(g_h);
    b.r   = (float*)symaddr(g_r);
    b.G   = (float*)symaddr(g_G);
    b.V   = (float*)symaddr(g_V);
    b.P   = (float*)symaddr(g_P);
    b.gG  = (float*)symaddr(g_gG);
    b.gV  = (float*)symaddr(g_gV);
    b.gP  = (float*)symaddr(g_gP);
    b.X1  = (float*)symaddr(g_X1);
    b.X2  = (float*)symaddr(g_X2);
    b.A   = (float*)symaddr(g_Am);
    b.A2  = (float*)symaddr(g_A2);
    b.nrm = (double*)symaddr(g_nrm);

    const size_t TB = sizeof(float) * (size_t)DIMM * HIDD;
    cudaMemcpyAsync(b.G, ttt_gate, TB, cudaMemcpyDeviceToDevice, 0);
    cudaMemcpyAsync(b.V, ttt_val,  TB, cudaMemcpyDeviceToDevice, 0);
    cudaMemcpyAsync(b.P, ttt_proj, TB, cudaMemcpyDeviceToDevice, 0);

    // qkv = x @ qkv_w + qkv_b
    gemm(0, 0, x, DIMM, qkv_w, 3 * DIMM, b.qkv, 3 * DIMM,
         NTOK, 3 * DIMM, DIMM, 1.f, 1.f, qkv_b, 0);

    // per-head normalize q and k in place
    {
        int nb = (NTOK * 16 * 32 + 255) / 256;
        norm_heads_k<<<nb, 256>>>(b.qkv, qn_s, qn_b);
        norm_heads_k<<<nb, 256>>>(b.qkv + DIMM, kn_s, kn_b);
    }

    const float* kmat = b.qkv + DIMM;       // [NTOK, DIMM], ld = 3*DIMM
    const float* vmat = b.qkv + 2 * DIMM;   // [NTOK, DIMM], ld = 3*DIMM
    const int NH4 = NTOK * HIDD / 4;
    const int nbH = (NH4 + 255) / 256;

    for (int step = 0; step < 2; ++step) {
        // forward
        gemm(0, 0, kmat, 3 * DIMM, b.G, HIDD, b.kg, HIDD, NTOK, HIDD, DIMM, 1.f, 0.f, nullptr, 0);
        gemm(0, 0, kmat, 3 * DIMM, b.V, HIDD, b.kv, HIDD, NTOK, HIDD, DIMM, 1.f, 0.f, nullptr, 0);
        swish_mul_k<<<nbH, 256>>>((const float4*)b.kg, (const float4*)b.kv, (float4*)b.h, NH4);
        // r = h@P - v  (NS is scale-invariant: loss prefactor dropped)
        gemm(0, 0, b.h, HIDD, b.P, DIMM, b.r, DIMM, NTOK, DIMM, HIDD, 1.f, -1.f, vmat, 3 * DIMM);
        // gP = h^T @ r
        gemm(1, 0, b.h, HIDD, b.r, DIMM, b.gP, DIMM, HIDD, DIMM, NTOK, 1.f, 0.f, nullptr, 0);
        // dh = r @ P^T  -> reuse h buffer
        gemm(0, 1, b.r, DIMM, b.P, DIMM, b.h, HIDD, NTOK, HIDD, DIMM, 1.f, 0.f, nullptr, 0);
        // dkg -> kg buf, dkv -> kv buf
        bw_ew_k<<<nbH, 256>>>((const float4*)b.h, (float4*)b.kg, (float4*)b.kv, NH4);
        // gG = k^T @ dkg ; gV = k^T @ dkv
        gemm(1, 0, kmat, 3 * DIMM, b.kg, HIDD, b.gG, HIDD, DIMM, HIDD, NTOK, 1.f, 0.f, nullptr, 0);
        gemm(1, 0, kmat, 3 * DIMM, b.kv, HIDD, b.gV, HIDD, DIMM, HIDD, NTOK, 1.f, 0.f, nullptr, 0);
        // Muon updates
        run_ns(b.gG, b.G, false, b);
        run_ns(b.gV, b.V, false, b);
        run_ns(b.gP, b.P, true,  b);
    }

    // final forward with q
    gemm(0, 0, b.qkv, 3 * DIMM, b.G, HIDD, b.kg, HIDD, NTOK, HIDD, DIMM, 1.f, 0.f, nullptr, 0);
    gemm(0, 0, b.qkv, 3 * DIMM, b.V, HIDD, b.kv, HIDD, NTOK, HIDD, DIMM, 1.f, 0.f, nullptr, 0);
    swish_mul_k<<<nbH, 256>>>((const float4*)b.kg, (const float4*)b.kv, (float4*)b.h, NH4);
    gemm(0, 0, b.h, HIDD, b.P, DIMM, b.r, DIMM, NTOK, DIMM, HIDD, 1.f, 0.f, nullptr, 0);
    // out = (h_q @ P) @ proj_w + proj_b
    gemm(0, 0, b.r, DIMM, proj_w, DIMM, out, DIMM, NTOK, DIMM, DIMM, 1.f, 1.f, proj_b, 0);
}

// round 4
// speedup vs baseline: 3.3946x; 3.3946x over previous
#include <cuda_runtime.h>
#include <cuda_bf16.h>
#include <cstdint>
#include <cstddef>

// ---------------- problem constants ----------------
#define NTOK 10992
#define MP   11008          // padded tokens: multiple of 128 (and 64)
#define DIMM 1024
#define HIDD 4096
#define LRATE 0.1f
#define NS_A 3.4445f
#define NS_B (-4.7750f)
#define NS_C 2.0315f

typedef unsigned long long u64;
typedef __nv_bfloat16 bf16;

// tcgen05 is an sm_103a arch-SPECIFIC feature. The build also runs a generic
// compute_103 PTX pass where those instructions do not exist; compile an empty
// body there. The GPU loads the sm_103a cubin, which has the real body.
#if !defined(__CUDA_ARCH__) || defined(__CUDA_ARCH_FEAT_SM103_ALL)
#define TC_HAS_TCGEN05 1
#else
#define TC_HAS_TCGEN05 0
#endif

// ================= PTX helpers (sm_103a) =================
#if TC_HAS_TCGEN05
__device__ __forceinline__ uint32_t smem_u32(const void* p) {
    uint32_t a;
    asm("{ .reg .u64 t; cvta.to.shared.u64 t, %1; cvt.u32.u64 %0, t; }" : "=r"(a) : "l"(p));
    return a;
}
__device__ __forceinline__ uint32_t elect1() {
    uint32_t p;
    asm volatile("{\n.reg .pred p;\nelect.sync _|p, 0xFFFFFFFF;\nselp.b32 %0,1,0,p;\n}" : "=r"(p));
    return p;
}
#define MBARRIER_INIT(a, c) \
    asm volatile("mbarrier.init.shared.b64 [%0], %1;" :: "r"((uint32_t)(a)), "r"((uint32_t)(c)) : "memory")
#define MBARRIER_WAIT_PARITY(a, ph) do { \
    uint32_t _m = (uint32_t)(a); uint32_t _p = (uint32_t)(ph); uint32_t _d; \
    asm volatile("{\n.reg .pred p;\nmbarrier.try_wait.parity.acquire.cta.shared::cta.b64 p, [%1], %2;\nselp.b32 %0,1,0,p;\n}" \
        : "=r"(_d) : "r"(_m), "r"(_p) : "memory"); \
    if (!_d) { \
        asm volatile("{\n.reg .pred P1;\nWL_%=:\nmbarrier.try_wait.parity.acquire.cta.shared::cta.b64 P1, [%0], %1, 0x989680;\n@P1 bra.uni WD_%=;\nbra.uni WL_%=;\nWD_%=:\n}" \
            :: "r"(_m), "r"(_p) : "memory"); \
    } } while (0)
#define TCGEN05_ALLOC(sa, n) \
    asm volatile("tcgen05.alloc.cta_group::1.sync.aligned.shared::cta.b32 [%0], %1;" \
        :: "r"((uint32_t)(sa)), "r"((uint32_t)(n)) : "memory")
#define TCGEN05_RELINQ() \
    asm volatile("tcgen05.relinquish_alloc_permit.cta_group::1.sync.aligned;")
#define TCGEN05_DEALLOC(t, n) \
    asm volatile("tcgen05.dealloc.cta_group::1.sync.aligned.b32 %0, %1;" :: "r"(t), "r"((uint32_t)(n)))
#define TCGEN05_COMMIT(a) \
    asm volatile("tcgen05.commit.cta_group::1.mbarrier::arrive::one.shared::cluster.b64 [%0];" \
        :: "r"((uint32_t)(a)) : "memory")
#define TCGEN05_FENCE_AFTER() asm volatile("tcgen05.fence::after_thread_sync;" ::: "memory")
#define TCGEN05_WAIT_LD() asm volatile("tcgen05.wait::ld.sync.aligned;" ::: "memory")
#define FENCE_ASYNC() asm volatile("fence.proxy.async.shared::cta;" ::: "memory")
#define STS128(r0, r1, r2, r3, a) \
    asm volatile("st.shared.v4.b32 [%0], {%1,%2,%3,%4};" :: "r"(a), "r"(r0), "r"(r1), "r"(r2), "r"(r3) : "memory")
#define TCGEN05_LD_X32(r, ta) \
    asm volatile("tcgen05.ld.sync.aligned.32x32b.x32.b32 " \
        "{%0,%1,%2,%3,%4,%5,%6,%7,%8,%9,%10,%11,%12,%13,%14,%15," \
        "%16,%17,%18,%19,%20,%21,%22,%23,%24,%25,%26,%27,%28,%29,%30,%31}, [%32];" \
        : "=r"((r)[0]), "=r"((r)[1]), "=r"((r)[2]), "=r"((r)[3]), "=r"((r)[4]), "=r"((r)[5]), \
          "=r"((r)[6]), "=r"((r)[7]), "=r"((r)[8]), "=r"((r)[9]), "=r"((r)[10]), "=r"((r)[11]), \
          "=r"((r)[12]), "=r"((r)[13]), "=r"((r)[14]), "=r"((r)[15]), "=r"((r)[16]), "=r"((r)[17]), \
          "=r"((r)[18]), "=r"((r)[19]), "=r"((r)[20]), "=r"((r)[21]), "=r"((r)[22]), "=r"((r)[23]), \
          "=r"((r)[24]), "=r"((r)[25]), "=r"((r)[26]), "=r"((r)[27]), "=r"((r)[28]), "=r"((r)[29]), \
          "=r"((r)[30]), "=r"((r)[31]) : "r"(ta))

// SW128 K-major smem descriptor (version=1, LBO=1, SBO=64)
static constexpr u64 SMEM_DESC_BASE =
    (u64(2) << 61) | (u64(1) << 46) | (u64(64) << 32) | (u64(1) << 16);
__device__ __forceinline__ u64 mkdesc(uint32_t sa) {
    return SMEM_DESC_BASE | ((u64)(sa >> 4) & 0x3FFF);
}

__device__ __forceinline__ void mma_f16_ss(uint32_t d, u64 ad, u64 bd, uint32_t idesc, bool acc) {
    uint32_t en = acc ? 1u : 0u;
    asm volatile(
        "{\n\t.reg .pred p;\n\tsetp.ne.u32 p, %4, 0;\n\t"
        "tcgen05.mma.cta_group::1.kind::f16 [%0], %1, %2, %3, {%5,%5,%5,%5}, p;\n\t}"
        :: "r"(d), "l"(ad), "l"(bd), "r"(idesc), "r"(en), "r"(0u) : "memory");
}
#endif // TC_HAS_TCGEN05

#define SWZ(b) ((b) ^ (((b) >> 3) & 0x70))
// idesc kind::f16: dtype=F32, a=BF16, b=BF16, N=128, M=128
#define TCIDESC 0x08200490u

// ---------------- device scratch ----------------
__device__ float g_qkv[(size_t)NTOK * 3 * DIMM];
__device__ float g_kg [(size_t)NTOK * HIDD];
__device__ float g_kv [(size_t)NTOK * HIDD];
__device__ float g_h  [(size_t)NTOK * HIDD];
__device__ float g_r  [(size_t)NTOK * DIMM];
__device__ float g_G  [DIMM * HIDD];
__device__ float g_V  [DIMM * HIDD];
__device__ float g_P  [HIDD * DIMM];
__device__ float g_gG [DIMM * HIDD];
__device__ float g_gV [DIMM * HIDD];
__device__ float g_gP [DIMM * HIDD];   // holds gP^T [DIMM,HIDD]
__device__ float g_X1 [DIMM * HIDD];
__device__ float g_X2 [DIMM * HIDD];
__device__ float g_Am [DIMM * DIMM];
__device__ float g_A2 [DIMM * DIMM];
__device__ double g_nrm[1];

// bf16 hi/lo pool
static constexpr size_t E_TOKD = (size_t)MP * DIMM;
static constexpr size_t E_TOKH = (size_t)MP * HIDD;
static constexpr size_t E_W    = (size_t)DIMM * HIDD;
static constexpr size_t E_A    = (size_t)DIMM * DIMM;
static constexpr size_t E_QKVW = (size_t)DIMM * 3 * DIMM;
static constexpr size_t O_X    = 0;
static constexpr size_t O_K    = O_X    + E_TOKD * 4;
static constexpr size_t O_KT   = O_K    + E_TOKD * 4;
static constexpr size_t O_Q    = O_KT   + E_TOKD * 4;
static constexpr size_t O_RT   = O_Q    + E_TOKD * 4;
static constexpr size_t O_H    = O_RT   + E_TOKD * 4;
static constexpr size_t O_HT   = O_H    + E_TOKH * 4;
static constexpr size_t O_DKGT = O_HT   + E_TOKH * 4;
static constexpr size_t O_DKVT = O_DKGT + E_TOKH * 4;
static constexpr size_t O_WGT  = O_DKVT + E_TOKH * 4;
static constexpr size_t O_WVT  = O_WGT  + E_W * 4;
static constexpr size_t O_WP   = O_WVT  + E_W * 4;
static constexpr size_t O_WPT  = O_WP   + E_W * 4;
static constexpr size_t O_QKVW = O_WPT  + E_W * 4;
static constexpr size_t O_PRJW = O_QKVW + E_QKVW * 4;
static constexpr size_t O_NSX  = O_PRJW + E_A * 4;
static constexpr size_t O_NSXT = O_NSX  + E_W * 4;
static constexpr size_t O_NSA  = O_NSXT + E_W * 4;
static constexpr size_t O_NSA2 = O_NSA  + E_A * 4;
static constexpr size_t POOL_B = O_NSA2 + E_A * 4;
__device__ __align__(1024) unsigned char g_bf[POOL_B];

// ================= tcgen05 split-bf16 GEMM =================
// C[M,N] = alpha * (Ahi+Alo)[Mp,Kp] * (Bhi+Blo)[Np,Kp]^T + beta*E
#define TC_SMEM (131072 + 1024)

__global__ void __launch_bounds__(256, 1) tc_gemm(
    const bf16* __restrict__ Ahi, const bf16* __restrict__ Alo,
    const bf16* __restrict__ Bhi, const bf16* __restrict__ Blo,
    int Kp, float* __restrict__ C, int ldc,
    const float* __restrict__ E, int ldE,
    float alpha, float beta, int M)
{
#if TC_HAS_TCGEN05
    extern __shared__ unsigned char dsm_raw[];
    __shared__ __align__(8) u64 s_mb[2];
    __shared__ uint32_t s_tmem[1];

    const int tid = threadIdx.x;
    const int wid = tid >> 5;
    const int lane = tid & 31;

    const uint32_t sb = (smem_u32(dsm_raw) + 1023) & ~1023u;
    const uint32_t mb0 = smem_u32(&s_mb[0]);
    const uint32_t mb1 = smem_u32(&s_mb[1]);

    if (tid == 0) { MBARRIER_INIT(mb0, 1); MBARRIER_INIT(mb1, 1); }
    if (wid == 0) {
        TCGEN05_ALLOC(smem_u32(s_tmem), 128);
        TCGEN05_RELINQ();
    }
    __syncthreads();
    const uint32_t tmem = s_tmem[0];

    const int m0 = blockIdx.y * 128;
    const int n0 = blockIdx.x * 128;

    const int row  = tid >> 1;
    const int hoff = (tid & 1) * 64;
    const char* pA[4];
    pA[0] = (const char*)(Ahi + (size_t)(m0 + row) * Kp);
    pA[1] = (const char*)(Alo + (size_t)(m0 + row) * Kp);
    pA[2] = (const char*)(Bhi + (size_t)(n0 + row) * Kp);
    pA[3] = (const char*)(Blo + (size_t)(n0 + row) * Kp);
    const uint32_t swbase = (uint32_t)row * 128 + hoff;

    const int NC = Kp >> 6;
    for (int c = 0; c < NC; ++c) {
        const int s = c & 1, t = c >> 1;
        const uint32_t mbs = s ? mb1 : mb0;
        if (c >= 2) { MBARRIER_WAIT_PARITY(mbs, (t - 1) & 1); }
        const uint32_t stg = sb + (uint32_t)s * 65536u;
        const size_t gb = (size_t)c * 128;
#pragma unroll
        for (int q = 0; q < 4; ++q) {
            const uint32_t tb = stg + (uint32_t)q * 16384u;
#pragma unroll
            for (int j = 0; j < 4; ++j) {
                uint4 v = *reinterpret_cast<const uint4*>(pA[q] + gb + hoff + j * 16);
                STS128(v.x, v.y, v.z, v.w, tb + SWZ(swbase + j * 16));
            }
        }
        FENCE_ASYNC();
        __syncthreads();
        if (wid == 0 && elect1()) {
            u64 aH = mkdesc(stg);
            u64 aL = mkdesc(stg + 16384);
            u64 bH = mkdesc(stg + 32768);
            u64 bL = mkdesc(stg + 49152);
#pragma unroll
            for (int ks = 0; ks < 4; ++ks)
                mma_f16_ss(tmem, aH + ks * 2, bH + ks * 2, TCIDESC, !(c == 0 && ks == 0));
#pragma unroll
            for (int ks = 0; ks < 4; ++ks)
                mma_f16_ss(tmem, aH + ks * 2, bL + ks * 2, TCIDESC, true);
#pragma unroll
            for (int ks = 0; ks < 4; ++ks)
                mma_f16_ss(tmem, aL + ks * 2, bH + ks * 2, TCIDESC, true);
            TCGEN05_COMMIT(mbs);
        }
    }
    {
        const int cl = NC - 1;
        MBARRIER_WAIT_PARITY((cl & 1) ? mb1 : mb0, (cl >> 1) & 1);
    }
    TCGEN05_FENCE_AFTER();

    // epilogue: warps 0-3 -> cols [0,64), warps 4-7 -> cols [64,128)
    const int sub = wid & 3;
    const int colb = (wid < 4) ? 0 : 64;
    const int m = m0 + sub * 32 + lane;
#pragma unroll
    for (int half = 0; half < 2; ++half) {
        uint32_t r32[32];
        TCGEN05_LD_X32(r32, tmem + colb + half * 32);
        TCGEN05_WAIT_LD();
        if (m < M) {
            float* crow = C + (size_t)m * ldc + n0 + colb + half * 32;
            if (beta != 0.f) {
                const float* erow = E + (size_t)m * ldE + n0 + colb + half * 32;
#pragma unroll
                for (int j = 0; j < 32; j += 4) {
                    float4 e = *reinterpret_cast<const float4*>(erow + j);
                    float4 o;
                    o.x = alpha * __uint_as_float(r32[j])     + beta * e.x;
                    o.y = alpha * __uint_as_float(r32[j + 1]) + beta * e.y;
                    o.z = alpha * __uint_as_float(r32[j + 2]) + beta * e.z;
                    o.w = alpha * __uint_as_float(r32[j + 3]) + beta * e.w;
                    *reinterpret_cast<float4*>(crow + j) = o;
                }
            } else {
#pragma unroll
                for (int j = 0; j < 32; j += 4) {
                    float4 o;
                    o.x = alpha * __uint_as_float(r32[j]);
                    o.y = alpha * __uint_as_float(r32[j + 1]);
                    o.z = alpha * __uint_as_float(r32[j + 2]);
                    o.w = alpha * __uint_as_float(r32[j + 3]);
                    *reinterpret_cast<float4*>(crow + j) = o;
                }
            }
        }
    }
    __syncthreads();
    if (wid == 0) TCGEN05_DEALLOC(tmem, 128);
#endif // TC_HAS_TCGEN05
}

// ================= conversion kernels =================
__global__ void conv_k(const float* __restrict__ src, int ld, int R, int C,
                       bf16* __restrict__ hi, bf16* __restrict__ lo, int Cp)
{
    int c = (blockIdx.x * blockDim.x + threadIdx.x) * 4;
    int r = blockIdx.y;
    if (c >= Cp) return;
    __align__(8) bf16 h4[4];
    __align__(8) bf16 l4[4];
    if (r < R && c < C) {
        float4 v = *reinterpret_cast<const float4*>(src + (size_t)r * ld + c);
        float vv[4] = {v.x, v.y, v.z, v.w};
#pragma unroll
        for (int j = 0; j < 4; j++) {
            bf16 h = __float2bfloat16(vv[j]);
            h4[j] = h;
            l4[j] = __float2bfloat16(vv[j] - __bfloat162float(h));
        }
    } else {
#pragma unroll
        for (int j = 0; j < 4; j++) { h4[j] = __float2bfloat16(0.f); l4[j] = h4[j]; }
    }
    size_t o = (size_t)r * Cp + c;
    *reinterpret_cast<uint2*>(hi + o) = *reinterpret_cast<const uint2*>(h4);
    *reinterpret_cast<uint2*>(lo + o) = *reinterpret_cast<const uint2*>(l4);
}

__global__ void convT_k(const float* __restrict__ src, int ld, int R, int C,
                        bf16* __restrict__ hi, bf16* __restrict__ lo, int Rp)
{
    __shared__ float t[32][33];
    int c0 = blockIdx.x * 32;
    int r0 = blockIdx.y * 32;
    int tx = threadIdx.x, ty = threadIdx.y;
#pragma unroll
    for (int j = 0; j < 32; j += 8) {
        int r = r0 + ty + j;
        t[ty + j][tx] = (r < R) ? src[(size_t)r * ld + c0 + tx] : 0.f;
    }
    __syncthreads();
#pragma unroll
    for (int j = 0; j < 32; j += 8) {
        float v = t[tx][ty + j];
        size_t o = (size_t)(c0 + ty + j) * Rp + r0 + tx;
        bf16 h = __float2bfloat16(v);
        hi[o] = h;
        lo[o] = __float2bfloat16(v - __bfloat162float(h));
    }
}

// ================= elementwise / reductions =================
__global__ void norm_heads_k(float* __restrict__ base,
                             const float* __restrict__ sc, const float* __restrict__ bi)
{
    int w = (blockIdx.x * blockDim.x + threadIdx.x) >> 5;
    int lane = threadIdx.x & 31;
    if (w >= NTOK * 16) return;
    int rowi = w >> 4, head = w & 15;
    float* p = base + (size_t)rowi * (3 * DIMM) + head * 64;
    float x0 = p[lane], x1 = p[lane + 32];
    float ss = x0 * x0 + x1 * x1;
#pragma unroll
    for (int o = 16; o; o >>= 1) ss += __shfl_xor_sync(0xffffffffu, ss, o);
    float inv = 1.f / (sqrtf(ss) + 1e-6f);
    p[lane]      = x0 * inv * sc[lane]      + bi[lane];
    p[lane + 32] = x1 * inv * sc[lane + 32] + bi[lane + 32];
}

__global__ void swish_mul_k(const float4* __restrict__ kg, const float4* __restrict__ kv,
                            float4* __restrict__ h, int n4)
{
    int i = blockIdx.x * blockDim.x + threadIdx.x;
    if (i >= n4) return;
    float4 g = kg[i], u = kv[i], o;
    o.x = g.x / (1.f + __expf(-g.x)) * u.x;
    o.y = g.y / (1.f + __expf(-g.y)) * u.y;
    o.z = g.z / (1.f + __expf(-g.z)) * u.z;
    o.w = g.w / (1.f + __expf(-g.w)) * u.w;
    h[i] = o;
}

__global__ void bw_ew_k(const float4* __restrict__ dh,
                        float4* __restrict__ kg_io, float4* __restrict__ kv_io, int n4)
{
    int i = blockIdx.x * blockDim.x + threadIdx.x;
    if (i >= n4) return;
    float4 d = dh[i], g = kg_io[i], u = kv_io[i], dg, du;
#define BW1(c) { float s = 1.f/(1.f+__expf(-g.c)); float sw = g.c*s; \
                 du.c = d.c*sw; dg.c = d.c*u.c*s*(1.f + g.c*(1.f-s)); }
    BW1(x) BW1(y) BW1(z) BW1(w)
#undef BW1
    kv_io[i] = du;
    kg_io[i] = dg;
}

__global__ void zerod_k(double* p) { *p = 0.0; }

__global__ void sumsq_k(const float* __restrict__ x, int n, double* __restrict__ out)
{
    __shared__ double sm[256];
    double a = 0.0;
    for (int i = blockIdx.x * blockDim.x + threadIdx.x; i < n; i += gridDim.x * blockDim.x) {
        float v = x[i];
        a += (double)v * (double)v;
    }
    sm[threadIdx.x] = a;
    __syncthreads();
    for (int s = 128; s; s >>= 1) {
        if (threadIdx.x < s) sm[threadIdx.x] += sm[threadIdx.x + s];
        __syncthreads();
    }
    if (threadIdx.x == 0) atomicAdd(out, sm[0]);
}

__global__ void scale_k(const float4* __restrict__ g, float4* __restrict__ X, int n4,
                        const double* __restrict__ nrm)
{
    int i = blockIdx.x * blockDim.x + threadIdx.x;
    if (i >= n4) return;
    float inv = (float)(1.0 / (sqrt(*nrm) + 1e-7));
    float4 v = g[i];
    v.x *= inv; v.y *= inv; v.z *= inv; v.w *= inv;
    X[i] = v;
}

__global__ void transpose_k(const float* __restrict__ src, float* __restrict__ dst,
                            int R, int C, const double* __restrict__ nrm)
{
    __shared__ float t[32][33];
    float inv = nrm ? (float)(1.0 / (sqrt(*nrm) + 1e-7)) : 1.f;
    int c0 = blockIdx.x * 32, r0 = blockIdx.y * 32;
    int x = c0 + threadIdx.x;
#pragma unroll
    for (int j = 0; j < 32; j += 8)
        t[threadIdx.y + j][threadIdx.x] = src[(size_t)(r0 + threadIdx.y + j) * C + x] * inv;
    __syncthreads();
    int x2 = r0 + threadIdx.x;
#pragma unroll
    for (int j = 0; j < 32; j += 8)
        dst[(size_t)(c0 + threadIdx.y + j) * R + x2] = t[threadIdx.x][threadIdx.y + j];
}

__global__ void upd_k(float4* __restrict__ p, const float4* __restrict__ x, int n4)
{
    int i = blockIdx.x * blockDim.x + threadIdx.x;
    if (i >= n4) return;
    float4 a = p[i], bb = x[i];
    a.x -= LRATE * bb.x; a.y -= LRATE * bb.y; a.z -= LRATE * bb.z; a.w -= LRATE * bb.w;
    p[i] = a;
}

// ================= host orchestration =================
struct BP { bf16 *hi, *lo; };

static void* symaddr(const void* s) { void* p = nullptr; cudaGetSymbolAddress(&p, s); return p; }

static void tc(BP A, BP B, int Kp, float* C, int ldc, int M, int N,
               float alpha, float beta, const float* E, int ldE)
{
    dim3 gr(N / 128, (M + 127) / 128);
    tc_gemm<<<gr, 256, TC_SMEM>>>(A.hi, A.lo, B.hi, B.lo, Kp, C, ldc, E, ldE, alpha, beta, M);
}

static void conv(const float* s, int ld, int R, int C, BP d, int Rp, int Cp)
{
    dim3 gr((Cp / 4 + 255) / 256, Rp);
    conv_k<<<gr, 256>>>(s, ld, R, C, d.hi, d.lo, Cp);
}

static void convT(const float* s, int ld, int R, int C, BP d, int Rp)
{
    dim3 gr(C / 32, Rp / 32);
    convT_k<<<gr, dim3(32, 8)>>>(s, ld, R, C, d.hi, d.lo, Rp);
}

struct Ctx {
    float *qkv, *kg, *kv, *h, *r, *G, *V, *P, *gG, *gV, *gP, *X1, *X2, *A, *A2;
    double* nrm;
    unsigned char* pool;
    BP bp(size_t off, size_t elems) const {
        BP r; r.hi = (bf16*)(pool + off); r.lo = r.hi + elems; return r;
    }
};

static void ns_tc(float* g, float* theta, bool thetaT, Ctx& c)
{
    const int NE = DIMM * HIDD;
    BP nsX = c.bp(O_NSX, E_W), nsXT = c.bp(O_NSXT, E_W);
    BP nsA = c.bp(O_NSA, E_A), nsA2 = c.bp(O_NSA2, E_A);
    zerod_k<<<1, 1>>>(c.nrm);
    sumsq_k<<<1024, 256>>>(g, NE, c.nrm);
    scale_k<<<(NE / 4 + 255) / 256, 256>>>((const float4*)g, (float4*)c.X1, NE / 4, c.nrm);
    float* X = c.X1;
    float* Y = c.X2;
    for (int it = 0; it < 5; ++it) {
        conv (X, HIDD, DIMM, HIDD, nsX, DIMM, HIDD);
        convT(X, HIDD, DIMM, HIDD, nsXT, DIMM);
        tc(nsX, nsX, HIDD, c.A, DIMM, DIMM, DIMM, 1.f, 0.f, nullptr, 0);
        conv(c.A, DIMM, DIMM, DIMM, nsA, DIMM, DIMM);
        tc(nsA, nsA, DIMM, c.A2, DIMM, DIMM, DIMM, NS_C, NS_B, c.A, DIMM);
        conv(c.A2, DIMM, DIMM, DIMM, nsA2, DIMM, DIMM);
        tc(nsA2, nsXT, DIMM, Y, HIDD, DIMM, HIDD, 1.f, NS_A, X, HIDD);
        float* t = X; X = Y; Y = t;
    }
    if (!thetaT) {
        upd_k<<<(NE / 4 + 255) / 256, 256>>>((float4*)theta, (const float4*)X, NE / 4);
    } else {
        dim3 gr(HIDD / 32, DIMM / 32);
        transpose_k<<<gr, dim3(32, 8)>>>(X, Y, DIMM, HIDD, nullptr);
        upd_k<<<(NE / 4 + 255) / 256, 256>>>((float4*)theta, (const float4*)Y, NE / 4);
    }
}

extern "C" void kernel_launch(void* const* d_in, const int* in_sizes, int n_in,
                              void* d_out, int out_size)
{
    const float* x        = (const float*)d_in[0];
    const float* qkv_w    = (const float*)d_in[1];
    const float* qkv_b    = (const float*)d_in[2];
    const float* qn_s     = (const float*)d_in[3];
    const float* qn_b     = (const float*)d_in[4];
    const float* kn_s     = (const float*)d_in[5];
    const float* kn_b     = (const float*)d_in[6];
    const float* ttt_gate = (const float*)d_in[7];
    const float* ttt_val  = (const float*)d_in[8];
    const float* ttt_proj = (const float*)d_in[9];
    const float* proj_w   = (const float*)d_in[10];
    const float* proj_b   = (const float*)d_in[11];
    float* out = (float*)d_out;

    cudaFuncSetAttribute(tc_gemm, cudaFuncAttributeMaxDynamicSharedMemorySize, TC_SMEM);

    Ctx c;
    c.qkv = (float*)symaddr(g_qkv); c.kg = (float*)symaddr(g_kg);
    c.kv  = (float*)symaddr(g_kv);  c.h  = (float*)symaddr(g_h);
    c.r   = (float*)symaddr(g_r);   c.G  = (float*)symaddr(g_G);
    c.V   = (float*)symaddr(g_V);   c.P  = (float*)symaddr(g_P);
    c.gG  = (float*)symaddr(g_gG);  c.gV = (float*)symaddr(g_gV);
    c.gP  = (float*)symaddr(g_gP);  c.X1 = (float*)symaddr(g_X1);
    c.X2  = (float*)symaddr(g_X2);  c.A  = (float*)symaddr(g_Am);
    c.A2  = (float*)symaddr(g_A2);  c.nrm = (double*)symaddr(g_nrm);
    c.pool = (unsigned char*)symaddr(g_bf);

    BP xb   = c.bp(O_X, E_TOKD);
    BP kb   = c.bp(O_K, E_TOKD);
    BP kTb  = c.bp(O_KT, E_TOKD);
    BP qb   = c.bp(O_Q, E_TOKD);
    BP rTb  = c.bp(O_RT, E_TOKD);
    BP hb   = c.bp(O_H, E_TOKH);
    BP hTb  = c.bp(O_HT, E_TOKH);
    BP dkgT = c.bp(O_DKGT, E_TOKH);
    BP dkvT = c.bp(O_DKVT, E_TOKH);
    BP wGt  = c.bp(O_WGT, E_W);
    BP wVt  = c.bp(O_WVT, E_W);
    BP wP   = c.bp(O_WP,  E_W);
    BP wPt  = c.bp(O_WPT, E_W);
    BP qkvwT = c.bp(O_QKVW, E_QKVW);
    BP projwT = c.bp(O_PRJW, E_A);

    const size_t TB = sizeof(float) * (size_t)DIMM * HIDD;
    cudaMemcpyAsync(c.G, ttt_gate, TB, cudaMemcpyDeviceToDevice, 0);
    cudaMemcpyAsync(c.V, ttt_val,  TB, cudaMemcpyDeviceToDevice, 0);
    cudaMemcpyAsync(c.P, ttt_proj, TB, cudaMemcpyDeviceToDevice, 0);

    // ---- qkv = x @ qkv_w + b ----
    conv (x, DIMM, NTOK, DIMM, xb, MP, DIMM);
    convT(qkv_w, 3 * DIMM, DIMM, 3 * DIMM, qkvwT, DIMM);
    tc(xb, qkvwT, DIMM, c.qkv, 3 * DIMM, NTOK, 3 * DIMM, 1.f, 1.f, qkv_b, 0);

    {
        int nb = (NTOK * 16 * 32 + 255) / 256;
        norm_heads_k<<<nb, 256>>>(c.qkv, qn_s, qn_b);
        norm_heads_k<<<nb, 256>>>(c.qkv + DIMM, kn_s, kn_b);
    }

    const float* kmat = c.qkv + DIMM;
    const float* vmat = c.qkv + 2 * DIMM;
    conv (kmat, 3 * DIMM, NTOK, DIMM, kb, MP, DIMM);
    convT(kmat, 3 * DIMM, NTOK, DIMM, kTb, MP);
    conv (c.qkv, 3 * DIMM, NTOK, DIMM, qb, MP, DIMM);

    const int NH4 = NTOK * HIDD / 4;
    const int nbH = (NH4 + 255) / 256;

    for (int step = 0; step < 2; ++step) {
        convT(c.G, HIDD, DIMM, HIDD, wGt, DIMM);
        convT(c.V, HIDD, DIMM, HIDD, wVt, DIMM);
        conv (c.P, DIMM, HIDD, DIMM, wP, HIDD, DIMM);
        convT(c.P, DIMM, HIDD, DIMM, wPt, HIDD);

        tc(kb, wGt, DIMM, c.kg, HIDD, NTOK, HIDD, 1.f, 0.f, nullptr, 0);
        tc(kb, wVt, DIMM, c.kv, HIDD, NTOK, HIDD, 1.f, 0.f, nullptr, 0);
        swish_mul_k<<<nbH, 256>>>((const float4*)c.kg, (const float4*)c.kv, (float4*)c.h, NH4);
        conv (c.h, HIDD, NTOK, HIDD, hb, MP, HIDD);
        convT(c.h, HIDD, NTOK, HIDD, hTb, MP);
        tc(hb, wPt, HIDD, c.r, DIMM, NTOK, DIMM, 1.f, -1.f, vmat, 3 * DIMM);
        conv (c.r, DIMM, NTOK, DIMM, xb, MP, DIMM);
        convT(c.r, DIMM, NTOK, DIMM, rTb, MP);
        tc(rTb, hTb, MP, c.gP, HIDD, DIMM, HIDD, 1.f, 0.f, nullptr, 0);
        tc(xb, wP, DIMM, c.h, HIDD, NTOK, HIDD, 1.f, 0.f, nullptr, 0);
        bw_ew_k<<<nbH, 256>>>((const float4*)c.h, (float4*)c.kg, (float4*)c.kv, NH4);
        convT(c.kg, HIDD, NTOK, HIDD, dkgT, MP);
        convT(c.kv, HIDD, NTOK, HIDD, dkvT, MP);
        tc(kTb, dkgT, MP, c.gG, HIDD, DIMM, HIDD, 1.f, 0.f, nullptr, 0);
        tc(kTb, dkvT, MP, c.gV, HIDD, DIMM, HIDD, 1.f, 0.f, nullptr, 0);

        ns_tc(c.gG, c.G, false, c);
        ns_tc(c.gV, c.V, false, c);
        ns_tc(c.gP, c.P, true, c);
    }

    // ---- final forward with q ----
    convT(c.G, HIDD, DIMM, HIDD, wGt, DIMM);
    convT(c.V, HIDD, DIMM, HIDD, wVt, DIMM);
    convT(c.P, DIMM, HIDD, DIMM, wPt, HIDD);
    tc(qb, wGt, DIMM, c.kg, HIDD, NTOK, HIDD, 1.f, 0.f, nullptr, 0);
    tc(qb, wVt, DIMM, c.kv, HIDD, NTOK, HIDD, 1.f, 0.f, nullptr, 0);
    swish_mul_k<<<nbH, 256>>>((const float4*)c.kg, (const float4*)c.kv, (float4*)c.h, NH4);
    conv(c.h, HIDD, NTOK, HIDD, hb, MP, HIDD);
    tc(hb, wPt, HIDD, c.r, DIMM, NTOK, DIMM, 1.f, 0.f, nullptr, 0);
    conv(c.r, DIMM, NTOK, DIMM, xb, MP, DIMM);
    convT(proj_w, DIMM, DIMM, DIMM, projwT, DIMM);
    tc(xb, projwT, DIMM, out, DIMM, NTOK, DIMM, 1.f, 1.f, proj_b, 0);
}

// round 5
// speedup vs baseline: 4.1566x; 1.2245x over previous
#include <cuda_runtime.h>
#include <cuda_bf16.h>
#include <cstdint>
#include <cstddef>

// ---------------- problem constants ----------------
#define NTOK 10992
#define MP   11008
#define DIMM 1024
#define HIDD 4096
#define LRATE 0.1f
#define NS_A 3.4445f
#define NS_B (-4.7750f)
#define NS_C 2.0315f

typedef unsigned long long u64;
typedef long long i64;
typedef __nv_bfloat16 bf16;

#if !defined(__CUDA_ARCH__) || defined(__CUDA_ARCH_FEAT_SM103_ALL)
#define TC_HAS_TCGEN05 1
#else
#define TC_HAS_TCGEN05 0
#endif

// ================= PTX helpers (sm_103a) =================
#if TC_HAS_TCGEN05
__device__ __forceinline__ uint32_t smem_u32(const void* p) {
    uint32_t a;
    asm("{ .reg .u64 t; cvta.to.shared.u64 t, %1; cvt.u32.u64 %0, t; }" : "=r"(a) : "l"(p));
    return a;
}
__device__ __forceinline__ uint32_t elect1() {
    uint32_t p;
    asm volatile("{\n.reg .pred p;\nelect.sync _|p, 0xFFFFFFFF;\nselp.b32 %0,1,0,p;\n}" : "=r"(p));
    return p;
}
#define MBARRIER_INIT(a, c) \
    asm volatile("mbarrier.init.shared.b64 [%0], %1;" :: "r"((uint32_t)(a)), "r"((uint32_t)(c)) : "memory")
#define MBARRIER_WAIT_PARITY(a, ph) do { \
    uint32_t _m = (uint32_t)(a); uint32_t _p = (uint32_t)(ph); uint32_t _d; \
    asm volatile("{\n.reg .pred p;\nmbarrier.try_wait.parity.acquire.cta.shared::cta.b64 p, [%1], %2;\nselp.b32 %0,1,0,p;\n}" \
        : "=r"(_d) : "r"(_m), "r"(_p) : "memory"); \
    if (!_d) { \
        asm volatile("{\n.reg .pred P1;\nWL_%=:\nmbarrier.try_wait.parity.acquire.cta.shared::cta.b64 P1, [%0], %1, 0x989680;\n@P1 bra.uni WD_%=;\nbra.uni WL_%=;\nWD_%=:\n}" \
            :: "r"(_m), "r"(_p) : "memory"); \
    } } while (0)
#define TCGEN05_ALLOC(sa, n) \
    asm volatile("tcgen05.alloc.cta_group::1.sync.aligned.shared::cta.b32 [%0], %1;" \
        :: "r"((uint32_t)(sa)), "r"((uint32_t)(n)) : "memory")
#define TCGEN05_RELINQ() \
    asm volatile("tcgen05.relinquish_alloc_permit.cta_group::1.sync.aligned;")
#define TCGEN05_DEALLOC(t, n) \
    asm volatile("tcgen05.dealloc.cta_group::1.sync.aligned.b32 %0, %1;" :: "r"(t), "r"((uint32_t)(n)))
#define TCGEN05_COMMIT(a) \
    asm volatile("tcgen05.commit.cta_group::1.mbarrier::arrive::one.shared::cluster.b64 [%0];" \
        :: "r"((uint32_t)(a)) : "memory")
#define TCGEN05_FENCE_AFTER() asm volatile("tcgen05.fence::after_thread_sync;" ::: "memory")
#define TCGEN05_WAIT_LD() asm volatile("tcgen05.wait::ld.sync.aligned;" ::: "memory")
#define FENCE_ASYNC() asm volatile("fence.proxy.async.shared::cta;" ::: "memory")
#define STS128(r0, r1, r2, r3, a) \
    asm volatile("st.shared.v4.b32 [%0], {%1,%2,%3,%4};" :: "r"(a), "r"(r0), "r"(r1), "r"(r2), "r"(r3) : "memory")
#define TCGEN05_LD_X32(r, ta) \
    asm volatile("tcgen05.ld.sync.aligned.32x32b.x32.b32 " \
        "{%0,%1,%2,%3,%4,%5,%6,%7,%8,%9,%10,%11,%12,%13,%14,%15," \
        "%16,%17,%18,%19,%20,%21,%22,%23,%24,%25,%26,%27,%28,%29,%30,%31}, [%32];" \
        : "=r"((r)[0]), "=r"((r)[1]), "=r"((r)[2]), "=r"((r)[3]), "=r"((r)[4]), "=r"((r)[5]), \
          "=r"((r)[6]), "=r"((r)[7]), "=r"((r)[8]), "=r"((r)[9]), "=r"((r)[10]), "=r"((r)[11]), \
          "=r"((r)[12]), "=r"((r)[13]), "=r"((r)[14]), "=r"((r)[15]), "=r"((r)[16]), "=r"((r)[17]), \
          "=r"((r)[18]), "=r"((r)[19]), "=r"((r)[20]), "=r"((r)[21]), "=r"((r)[22]), "=r"((r)[23]), \
          "=r"((r)[24]), "=r"((r)[25]), "=r"((r)[26]), "=r"((r)[27]), "=r"((r)[28]), "=r"((r)[29]), \
          "=r"((r)[30]), "=r"((r)[31]) : "r"(ta))

static constexpr u64 SMEM_DESC_BASE =
    (u64(2) << 61) | (u64(1) << 46) | (u64(64) << 32) | (u64(1) << 16);
__device__ __forceinline__ u64 mkdesc(uint32_t sa) {
    return SMEM_DESC_BASE | ((u64)(sa >> 4) & 0x3FFF);
}
__device__ __forceinline__ void mma_f16_ss(uint32_t d, u64 ad, u64 bd, uint32_t idesc, bool acc) {
    uint32_t en = acc ? 1u : 0u;
    asm volatile(
        "{\n\t.reg .pred p;\n\tsetp.ne.u32 p, %4, 0;\n\t"
        "tcgen05.mma.cta_group::1.kind::f16 [%0], %1, %2, %3, {%5,%5,%5,%5}, p;\n\t}"
        :: "r"(d), "l"(ad), "l"(bd), "r"(idesc), "r"(en), "r"(0u) : "memory");
}
#endif

#define SWZ(b) ((b) ^ (((b) >> 3) & 0x70))
#define TCIDESC 0x08200490u   // dtype=F32, a=BF16, b=BF16, N=128, M=128

// ---------------- fp32 scratch ----------------
static constexpr size_t E_TOKD = (size_t)MP * DIMM;
static constexpr size_t E_TOKH = (size_t)MP * HIDD;
static constexpr size_t E_W    = (size_t)DIMM * HIDD;
static constexpr size_t E_A    = (size_t)DIMM * DIMM;
static constexpr size_t E_QKVW = (size_t)DIMM * 3 * DIMM;

__device__ float g_qkv [(size_t)NTOK * 3 * DIMM];
__device__ float g_kgv [(size_t)2 * NTOK * HIDD];   // kg | kv  (also dkg|dkv)
__device__ float g_h   [(size_t)NTOK * HIDD];
__device__ float g_r   [(size_t)NTOK * DIMM];
__device__ float g_GV  [2 * E_W];                   // G | V
__device__ float g_P   [E_W];
__device__ float g_grad[3 * E_W];                   // gG | gV | gP^T
__device__ float g_X1  [3 * E_W];
__device__ float g_X2  [3 * E_W];
__device__ float g_A   [3 * E_A];
__device__ double g_nrm[3];

// ---------------- bf16 hi/lo pool (each BP region = 4*elems bytes) ----------------
static constexpr size_t O_X    = 0;
static constexpr size_t O_K    = O_X    + E_TOKD * 4;
static constexpr size_t O_KT   = O_K    + E_TOKD * 4;
static constexpr size_t O_Q    = O_KT   + E_TOKD * 4;
static constexpr size_t O_RT   = O_Q    + E_TOKD * 4;
static constexpr size_t O_H    = O_RT   + E_TOKD * 4;
static constexpr size_t O_HT   = O_H    + E_TOKH * 4;
static constexpr size_t O_DKGT = O_HT   + E_TOKH * 4;
static constexpr size_t O_DKVT = O_DKGT + E_TOKH * 4;
static constexpr size_t O_WGT  = O_DKVT + E_TOKH * 4;
static constexpr size_t O_WVT  = O_WGT  + E_W * 4;
static constexpr size_t O_WP   = O_WVT  + E_W * 4;
static constexpr size_t O_WPT  = O_WP   + E_W * 4;
static constexpr size_t O_QKVW = O_WPT  + E_W * 4;
static constexpr size_t O_PRJW = O_QKVW + E_QKVW * 4;
static constexpr size_t O_NSX  = O_PRJW + E_A * 4;
static constexpr size_t O_NSXT = O_NSX  + 3 * E_W * 4;
static constexpr size_t O_NSA  = O_NSXT + 3 * E_W * 4;
static constexpr size_t O_NSA2 = O_NSA  + 3 * E_A * 4;
static constexpr size_t POOL_B = O_NSA2 + 3 * E_A * 4;
__device__ __align__(1024) unsigned char g_bf[POOL_B];

// ================= tcgen05 split-bf16 GEMM (3-stage, reg-batched, z-batched) ======
#define TC_SMEM (3 * 65536 + 1024)

__global__ void __launch_bounds__(256, 1) tc_gemm(
    const bf16* __restrict__ Ahi, const bf16* __restrict__ Alo,
    const bf16* __restrict__ Bhi, const bf16* __restrict__ Blo,
    int Kp, float* __restrict__ C, int ldc,
    const float* __restrict__ E, int ldE,
    float alpha, float beta, int M,
    i64 az, i64 bz, i64 cz, i64 ez,
    bf16* __restrict__ Ohi, bf16* __restrict__ Olo, int ldo, i64 oz)
{
#if TC_HAS_TCGEN05
    extern __shared__ unsigned char dsm_raw[];
    __shared__ __align__(8) u64 s_mb[3];
    __shared__ uint32_t s_tmem[1];

    const int tid = threadIdx.x;
    const int wid = tid >> 5;
    const int lane = tid & 31;
    const i64 zz = blockIdx.z;
    Ahi += zz * az; Alo += zz * az;
    Bhi += zz * bz; Blo += zz * bz;
    if (C)   C   += zz * cz;
    if (E)   E   += zz * ez;
    if (Ohi) { Ohi += zz * oz; Olo += zz * oz; }

    const uint32_t sb  = (smem_u32(dsm_raw) + 1023) & ~1023u;
    const uint32_t mbB = smem_u32(&s_mb[0]);

    if (tid == 0) {
        MBARRIER_INIT(mbB, 1);
        MBARRIER_INIT(mbB + 8, 1);
        MBARRIER_INIT(mbB + 16, 1);
    }
    if (wid == 0) {
        TCGEN05_ALLOC(smem_u32(s_tmem), 128);
        TCGEN05_RELINQ();
    }
    __syncthreads();
    const uint32_t tmem = s_tmem[0];

    const int m0 = blockIdx.y * 128;
    const int n0 = blockIdx.x * 128;

    const int row  = tid >> 1;
    const int hoff = (tid & 1) * 64;
    const char* pA[4];
    pA[0] = (const char*)(Ahi + (size_t)(m0 + row) * Kp);
    pA[1] = (const char*)(Alo + (size_t)(m0 + row) * Kp);
    pA[2] = (const char*)(Bhi + (size_t)(n0 + row) * Kp);
    pA[3] = (const char*)(Blo + (size_t)(n0 + row) * Kp);
    const uint32_t swbase = (uint32_t)row * 128 + hoff;

    uint4 v[16];
#define TCFETCH(cc) do { const size_t gb_ = (size_t)(cc) * 128 + hoff;                 \
    _Pragma("unroll") for (int q_ = 0; q_ < 4; ++q_)                                   \
    _Pragma("unroll") for (int j_ = 0; j_ < 4; ++j_)                                   \
        v[q_ * 4 + j_] = *reinterpret_cast<const uint4*>(pA[q_] + gb_ + j_ * 16);      \
    } while (0)

    const int NC = Kp >> 6;
    TCFETCH(0);
    int m3 = 0, div3 = 0;
    for (int c = 0; c < NC; ++c) {
        const uint32_t mbs = mbB + (uint32_t)m3 * 8;
        const uint32_t stg = sb + (uint32_t)m3 * 65536u;
        if (div3 >= 1) { MBARRIER_WAIT_PARITY(mbs, (div3 - 1) & 1); }
#pragma unroll
        for (int q = 0; q < 4; ++q) {
            const uint32_t tb = stg + (uint32_t)q * 16384u;
#pragma unroll
            for (int j = 0; j < 4; ++j)
                STS128(v[q * 4 + j].x, v[q * 4 + j].y, v[q * 4 + j].z, v[q * 4 + j].w,
                       tb + SWZ(swbase + j * 16));
        }
        if (c + 1 < NC) { TCFETCH(c + 1); }   // LDGs overlap sync + MMA below
        FENCE_ASYNC();
        __syncthreads();
        if (wid == 0 && elect1()) {
            u64 aH = mkdesc(stg);
            u64 aL = mkdesc(stg + 16384);
            u64 bH = mkdesc(stg + 32768);
            u64 bL = mkdesc(stg + 49152);
#pragma unroll
            for (int ks = 0; ks < 4; ++ks)
                mma_f16_ss(tmem, aH + ks * 2, bH + ks * 2, TCIDESC, !(c == 0 && ks == 0));
#pragma unroll
            for (int ks = 0; ks < 4; ++ks)
                mma_f16_ss(tmem, aH + ks * 2, bL + ks * 2, TCIDESC, true);
#pragma unroll
            for (int ks = 0; ks < 4; ++ks)
                mma_f16_ss(tmem, aL + ks * 2, bH + ks * 2, TCIDESC, true);
            TCGEN05_COMMIT(mbs);
        }
        if (++m3 == 3) { m3 = 0; ++div3; }
    }
    {
        const int cl = NC - 1;
        MBARRIER_WAIT_PARITY(mbB + (uint32_t)(cl % 3) * 8, (cl / 3) & 1);
    }
    TCGEN05_FENCE_AFTER();

    // epilogue
    const int sub = wid & 3;
    const int colb = (wid < 4) ? 0 : 64;
    const int m = m0 + sub * 32 + lane;
#pragma unroll
    for (int half = 0; half < 2; ++half) {
        uint32_t r32[32];
        TCGEN05_LD_X32(r32, tmem + colb + half * 32);
        TCGEN05_WAIT_LD();
        if (m < M) {
            const int ncol = n0 + colb + half * 32;
            float o[32];
            if (beta != 0.f) {
                const float* erow = E + (size_t)m * ldE + ncol;
#pragma unroll
                for (int j = 0; j < 32; j += 4) {
                    float4 e = *reinterpret_cast<const float4*>(erow + j);
                    o[j]     = alpha * __uint_as_float(r32[j])     + beta * e.x;
                    o[j + 1] = alpha * __uint_as_float(r32[j + 1]) + beta * e.y;
                    o[j + 2] = alpha * __uint_as_float(r32[j + 2]) + beta * e.z;
                    o[j + 3] = alpha * __uint_as_float(r32[j + 3]) + beta * e.w;
                }
            } else {
#pragma unroll
                for (int j = 0; j < 32; ++j) o[j] = alpha * __uint_as_float(r32[j]);
            }
            if (C) {
                float* crow = C + (size_t)m * ldc + ncol;
#pragma unroll
                for (int j = 0; j < 32; j += 4)
                    *reinterpret_cast<float4*>(crow + j) = make_float4(o[j], o[j+1], o[j+2], o[j+3]);
            }
            if (Ohi) {
                bf16* hrow = Ohi + (size_t)m * ldo + ncol;
                bf16* lrow = Olo + (size_t)m * ldo + ncol;
#pragma unroll
                for (int j = 0; j < 32; j += 4) {
                    __align__(8) bf16 hv[4];
                    __align__(8) bf16 lv[4];
#pragma unroll
                    for (int t = 0; t < 4; ++t) {
                        bf16 hb_ = __float2bfloat16(o[j + t]);
                        hv[t] = hb_;
                        lv[t] = __float2bfloat16(o[j + t] - __bfloat162float(hb_));
                    }
                    *reinterpret_cast<uint2*>(hrow + j) = *reinterpret_cast<const uint2*>(hv);
                    *reinterpret_cast<uint2*>(lrow + j) = *reinterpret_cast<const uint2*>(lv);
                }
            }
        }
    }
    __syncthreads();
    if (wid == 0) TCGEN05_DEALLOC(tmem, 128);
#undef TCFETCH
#endif
}

// ================= conversion kernels (z-batched) =================
__global__ void conv_k(const float* __restrict__ src, int ld, int R, int C,
                       bf16* __restrict__ hi, bf16* __restrict__ lo, int Cp,
                       i64 srcZ, i64 dstZ)
{
    const i64 z = blockIdx.z;
    src += z * srcZ; hi += z * dstZ; lo += z * dstZ;
    int c = (blockIdx.x * blockDim.x + threadIdx.x) * 4;
    int r = blockIdx.y;
    if (c >= Cp) return;
    __align__(8) bf16 h4[4];
    __align__(8) bf16 l4[4];
    if (r < R && c < C) {
        float4 fv = *reinterpret_cast<const float4*>(src + (size_t)r * ld + c);
        float vv[4] = {fv.x, fv.y, fv.z, fv.w};
#pragma unroll
        for (int j = 0; j < 4; j++) {
            bf16 h = __float2bfloat16(vv[j]);
            h4[j] = h;
            l4[j] = __float2bfloat16(vv[j] - __bfloat162float(h));
        }
    } else {
#pragma unroll
        for (int j = 0; j < 4; j++) { h4[j] = __float2bfloat16(0.f); l4[j] = h4[j]; }
    }
    size_t o = (size_t)r * Cp + c;
    *reinterpret_cast<uint2*>(hi + o) = *reinterpret_cast<const uint2*>(h4);
    *reinterpret_cast<uint2*>(lo + o) = *reinterpret_cast<const uint2*>(l4);
}

__global__ void convT_k(const float* __restrict__ src, int ld, int R, int C,
                        bf16* __restrict__ hi, bf16* __restrict__ lo, int Rp,
                        i64 srcZ, i64 dstZ)
{
    __shared__ float t[32][33];
    const i64 z = blockIdx.z;
    src += z * srcZ; hi += z * dstZ; lo += z * dstZ;
    int c0 = blockIdx.x * 32;
    int r0 = blockIdx.y * 32;
    int tx = threadIdx.x, ty = threadIdx.y;
#pragma unroll
    for (int j = 0; j < 32; j += 8) {
        int r = r0 + ty + j;
        t[ty + j][tx] = (r < R) ? src[(size_t)r * ld + c0 + tx] : 0.f;
    }
    __syncthreads();
#pragma unroll
    for (int j = 0; j < 32; j += 8) {
        float fv = t[tx][ty + j];
        size_t o = (size_t)(c0 + ty + j) * Rp + r0 + tx;
        bf16 h = __float2bfloat16(fv);
        hi[o] = h;
        lo[o] = __float2bfloat16(fv - __bfloat162float(h));
    }
}

// ================= elementwise / reductions =================
__global__ void norm_heads_k(float* __restrict__ base,
                             const float* __restrict__ sc, const float* __restrict__ bi)
{
    int w = (blockIdx.x * blockDim.x + threadIdx.x) >> 5;
    int lane = threadIdx.x & 31;
    if (w >= NTOK * 16) return;
    int rowi = w >> 4, head = w & 15;
    float* p = base + (size_t)rowi * (3 * DIMM) + head * 64;
    float x0 = p[lane], x1 = p[lane + 32];
    float ss = x0 * x0 + x1 * x1;
#pragma unroll
    for (int o = 16; o; o >>= 1) ss += __shfl_xor_sync(0xffffffffu, ss, o);
    float inv = 1.f / (sqrtf(ss) + 1e-6f);
    p[lane]      = x0 * inv * sc[lane]      + bi[lane];
    p[lane + 32] = x1 * inv * sc[lane + 32] + bi[lane + 32];
}

// h = swish(kg)*kv, also emit bf16 hi/lo pair of h (same linear layout)
__global__ void swish_pair_k(const float4* __restrict__ kg, const float4* __restrict__ kv,
                             float4* __restrict__ h, bf16* __restrict__ hhi,
                             bf16* __restrict__ hlo, int n4)
{
    int i = blockIdx.x * blockDim.x + threadIdx.x;
    if (i >= n4) return;
    float4 g = kg[i], u = kv[i], o;
    o.x = g.x / (1.f + __expf(-g.x)) * u.x;
    o.y = g.y / (1.f + __expf(-g.y)) * u.y;
    o.z = g.z / (1.f + __expf(-g.z)) * u.z;
    o.w = g.w / (1.f + __expf(-g.w)) * u.w;
    h[i] = o;
    float vv[4] = {o.x, o.y, o.z, o.w};
    __align__(8) bf16 hv[4];
    __align__(8) bf16 lv[4];
#pragma unroll
    for (int j = 0; j < 4; j++) {
        bf16 hb_ = __float2bfloat16(vv[j]);
        hv[j] = hb_;
        lv[j] = __float2bfloat16(vv[j] - __bfloat162float(hb_));
    }
    reinterpret_cast<uint2*>(hhi)[i] = *reinterpret_cast<const uint2*>(hv);
    reinterpret_cast<uint2*>(hlo)[i] = *reinterpret_cast<const uint2*>(lv);
}

__global__ void bw_ew_k(const float4* __restrict__ dh,
                        float4* __restrict__ kg_io, float4* __restrict__ kv_io, int n4)
{
    int i = blockIdx.x * blockDim.x + threadIdx.x;
    if (i >= n4) return;
    float4 d = dh[i], g = kg_io[i], u = kv_io[i], dg, du;
#define BW1(c) { float s = 1.f/(1.f+__expf(-g.c)); float sw = g.c*s; \
                 du.c = d.c*sw; dg.c = d.c*u.c*s*(1.f + g.c*(1.f-s)); }
    BW1(x) BW1(y) BW1(z) BW1(w)
#undef BW1
    kv_io[i] = du;
    kg_io[i] = dg;
}

__global__ void zero3_k(double* p) { if (threadIdx.x < 3) p[threadIdx.x] = 0.0; }

__global__ void sumsq3_k(const float* __restrict__ x, int n, double* __restrict__ out)
{
    __shared__ double sm[256];
    const int z = blockIdx.y;
    x += (size_t)z * n;
    double a = 0.0;
    for (int i = blockIdx.x * blockDim.x + threadIdx.x; i < n; i += gridDim.x * blockDim.x) {
        float fv = x[i];
        a += (double)fv * (double)fv;
    }
    sm[threadIdx.x] = a;
    __syncthreads();
    for (int s = 128; s; s >>= 1) {
        if (threadIdx.x < s) sm[threadIdx.x] += sm[threadIdx.x + s];
        __syncthreads();
    }
    if (threadIdx.x == 0) atomicAdd(&out[z], sm[0]);
}

__global__ void scale3_k(const float4* __restrict__ g, float4* __restrict__ X, int n4,
                         const double* __restrict__ nrm)
{
    const int z = blockIdx.y;
    int i = blockIdx.x * blockDim.x + threadIdx.x;
    if (i >= n4) return;
    float inv = (float)(1.0 / (sqrt(nrm[z]) + 1e-7));
    float4 fv = g[(size_t)z * n4 + i];
    fv.x *= inv; fv.y *= inv; fv.z *= inv; fv.w *= inv;
    X[(size_t)z * n4 + i] = fv;
}

__global__ void transpose_k(const float* __restrict__ src, float* __restrict__ dst,
                            int R, int C)
{
    __shared__ float t[32][33];
    int c0 = blockIdx.x * 32, r0 = blockIdx.y * 32;
    int x = c0 + threadIdx.x;
#pragma unroll
    for (int j = 0; j < 32; j += 8)
        t[threadIdx.y + j][threadIdx.x] = src[(size_t)(r0 + threadIdx.y + j) * C + x];
    __syncthreads();
    int x2 = r0 + threadIdx.x;
#pragma unroll
    for (int j = 0; j < 32; j += 8)
        dst[(size_t)(c0 + threadIdx.y + j) * R + x2] = t[threadIdx.x][threadIdx.y + j];
}

__global__ void upd_k(float4* __restrict__ p, const float4* __restrict__ x, int n4)
{
    int i = blockIdx.x * blockDim.x + threadIdx.x;
    if (i >= n4) return;
    float4 a = p[i], bb = x[i];
    a.x -= LRATE * bb.x; a.y -= LRATE * bb.y; a.z -= LRATE * bb.z; a.w -= LRATE * bb.w;
    p[i] = a;
}

// ================= host orchestration =================
struct BP { bf16 *hi, *lo; };

static void* symaddr(const void* s) { void* p = nullptr; cudaGetSymbolAddress(&p, s); return p; }

static void tc(BP A, BP B, int Kp, float* C, int ldc, int M, int N,
               float alpha, float beta, const float* E, int ldE,
               int nz = 1, i64 az = 0, i64 bz = 0, i64 cz = 0, i64 ez = 0,
               BP O = {nullptr, nullptr}, int ldo = 0, i64 oz = 0)
{
    dim3 gr(N / 128, (M + 127) / 128, nz);
    tc_gemm<<<gr, 256, TC_SMEM>>>(A.hi, A.lo, B.hi, B.lo, Kp, C, ldc, E, ldE,
                                  alpha, beta, M, az, bz, cz, ez, O.hi, O.lo, ldo, oz);
}

static void conv(const float* s, int ld, int R, int C, BP d, int Rp, int Cp,
                 int nz = 1, i64 sZ = 0, i64 dZ = 0)
{
    dim3 gr((Cp / 4 + 255) / 256, Rp, nz);
    conv_k<<<gr, 256>>>(s, ld, R, C, d.hi, d.lo, Cp, sZ, dZ);
}

static void convT(const float* s, int ld, int R, int C, BP d, int Rp,
                  int nz = 1, i64 sZ = 0, i64 dZ = 0)
{
    dim3 gr(C / 32, Rp / 32, nz);
    convT_k<<<gr, dim3(32, 8)>>>(s, ld, R, C, d.hi, d.lo, Rp, sZ, dZ);
}

extern "C" void kernel_launch(void* const* d_in, const int* in_sizes, int n_in,
                              void* d_out, int out_size)
{
    const float* x        = (const float*)d_in[0];
    const float* qkv_w    = (const float*)d_in[1];
    const float* qkv_b    = (const float*)d_in[2];
    const float* qn_s     = (const float*)d_in[3];
    const float* qn_b     = (const float*)d_in[4];
    const float* kn_s     = (const float*)d_in[5];
    const float* kn_b     = (const float*)d_in[6];
    const float* ttt_gate = (const float*)d_in[7];
    const float* ttt_val  = (const float*)d_in[8];
    const float* ttt_proj = (const float*)d_in[9];
    const float* proj_w   = (const float*)d_in[10];
    const float* proj_b   = (const float*)d_in[11];
    float* out = (float*)d_out;

    cudaFuncSetAttribute(tc_gemm, cudaFuncAttributeMaxDynamicSharedMemorySize, TC_SMEM);

    float* qkv  = (float*)symaddr(g_qkv);
    float* kgv  = (float*)symaddr(g_kgv);
    float* h    = (float*)symaddr(g_h);
    float* r    = (float*)symaddr(g_r);
    float* GV   = (float*)symaddr(g_GV);
    float* P    = (float*)symaddr(g_P);
    float* grad = (float*)symaddr(g_grad);
    float* X1   = (float*)symaddr(g_X1);
    float* X2   = (float*)symaddr(g_X2);
    float* Amat = (float*)symaddr(g_A);
    double* nrm = (double*)symaddr(g_nrm);
    unsigned char* pool = (unsigned char*)symaddr(g_bf);

    auto bp = [&](size_t off, size_t elems) { BP b; b.hi = (bf16*)(pool + off); b.lo = b.hi + elems; return b; };

    BP xb    = bp(O_X, E_TOKD);      // x pairs, later reused as r pairs
    BP kb    = bp(O_K, E_TOKD);
    BP kTb   = bp(O_KT, E_TOKD);
    BP qb    = bp(O_Q, E_TOKD);
    BP rTb   = bp(O_RT, E_TOKD);
    BP hb    = bp(O_H, E_TOKH);
    BP hTb   = bp(O_HT, E_TOKH);
    BP dkgT  = bp(O_DKGT, E_TOKH);
    BP wGt   = bp(O_WGT, E_W);
    BP wP    = bp(O_WP,  E_W);
    BP wPt   = bp(O_WPT, E_W);
    BP qkvwT = bp(O_QKVW, E_QKVW);
    BP projwT = bp(O_PRJW, E_A);
    BP nsX   = bp(O_NSX,  E_W);
    BP nsXT  = bp(O_NSXT, E_W);
    BP nsA   = bp(O_NSA,  E_A);
    BP nsA2  = bp(O_NSA2, E_A);
    BP NOB   = {nullptr, nullptr};

    const size_t TB = sizeof(float) * E_W;
    cudaMemcpyAsync(GV,       ttt_gate, TB, cudaMemcpyDeviceToDevice, 0);
    cudaMemcpyAsync(GV + E_W, ttt_val,  TB, cudaMemcpyDeviceToDevice, 0);
    cudaMemcpyAsync(P,        ttt_proj, TB, cudaMemcpyDeviceToDevice, 0);

    // ---- qkv = x @ qkv_w + b ----
    conv (x, DIMM, NTOK, DIMM, xb, MP, DIMM);
    convT(qkv_w, 3 * DIMM, DIMM, 3 * DIMM, qkvwT, DIMM);
    tc(xb, qkvwT, DIMM, qkv, 3 * DIMM, NTOK, 3 * DIMM, 1.f, 1.f, qkv_b, 0);

    {
        int nb = (NTOK * 16 * 32 + 255) / 256;
        norm_heads_k<<<nb, 256>>>(qkv, qn_s, qn_b);
        norm_heads_k<<<nb, 256>>>(qkv + DIMM, kn_s, kn_b);
    }

    const float* kmat = qkv + DIMM;
    const float* vmat = qkv + 2 * DIMM;
    conv (kmat, 3 * DIMM, NTOK, DIMM, kb, MP, DIMM);
    convT(kmat, 3 * DIMM, NTOK, DIMM, kTb, MP);
    conv (qkv, 3 * DIMM, NTOK, DIMM, qb, MP, DIMM);

    const int NH4 = NTOK * HIDD / 4;
    const int nbH = (NH4 + 255) / 256;
    const i64 ZW = 2 * (i64)E_W;       // BP-region stride (elements)
    const i64 ZA = 2 * (i64)E_A;
    const i64 ZTH = 2 * (i64)E_TOKH;
    const i64 KGV = (i64)NTOK * HIDD;

    for (int step = 0; step < 2; ++step) {
        convT(GV, HIDD, DIMM, HIDD, wGt, DIMM, 2, (i64)E_W, ZW);  // wGt | wVt
        conv (P, DIMM, HIDD, DIMM, wP, HIDD, DIMM);
        convT(P, DIMM, HIDD, DIMM, wPt, HIDD);

        // kg|kv = k @ {G,V}   (batched z=2, shared A)
        tc(kb, wGt, DIMM, kgv, HIDD, NTOK, HIDD, 1.f, 0.f, nullptr, 0,
           2, 0, ZW, KGV, 0);
        swish_pair_k<<<nbH, 256>>>((const float4*)kgv, (const float4*)(kgv + KGV),
                                   (float4*)h, hb.hi, hb.lo, NH4);
        convT(h, HIDD, NTOK, HIDD, hTb, MP);
        // r = h@P - v   (+ r pairs into xb)
        tc(hb, wPt, HIDD, r, DIMM, NTOK, DIMM, 1.f, -1.f, vmat, 3 * DIMM,
           1, 0, 0, 0, 0, xb, DIMM, 0);
        convT(r, DIMM, NTOK, DIMM, rTb, MP);
        // gP^T = r^T @ h
        tc(rTb, hTb, MP, grad + 2 * E_W, HIDD, DIMM, HIDD, 1.f, 0.f, nullptr, 0);
        // dh = r @ P^T
        tc(xb, wP, DIMM, h, HIDD, NTOK, HIDD, 1.f, 0.f, nullptr, 0);
        bw_ew_k<<<nbH, 256>>>((const float4*)h, (float4*)kgv, (float4*)(kgv + KGV), NH4);
        convT(kgv, HIDD, NTOK, HIDD, dkgT, MP, 2, KGV, ZTH);
        // gG|gV = k^T @ {dkg,dkv}
        tc(kTb, dkgT, MP, grad, HIDD, DIMM, HIDD, 1.f, 0.f, nullptr, 0,
           2, 0, ZTH, (i64)E_W, 0);

        // ---- batched Newton-Schulz over {gG, gV, gP^T} ----
        zero3_k<<<1, 4>>>(nrm);
        sumsq3_k<<<dim3(256, 3), 256>>>(grad, (int)E_W, nrm);
        scale3_k<<<dim3(((int)E_W / 4 + 255) / 256, 3), 256>>>(
            (const float4*)grad, (float4*)X1, (int)E_W / 4, nrm);
        float* X = X1;
        float* Y = X2;
        conv (X, HIDD, DIMM, HIDD, nsX, DIMM, HIDD, 3, (i64)E_W, ZW);
        convT(X, HIDD, DIMM, HIDD, nsXT, DIMM, 3, (i64)E_W, ZW);
        for (int it = 0; it < 5; ++it) {
            // A = X @ X^T  (+ pairs)
            tc(nsX, nsX, HIDD, Amat, DIMM, DIMM, DIMM, 1.f, 0.f, nullptr, 0,
               3, ZW, ZW, (i64)E_A, 0, nsA, DIMM, ZA);
            // A2 = c*A@A + b*A  (pairs only)
            tc(nsA, nsA, DIMM, nullptr, 0, DIMM, DIMM, NS_C, NS_B, Amat, DIMM,
               3, ZA, ZA, 0, (i64)E_A, nsA2, DIMM, ZA);
            // Y = A2 @ X + a*X  (+ pairs into nsX for next iter)
            tc(nsA2, nsXT, DIMM, Y, HIDD, DIMM, HIDD, 1.f, NS_A, X, HIDD,
               3, ZA, ZW, (i64)E_W, (i64)E_W, nsX, HIDD, ZW);
            if (it < 4)
                convT(Y, HIDD, DIMM, HIDD, nsXT, DIMM, 3, (i64)E_W, ZW);
            float* t = X; X = Y; Y = t;
        }
        // updates: G,V direct (first 2*E_W of X contiguous)
        upd_k<<<((int)(2 * E_W / 4) + 255) / 256, 256>>>((float4*)GV, (const float4*)X, (int)(2 * E_W / 4));
        // P: transpose X[2] back to [HIDD,DIMM]
        {
            dim3 gr(HIDD / 32, DIMM / 32);
            transpose_k<<<gr, dim3(32, 8)>>>(X + 2 * E_W, Y, DIMM, HIDD);
            upd_k<<<((int)(E_W / 4) + 255) / 256, 256>>>((float4*)P, (const float4*)Y, (int)(E_W / 4));
        }
    }

    // ---- final forward with q ----
    convT(GV, HIDD, DIMM, HIDD, wGt, DIMM, 2, (i64)E_W, ZW);
    convT(P, DIMM, HIDD, DIMM, wPt, HIDD);
    tc(qb, wGt, DIMM, kgv, HIDD, NTOK, HIDD, 1.f, 0.f, nullptr, 0,
       2, 0, ZW, KGV, 0);
    swish_pair_k<<<nbH, 256>>>((const float4*)kgv, (const float4*)(kgv + KGV),
                               (float4*)h, hb.hi, hb.lo, NH4);
    // r pairs only
    tc(hb, wPt, HIDD, nullptr, 0, NTOK, DIMM, 1.f, 0.f, nullptr, 0,
       1, 0, 0, 0, 0, xb, DIMM, 0);
    convT(proj_w, DIMM, DIMM, DIMM, projwT, DIMM);
    tc(xb, projwT, DIMM, out, DIMM, NTOK, DIMM, 1.f, 1.f, proj_b, 0);
}

// round 6
// speedup vs baseline: 5.8552x; 1.4087x over previous
#include <cuda_runtime.h>
#include <cuda_bf16.h>
#include <cstdint>
#include <cstddef>

// ---------------- problem constants ----------------
#define NTOK 10992
#define MP   11008
#define DIMM 1024
#define HIDD 4096
#define LRATE 0.1f
#define NS_A 3.4445f
#define NS_B (-4.7750f)
#define NS_C 2.0315f

typedef unsigned long long u64;
typedef long long i64;
typedef __nv_bfloat16 bf16;

#if !defined(__CUDA_ARCH__) || defined(__CUDA_ARCH_FEAT_SM103_ALL)
#define TC_HAS_TCGEN05 1
#else
#define TC_HAS_TCGEN05 0
#endif

// ================= PTX helpers (sm_103a) =================
#if TC_HAS_TCGEN05
__device__ __forceinline__ uint32_t smem_u32(const void* p) {
    uint32_t a;
    asm("{ .reg .u64 t; cvta.to.shared.u64 t, %1; cvt.u32.u64 %0, t; }" : "=r"(a) : "l"(p));
    return a;
}
__device__ __forceinline__ uint32_t elect1() {
    uint32_t p;
    asm volatile("{\n.reg .pred p;\nelect.sync _|p, 0xFFFFFFFF;\nselp.b32 %0,1,0,p;\n}" : "=r"(p));
    return p;
}
#define MBARRIER_INIT(a, c) \
    asm volatile("mbarrier.init.shared.b64 [%0], %1;" :: "r"((uint32_t)(a)), "r"((uint32_t)(c)) : "memory")
#define MBARRIER_WAIT_PARITY(a, ph) do { \
    uint32_t _m = (uint32_t)(a); uint32_t _p = (uint32_t)(ph); uint32_t _d; \
    asm volatile("{\n.reg .pred p;\nmbarrier.try_wait.parity.acquire.cta.shared::cta.b64 p, [%1], %2;\nselp.b32 %0,1,0,p;\n}" \
        : "=r"(_d) : "r"(_m), "r"(_p) : "memory"); \
    if (!_d) { \
        asm volatile("{\n.reg .pred P1;\nWL_%=:\nmbarrier.try_wait.parity.acquire.cta.shared::cta.b64 P1, [%0], %1, 0x989680;\n@P1 bra.uni WD_%=;\nbra.uni WL_%=;\nWD_%=:\n}" \
            :: "r"(_m), "r"(_p) : "memory"); \
    } } while (0)
#define TCGEN05_ALLOC(sa, n) \
    asm volatile("tcgen05.alloc.cta_group::1.sync.aligned.shared::cta.b32 [%0], %1;" \
        :: "r"((uint32_t)(sa)), "r"((uint32_t)(n)) : "memory")
#define TCGEN05_RELINQ() \
    asm volatile("tcgen05.relinquish_alloc_permit.cta_group::1.sync.aligned;")
#define TCGEN05_DEALLOC(t, n) \
    asm volatile("tcgen05.dealloc.cta_group::1.sync.aligned.b32 %0, %1;" :: "r"(t), "r"((uint32_t)(n)))
#define TCGEN05_COMMIT(a) \
    asm volatile("tcgen05.commit.cta_group::1.mbarrier::arrive::one.shared::cluster.b64 [%0];" \
        :: "r"((uint32_t)(a)) : "memory")
#define TCGEN05_FENCE_AFTER() asm volatile("tcgen05.fence::after_thread_sync;" ::: "memory")
#define TCGEN05_WAIT_LD() asm volatile("tcgen05.wait::ld.sync.aligned;" ::: "memory")
#define FENCE_ASYNC() asm volatile("fence.proxy.async.shared::cta;" ::: "memory")
#define STS128(r0, r1, r2, r3, a) \
    asm volatile("st.shared.v4.b32 [%0], {%1,%2,%3,%4};" :: "r"(a), "r"(r0), "r"(r1), "r"(r2), "r"(r3) : "memory")
#define TCGEN05_LD_X32(r, ta) \
    asm volatile("tcgen05.ld.sync.aligned.32x32b.x32.b32 " \
        "{%0,%1,%2,%3,%4,%5,%6,%7,%8,%9,%10,%11,%12,%13,%14,%15," \
        "%16,%17,%18,%19,%20,%21,%22,%23,%24,%25,%26,%27,%28,%29,%30,%31}, [%32];" \
        : "=r"((r)[0]), "=r"((r)[1]), "=r"((r)[2]), "=r"((r)[3]), "=r"((r)[4]), "=r"((r)[5]), \
          "=r"((r)[6]), "=r"((r)[7]), "=r"((r)[8]), "=r"((r)[9]), "=r"((r)[10]), "=r"((r)[11]), \
          "=r"((r)[12]), "=r"((r)[13]), "=r"((r)[14]), "=r"((r)[15]), "=r"((r)[16]), "=r"((r)[17]), \
          "=r"((r)[18]), "=r"((r)[19]), "=r"((r)[20]), "=r"((r)[21]), "=r"((r)[22]), "=r"((r)[23]), \
          "=r"((r)[24]), "=r"((r)[25]), "=r"((r)[26]), "=r"((r)[27]), "=r"((r)[28]), "=r"((r)[29]), \
          "=r"((r)[30]), "=r"((r)[31]) : "r"(ta))

static constexpr u64 SMEM_DESC_BASE =
    (u64(2) << 61) | (u64(1) << 46) | (u64(64) << 32) | (u64(1) << 16);
__device__ __forceinline__ u64 mkdesc(uint32_t sa) {
    return SMEM_DESC_BASE | ((u64)(sa >> 4) & 0x3FFF);
}
__device__ __forceinline__ void mma_f16_ss(uint32_t d, u64 ad, u64 bd, uint32_t idesc, bool acc) {
    uint32_t en = acc ? 1u : 0u;
    asm volatile(
        "{\n\t.reg .pred p;\n\tsetp.ne.u32 p, %4, 0;\n\t"
        "tcgen05.mma.cta_group::1.kind::f16 [%0], %1, %2, %3, {%5,%5,%5,%5}, p;\n\t}"
        :: "r"(d), "l"(ad), "l"(bd), "r"(idesc), "r"(en), "r"(0u) : "memory");
}
#endif

#define SWZ(b) ((b) ^ (((b) >> 3) & 0x70))
#define TCIDESC 0x08200490u   // dtype=F32, a=BF16, b=BF16, N=128, M=128

// ---------------- fp32 scratch ----------------
static constexpr size_t E_TOKD = (size_t)MP * DIMM;
static constexpr size_t E_TOKH = (size_t)MP * HIDD;
static constexpr size_t E_W    = (size_t)DIMM * HIDD;
static constexpr size_t E_A    = (size_t)DIMM * DIMM;
static constexpr size_t E_QKVW = (size_t)DIMM * 3 * DIMM;

__device__ float g_qkv [(size_t)NTOK * 3 * DIMM];
__device__ float g_kgv [(size_t)2 * NTOK * HIDD];   // kg | kv  (also dkg|dkv)
__device__ float g_h   [(size_t)NTOK * HIDD];
__device__ float g_r   [(size_t)NTOK * DIMM];
__device__ float g_GV  [2 * E_W];                   // G | V
__device__ float g_P   [E_W];
__device__ float g_grad[3 * E_W];                   // gG | gV | gP^T
__device__ float g_X1  [3 * E_W];
__device__ float g_X2  [3 * E_W];
__device__ float g_A   [3 * E_A];
__device__ double g_nrm[3];

// ---------------- bf16 hi/lo pool ----------------
static constexpr size_t O_X    = 0;
static constexpr size_t O_K    = O_X    + E_TOKD * 4;
static constexpr size_t O_KT   = O_K    + E_TOKD * 4;
static constexpr size_t O_Q    = O_KT   + E_TOKD * 4;
static constexpr size_t O_RT   = O_Q    + E_TOKD * 4;
static constexpr size_t O_H    = O_RT   + E_TOKD * 4;
static constexpr size_t O_HT   = O_H    + E_TOKH * 4;
static constexpr size_t O_DKGT = O_HT   + E_TOKH * 4;
static constexpr size_t O_DKVT = O_DKGT + E_TOKH * 4;
static constexpr size_t O_WGT  = O_DKVT + E_TOKH * 4;
static constexpr size_t O_WVT  = O_WGT  + E_W * 4;
static constexpr size_t O_WP   = O_WVT  + E_W * 4;
static constexpr size_t O_WPT  = O_WP   + E_W * 4;
static constexpr size_t O_QKVW = O_WPT  + E_W * 4;
static constexpr size_t O_PRJW = O_QKVW + E_QKVW * 4;
static constexpr size_t O_NSX  = O_PRJW + E_A * 4;
static constexpr size_t O_NSXT = O_NSX  + 3 * E_W * 4;
static constexpr size_t O_NSA  = O_NSXT + 3 * E_W * 4;
static constexpr size_t O_NSA2 = O_NSA  + 3 * E_A * 4;
static constexpr size_t POOL_B = O_NSA2 + 3 * E_A * 4;
__device__ __align__(1024) unsigned char g_bf[POOL_B];

// ================= tcgen05 split-bf16 GEMM (3-stage, coalesced, z-batched) ======
#define TC_SMEM (3 * 65536 + 1024)

__global__ void __launch_bounds__(256, 1) tc_gemm(
    const bf16* __restrict__ Ahi, const bf16* __restrict__ Alo,
    const bf16* __restrict__ Bhi, const bf16* __restrict__ Blo,
    int Kp, float* __restrict__ C, int ldc,
    const float* __restrict__ E, int ldE,
    float alpha, float beta, int M,
    i64 az, i64 bz, i64 cz, i64 ez,
    bf16* __restrict__ Ohi, bf16* __restrict__ Olo, int ldo, i64 oz)
{
#if TC_HAS_TCGEN05
    extern __shared__ unsigned char dsm_raw[];
    __shared__ __align__(8) u64 s_mb[3];
    __shared__ uint32_t s_tmem[1];

    const int tid = threadIdx.x;
    const int wid = tid >> 5;
    const int lane = tid & 31;
    const i64 zz = blockIdx.z;
    Ahi += zz * az; Alo += zz * az;
    Bhi += zz * bz; Blo += zz * bz;
    if (C)   C   += zz * cz;
    if (E)   E   += zz * ez;
    if (Ohi) { Ohi += zz * oz; Olo += zz * oz; }

    const uint32_t sb  = (smem_u32(dsm_raw) + 1023) & ~1023u;
    const uint32_t mbB = smem_u32(&s_mb[0]);

    if (tid == 0) {
        MBARRIER_INIT(mbB, 1);
        MBARRIER_INIT(mbB + 8, 1);
        MBARRIER_INIT(mbB + 16, 1);
    }
    if (wid == 0) {
        TCGEN05_ALLOC(smem_u32(s_tmem), 128);
        TCGEN05_RELINQ();
    }
    __syncthreads();
    const uint32_t tmem = s_tmem[0];

    const int m0 = blockIdx.y * 128;
    const int n0 = blockIdx.x * 128;

    // ---- coalesced staging map ----
    // thread tid handles rows r0+32k (k=0..3), byte-column (tid&7)*16.
    // A warp spans 4 consecutive rows x full 128B -> 4 lines per LDG.128 (minimum).
    const int r0    = tid >> 3;           // 0..31
    const int col16 = (tid & 7) * 16;     // byte col within 128B row
    const size_t rowB = (size_t)Kp * 2;   // bytes per gmem row
    const char* pA[4];
    pA[0] = (const char*)Ahi + (size_t)(m0 + r0) * rowB + col16;
    pA[1] = (const char*)Alo + (size_t)(m0 + r0) * rowB + col16;
    pA[2] = (const char*)Bhi + (size_t)(n0 + r0) * rowB + col16;
    pA[3] = (const char*)Blo + (size_t)(n0 + r0) * rowB + col16;
    uint32_t sw[4];
#pragma unroll
    for (int k = 0; k < 4; ++k)
        sw[k] = SWZ((uint32_t)(r0 + 32 * k) * 128 + col16);

    uint4 v[16];
#define TCFETCH(cc) do { const size_t gb_ = (size_t)(cc) * 128;                         \
    _Pragma("unroll") for (int q_ = 0; q_ < 4; ++q_)                                    \
    _Pragma("unroll") for (int k_ = 0; k_ < 4; ++k_)                                    \
        v[q_ * 4 + k_] = *reinterpret_cast<const uint4*>(pA[q_] + (size_t)(32 * k_) * rowB + gb_); \
    } while (0)

    const int NC = Kp >> 6;
    TCFETCH(0);
    int m3 = 0, div3 = 0;
    for (int c = 0; c < NC; ++c) {
        const uint32_t mbs = mbB + (uint32_t)m3 * 8;
        const uint32_t stg = sb + (uint32_t)m3 * 65536u;
        if (div3 >= 1) { MBARRIER_WAIT_PARITY(mbs, (div3 - 1) & 1); }
#pragma unroll
        for (int q = 0; q < 4; ++q) {
            const uint32_t tb = stg + (uint32_t)q * 16384u;
#pragma unroll
            for (int k = 0; k < 4; ++k)
                STS128(v[q * 4 + k].x, v[q * 4 + k].y, v[q * 4 + k].z, v[q * 4 + k].w,
                       tb + sw[k]);
        }
        if (c + 1 < NC) { TCFETCH(c + 1); }   // LDGs overlap sync + MMA below
        FENCE_ASYNC();
        __syncthreads();
        if (wid == 0 && elect1()) {
            u64 aH = mkdesc(stg);
            u64 aL = mkdesc(stg + 16384);
            u64 bH = mkdesc(stg + 32768);
            u64 bL = mkdesc(stg + 49152);
#pragma unroll
            for (int ks = 0; ks < 4; ++ks)
                mma_f16_ss(tmem, aH + ks * 2, bH + ks * 2, TCIDESC, !(c == 0 && ks == 0));
#pragma unroll
            for (int ks = 0; ks < 4; ++ks)
                mma_f16_ss(tmem, aH + ks * 2, bL + ks * 2, TCIDESC, true);
#pragma unroll
            for (int ks = 0; ks < 4; ++ks)
                mma_f16_ss(tmem, aL + ks * 2, bH + ks * 2, TCIDESC, true);
            TCGEN05_COMMIT(mbs);
        }
        if (++m3 == 3) { m3 = 0; ++div3; }
    }
    {
        const int cl = NC - 1;
        MBARRIER_WAIT_PARITY(mbB + (uint32_t)(cl % 3) * 8, (cl / 3) & 1);
    }
    TCGEN05_FENCE_AFTER();

    // epilogue
    const int sub = wid & 3;
    const int colb = (wid < 4) ? 0 : 64;
    const int m = m0 + sub * 32 + lane;
#pragma unroll
    for (int half = 0; half < 2; ++half) {
        uint32_t r32[32];
        TCGEN05_LD_X32(r32, tmem + colb + half * 32);
        TCGEN05_WAIT_LD();
        if (m < M) {
            const int ncol = n0 + colb + half * 32;
            float o[32];
            if (beta != 0.f) {
                const float* erow = E + (size_t)m * ldE + ncol;
#pragma unroll
                for (int j = 0; j < 32; j += 4) {
                    float4 e = *reinterpret_cast<const float4*>(erow + j);
                    o[j]     = alpha * __uint_as_float(r32[j])     + beta * e.x;
                    o[j + 1] = alpha * __uint_as_float(r32[j + 1]) + beta * e.y;
                    o[j + 2] = alpha * __uint_as_float(r32[j + 2]) + beta * e.z;
                    o[j + 3] = alpha * __uint_as_float(r32[j + 3]) + beta * e.w;
                }
            } else {
#pragma unroll
                for (int j = 0; j < 32; ++j) o[j] = alpha * __uint_as_float(r32[j]);
            }
            if (C) {
                float* crow = C + (size_t)m * ldc + ncol;
#pragma unroll
                for (int j = 0; j < 32; j += 4)
                    *reinterpret_cast<float4*>(crow + j) = make_float4(o[j], o[j+1], o[j+2], o[j+3]);
            }
            if (Ohi) {
                bf16* hrow = Ohi + (size_t)m * ldo + ncol;
                bf16* lrow = Olo + (size_t)m * ldo + ncol;
#pragma unroll
                for (int j = 0; j < 32; j += 4) {
                    __align__(8) bf16 hv[4];
                    __align__(8) bf16 lv[4];
#pragma unroll
                    for (int t = 0; t < 4; ++t) {
                        bf16 hb_ = __float2bfloat16(o[j + t]);
                        hv[t] = hb_;
                        lv[t] = __float2bfloat16(o[j + t] - __bfloat162float(hb_));
                    }
                    *reinterpret_cast<uint2*>(hrow + j) = *reinterpret_cast<const uint2*>(hv);
                    *reinterpret_cast<uint2*>(lrow + j) = *reinterpret_cast<const uint2*>(lv);
                }
            }
        }
    }
    __syncthreads();
    if (wid == 0) TCGEN05_DEALLOC(tmem, 128);
#undef TCFETCH
#endif
}

// ================= conversion kernels (z-batched) =================
__global__ void conv_k(const float* __restrict__ src, int ld, int R, int C,
                       bf16* __restrict__ hi, bf16* __restrict__ lo, int Cp,
                       i64 srcZ, i64 dstZ)
{
    const i64 z = blockIdx.z;
    src += z * srcZ; hi += z * dstZ; lo += z * dstZ;
    int c = (blockIdx.x * blockDim.x + threadIdx.x) * 4;
    int r = blockIdx.y;
    if (c >= Cp) return;
    __align__(8) bf16 h4[4];
    __align__(8) bf16 l4[4];
    if (r < R && c < C) {
        float4 fv = *reinterpret_cast<const float4*>(src + (size_t)r * ld + c);
        float vv[4] = {fv.x, fv.y, fv.z, fv.w};
#pragma unroll
        for (int j = 0; j < 4; j++) {
            bf16 h = __float2bfloat16(vv[j]);
            h4[j] = h;
            l4[j] = __float2bfloat16(vv[j] - __bfloat162float(h));
        }
    } else {
#pragma unroll
        for (int j = 0; j < 4; j++) { h4[j] = __float2bfloat16(0.f); l4[j] = h4[j]; }
    }
    size_t o = (size_t)r * Cp + c;
    *reinterpret_cast<uint2*>(hi + o) = *reinterpret_cast<const uint2*>(h4);
    *reinterpret_cast<uint2*>(lo + o) = *reinterpret_cast<const uint2*>(l4);
}

__global__ void convT_k(const float* __restrict__ src, int ld, int R, int C,
                        bf16* __restrict__ hi, bf16* __restrict__ lo, int Rp,
                        i64 srcZ, i64 dstZ)
{
    __shared__ float t[32][33];
    const i64 z = blockIdx.z;
    src += z * srcZ; hi += z * dstZ; lo += z * dstZ;
    int c0 = blockIdx.x * 32;
    int r0 = blockIdx.y * 32;
    int tx = threadIdx.x, ty = threadIdx.y;
#pragma unroll
    for (int j = 0; j < 32; j += 8) {
        int r = r0 + ty + j;
        t[ty + j][tx] = (r < R) ? src[(size_t)r * ld + c0 + tx] : 0.f;
    }
    __syncthreads();
#pragma unroll
    for (int j = 0; j < 32; j += 8) {
        float fv = t[tx][ty + j];
        size_t o = (size_t)(c0 + ty + j) * Rp + r0 + tx;
        bf16 h = __float2bfloat16(fv);
        hi[o] = h;
        lo[o] = __float2bfloat16(fv - __bfloat162float(h));
    }
}

// ================= elementwise / reductions =================
__global__ void norm_heads_k(float* __restrict__ base,
                             const float* __restrict__ sc, const float* __restrict__ bi)
{
    int w = (blockIdx.x * blockDim.x + threadIdx.x) >> 5;
    int lane = threadIdx.x & 31;
    if (w >= NTOK * 16) return;
    int rowi = w >> 4, head = w & 15;
    float* p = base + (size_t)rowi * (3 * DIMM) + head * 64;
    float x0 = p[lane], x1 = p[lane + 32];
    float ss = x0 * x0 + x1 * x1;
#pragma unroll
    for (int o = 16; o; o >>= 1) ss += __shfl_xor_sync(0xffffffffu, ss, o);
    float inv = 1.f / (sqrtf(ss) + 1e-6f);
    p[lane]      = x0 * inv * sc[lane]      + bi[lane];
    p[lane + 32] = x1 * inv * sc[lane + 32] + bi[lane + 32];
}

__global__ void swish_pair_k(const float4* __restrict__ kg, const float4* __restrict__ kv,
                             float4* __restrict__ h, bf16* __restrict__ hhi,
                             bf16* __restrict__ hlo, int n4)
{
    int i = blockIdx.x * blockDim.x + threadIdx.x;
    if (i >= n4) return;
    float4 g = kg[i], u = kv[i], o;
    o.x = g.x / (1.f + __expf(-g.x)) * u.x;
    o.y = g.y / (1.f + __expf(-g.y)) * u.y;
    o.z = g.z / (1.f + __expf(-g.z)) * u.z;
    o.w = g.w / (1.f + __expf(-g.w)) * u.w;
    h[i] = o;
    float vv[4] = {o.x, o.y, o.z, o.w};
    __align__(8) bf16 hv[4];
    __align__(8) bf16 lv[4];
#pragma unroll
    for (int j = 0; j < 4; j++) {
        bf16 hb_ = __float2bfloat16(vv[j]);
        hv[j] = hb_;
        lv[j] = __float2bfloat16(vv[j] - __bfloat162float(hb_));
    }
    reinterpret_cast<uint2*>(hhi)[i] = *reinterpret_cast<const uint2*>(hv);
    reinterpret_cast<uint2*>(hlo)[i] = *reinterpret_cast<const uint2*>(lv);
}

__global__ void bw_ew_k(const float4* __restrict__ dh,
                        float4* __restrict__ kg_io, float4* __restrict__ kv_io, int n4)
{
    int i = blockIdx.x * blockDim.x + threadIdx.x;
    if (i >= n4) return;
    float4 d = dh[i], g = kg_io[i], u = kv_io[i], dg, du;
#define BW1(c) { float s = 1.f/(1.f+__expf(-g.c)); float sw = g.c*s; \
                 du.c = d.c*sw; dg.c = d.c*u.c*s*(1.f + g.c*(1.f-s)); }
    BW1(x) BW1(y) BW1(z) BW1(w)
#undef BW1
    kv_io[i] = du;
    kg_io[i] = dg;
}

__global__ void zero3_k(double* p) { if (threadIdx.x < 3) p[threadIdx.x] = 0.0; }

__global__ void sumsq3_k(const float* __restrict__ x, int n, double* __restrict__ out)
{
    __shared__ double sm[256];
    const int z = blockIdx.y;
    x += (size_t)z * n;
    double a = 0.0;
    for (int i = blockIdx.x * blockDim.x + threadIdx.x; i < n; i += gridDim.x * blockDim.x) {
        float fv = x[i];
        a += (double)fv * (double)fv;
    }
    sm[threadIdx.x] = a;
    __syncthreads();
    for (int s = 128; s; s >>= 1) {
        if (threadIdx.x < s) sm[threadIdx.x] += sm[threadIdx.x + s];
        __syncthreads();
    }
    if (threadIdx.x == 0) atomicAdd(&out[z], sm[0]);
}

__global__ void scale3_k(const float4* __restrict__ g, float4* __restrict__ X, int n4,
                         const double* __restrict__ nrm)
{
    const int z = blockIdx.y;
    int i = blockIdx.x * blockDim.x + threadIdx.x;
    if (i >= n4) return;
    float inv = (float)(1.0 / (sqrt(nrm[z]) + 1e-7));
    float4 fv = g[(size_t)z * n4 + i];
    fv.x *= inv; fv.y *= inv; fv.z *= inv; fv.w *= inv;
    X[(size_t)z * n4 + i] = fv;
}

__global__ void transpose_k(const float* __restrict__ src, float* __restrict__ dst,
                            int R, int C)
{
    __shared__ float t[32][33];
    int c0 = blockIdx.x * 32, r0 = blockIdx.y * 32;
    int x = c0 + threadIdx.x;
#pragma unroll
    for (int j = 0; j < 32; j += 8)
        t[threadIdx.y + j][threadIdx.x] = src[(size_t)(r0 + threadIdx.y + j) * C + x];
    __syncthreads();
    int x2 = r0 + threadIdx.x;
#pragma unroll
    for (int j = 0; j < 32; j += 8)
        dst[(size_t)(c0 + threadIdx.y + j) * R + x2] = t[threadIdx.x][threadIdx.y + j];
}

__global__ void upd_k(float4* __restrict__ p, const float4* __restrict__ x, int n4)
{
    int i = blockIdx.x * blockDim.x + threadIdx.x;
    if (i >= n4) return;
    float4 a = p[i], bb = x[i];
    a.x -= LRATE * bb.x; a.y -= LRATE * bb.y; a.z -= LRATE * bb.z; a.w -= LRATE * bb.w;
    p[i] = a;
}

// ================= host orchestration =================
struct BP { bf16 *hi, *lo; };

static void* symaddr(const void* s) { void* p = nullptr; cudaGetSymbolAddress(&p, s); return p; }

static void tc(BP A, BP B, int Kp, float* C, int ldc, int M, int N,
               float alpha, float beta, const float* E, int ldE,
               int nz = 1, i64 az = 0, i64 bz = 0, i64 cz = 0, i64 ez = 0,
               BP O = {nullptr, nullptr}, int ldo = 0, i64 oz = 0)
{
    dim3 gr(N / 128, (M + 127) / 128, nz);
    tc_gemm<<<gr, 256, TC_SMEM>>>(A.hi, A.lo, B.hi, B.lo, Kp, C, ldc, E, ldE,
                                  alpha, beta, M, az, bz, cz, ez, O.hi, O.lo, ldo, oz);
}

static void conv(const float* s, int ld, int R, int C, BP d, int Rp, int Cp,
                 int nz = 1, i64 sZ = 0, i64 dZ = 0)
{
    dim3 gr((Cp / 4 + 255) / 256, Rp, nz);
    conv_k<<<gr, 256>>>(s, ld, R, C, d.hi, d.lo, Cp, sZ, dZ);
}

static void convT(const float* s, int ld, int R, int C, BP d, int Rp,
                  int nz = 1, i64 sZ = 0, i64 dZ = 0)
{
    dim3 gr(C / 32, Rp / 32, nz);
    convT_k<<<gr, dim3(32, 8)>>>(s, ld, R, C, d.hi, d.lo, Rp, sZ, dZ);
}

extern "C" void kernel_launch(void* const* d_in, const int* in_sizes, int n_in,
                              void* d_out, int out_size)
{
    const float* x        = (const float*)d_in[0];
    const float* qkv_w    = (const float*)d_in[1];
    const float* qkv_b    = (const float*)d_in[2];
    const float* qn_s     = (const float*)d_in[3];
    const float* qn_b     = (const float*)d_in[4];
    const float* kn_s     = (const float*)d_in[5];
    const float* kn_b     = (const float*)d_in[6];
    const float* ttt_gate = (const float*)d_in[7];
    const float* ttt_val  = (const float*)d_in[8];
    const float* ttt_proj = (const float*)d_in[9];
    const float* proj_w   = (const float*)d_in[10];
    const float* proj_b   = (const float*)d_in[11];
    float* out = (float*)d_out;

    cudaFuncSetAttribute(tc_gemm, cudaFuncAttributeMaxDynamicSharedMemorySize, TC_SMEM);

    float* qkv  = (float*)symaddr(g_qkv);
    float* kgv  = (float*)symaddr(g_kgv);
    float* h    = (float*)symaddr(g_h);
    float* r    = (float*)symaddr(g_r);
    float* GV   = (float*)symaddr(g_GV);
    float* P    = (float*)symaddr(g_P);
    float* grad = (float*)symaddr(g_grad);
    float* X1   = (float*)symaddr(g_X1);
    float* X2   = (float*)symaddr(g_X2);
    float* Amat = (float*)symaddr(g_A);
    double* nrm = (double*)symaddr(g_nrm);
    unsigned char* pool = (unsigned char*)symaddr(g_bf);

    auto bp = [&](size_t off, size_t elems) { BP b; b.hi = (bf16*)(pool + off); b.lo = b.hi + elems; return b; };

    BP xb    = bp(O_X, E_TOKD);
    BP kb    = bp(O_K, E_TOKD);
    BP kTb   = bp(O_KT, E_TOKD);
    BP qb    = bp(O_Q, E_TOKD);
    BP rTb   = bp(O_RT, E_TOKD);
    BP hb    = bp(O_H, E_TOKH);
    BP hTb   = bp(O_HT, E_TOKH);
    BP dkgT  = bp(O_DKGT, E_TOKH);
    BP wGt   = bp(O_WGT, E_W);
    BP wP    = bp(O_WP,  E_W);
    BP wPt   = bp(O_WPT, E_W);
    BP qkvwT = bp(O_QKVW, E_QKVW);
    BP projwT = bp(O_PRJW, E_A);
    BP nsX   = bp(O_NSX,  E_W);
    BP nsXT  = bp(O_NSXT, E_W);
    BP nsA   = bp(O_NSA,  E_A);
    BP nsA2  = bp(O_NSA2, E_A);

    const size_t TB = sizeof(float) * E_W;
    cudaMemcpyAsync(GV,       ttt_gate, TB, cudaMemcpyDeviceToDevice, 0);
    cudaMemcpyAsync(GV + E_W, ttt_val,  TB, cudaMemcpyDeviceToDevice, 0);
    cudaMemcpyAsync(P,        ttt_proj, TB, cudaMemcpyDeviceToDevice, 0);

    // ---- qkv = x @ qkv_w + b ----
    conv (x, DIMM, NTOK, DIMM, xb, MP, DIMM);
    convT(qkv_w, 3 * DIMM, DIMM, 3 * DIMM, qkvwT, DIMM);
    tc(xb, qkvwT, DIMM, qkv, 3 * DIMM, NTOK, 3 * DIMM, 1.f, 1.f, qkv_b, 0);

    {
        int nb = (NTOK * 16 * 32 + 255) / 256;
        norm_heads_k<<<nb, 256>>>(qkv, qn_s, qn_b);
        norm_heads_k<<<nb, 256>>>(qkv + DIMM, kn_s, kn_b);
    }

    const float* kmat = qkv + DIMM;
    const float* vmat = qkv + 2 * DIMM;
    conv (kmat, 3 * DIMM, NTOK, DIMM, kb, MP, DIMM);
    convT(kmat, 3 * DIMM, NTOK, DIMM, kTb, MP);
    conv (qkv, 3 * DIMM, NTOK, DIMM, qb, MP, DIMM);

    const int NH4 = NTOK * HIDD / 4;
    const int nbH = (NH4 + 255) / 256;
    const i64 ZW = 2 * (i64)E_W;
    const i64 ZA = 2 * (i64)E_A;
    const i64 ZTH = 2 * (i64)E_TOKH;
    const i64 KGV = (i64)NTOK * HIDD;

    for (int step = 0; step < 2; ++step) {
        convT(GV, HIDD, DIMM, HIDD, wGt, DIMM, 2, (i64)E_W, ZW);
        conv (P, DIMM, HIDD, DIMM, wP, HIDD, DIMM);
        convT(P, DIMM, HIDD, DIMM, wPt, HIDD);

        tc(kb, wGt, DIMM, kgv, HIDD, NTOK, HIDD, 1.f, 0.f, nullptr, 0,
           2, 0, ZW, KGV, 0);
        swish_pair_k<<<nbH, 256>>>((const float4*)kgv, (const float4*)(kgv + KGV),
                                   (float4*)h, hb.hi, hb.lo, NH4);
        convT(h, HIDD, NTOK, HIDD, hTb, MP);
        tc(hb, wPt, HIDD, r, DIMM, NTOK, DIMM, 1.f, -1.f, vmat, 3 * DIMM,
           1, 0, 0, 0, 0, xb, DIMM, 0);
        convT(r, DIMM, NTOK, DIMM, rTb, MP);
        tc(rTb, hTb, MP, grad + 2 * E_W, HIDD, DIMM, HIDD, 1.f, 0.f, nullptr, 0);
        tc(xb, wP, DIMM, h, HIDD, NTOK, HIDD, 1.f, 0.f, nullptr, 0);
        bw_ew_k<<<nbH, 256>>>((const float4*)h, (float4*)kgv, (float4*)(kgv + KGV), NH4);
        convT(kgv, HIDD, NTOK, HIDD, dkgT, MP, 2, KGV, ZTH);
        tc(kTb, dkgT, MP, grad, HIDD, DIMM, HIDD, 1.f, 0.f, nullptr, 0,
           2, 0, ZTH, (i64)E_W, 0);

        // ---- batched Newton-Schulz over {gG, gV, gP^T} ----
        zero3_k<<<1, 4>>>(nrm);
        sumsq3_k<<<dim3(256, 3), 256>>>(grad, (int)E_W, nrm);
        scale3_k<<<dim3(((int)E_W / 4 + 255) / 256, 3), 256>>>(
            (const float4*)grad, (float4*)X1, (int)E_W / 4, nrm);
        float* X = X1;
        float* Y = X2;
        conv (X, HIDD, DIMM, HIDD, nsX, DIMM, HIDD, 3, (i64)E_W, ZW);
        convT(X, HIDD, DIMM, HIDD, nsXT, DIMM, 3, (i64)E_W, ZW);
        for (int it = 0; it < 5; ++it) {
            tc(nsX, nsX, HIDD, Amat, DIMM, DIMM, DIMM, 1.f, 0.f, nullptr, 0,
               3, ZW, ZW, (i64)E_A, 0, nsA, DIMM, ZA);
            tc(nsA, nsA, DIMM, nullptr, 0, DIMM, DIMM, NS_C, NS_B, Amat, DIMM,
               3, ZA, ZA, 0, (i64)E_A, nsA2, DIMM, ZA);
            tc(nsA2, nsXT, DIMM, Y, HIDD, DIMM, HIDD, 1.f, NS_A, X, HIDD,
               3, ZA, ZW, (i64)E_W, (i64)E_W, nsX, HIDD, ZW);
            if (it < 4)
                convT(Y, HIDD, DIMM, HIDD, nsXT, DIMM, 3, (i64)E_W, ZW);
            float* t = X; X = Y; Y = t;
        }
        upd_k<<<((int)(2 * E_W / 4) + 255) / 256, 256>>>((float4*)GV, (const float4*)X, (int)(2 * E_W / 4));
        {
            dim3 gr(HIDD / 32, DIMM / 32);
            transpose_k<<<gr, dim3(32, 8)>>>(X + 2 * E_W, Y, DIMM, HIDD);
            upd_k<<<((int)(E_W / 4) + 255) / 256, 256>>>((float4*)P, (const float4*)Y, (int)(E_W / 4));
        }
    }

    // ---- final forward with q ----
    convT(GV, HIDD, DIMM, HIDD, wGt, DIMM, 2, (i64)E_W, ZW);
    convT(P, DIMM, HIDD, DIMM, wPt, HIDD);
    tc(qb, wGt, DIMM, kgv, HIDD, NTOK, HIDD, 1.f, 0.f, nullptr, 0,
       2, 0, ZW, KGV, 0);
    swish_pair_k<<<nbH, 256>>>((const float4*)kgv, (const float4*)(kgv + KGV),
                               (float4*)h, hb.hi, hb.lo, NH4);
    tc(hb, wPt, HIDD, nullptr, 0, NTOK, DIMM, 1.f, 0.f, nullptr, 0,
       1, 0, 0, 0, 0, xb, DIMM, 0);
    convT(proj_w, DIMM, DIMM, DIMM, projwT, DIMM);
    tc(xb, projwT, DIMM, out, DIMM, NTOK, DIMM, 1.f, 1.f, proj_b, 0);
}

// round 8
// speedup vs baseline: 7.3024x; 1.2472x over previous
#include <cuda_runtime.h>
#include <cuda_bf16.h>
#include <cstdint>
#include <cstddef>

// ---------------- problem constants ----------------
#define NTOK 10992
#define MP   11008
#define DIMM 1024
#define HIDD 4096
#define LRATE 0.1f
#define NS_A 3.4445f
#define NS_B (-4.7750f)
#define NS_C 2.0315f

typedef unsigned long long u64;
typedef long long i64;
typedef __nv_bfloat16 bf16;

#if !defined(__CUDA_ARCH__) || defined(__CUDA_ARCH_FEAT_SM103_ALL)
#define TC_HAS_TCGEN05 1
#else
#define TC_HAS_TCGEN05 0
#endif

// ================= PTX helpers (sm_103a) =================
#if TC_HAS_TCGEN05
__device__ __forceinline__ uint32_t smem_u32(const void* p) {
    uint32_t a;
    asm("{ .reg .u64 t; cvta.to.shared.u64 t, %1; cvt.u32.u64 %0, t; }" : "=r"(a) : "l"(p));
    return a;
}
__device__ __forceinline__ uint32_t elect1() {
    uint32_t p;
    asm volatile("{\n.reg .pred p;\nelect.sync _|p, 0xFFFFFFFF;\nselp.b32 %0,1,0,p;\n}" : "=r"(p));
    return p;
}
#define MBARRIER_INIT(a, c) \
    asm volatile("mbarrier.init.shared.b64 [%0], %1;" :: "r"((uint32_t)(a)), "r"((uint32_t)(c)) : "memory")
#define MBARRIER_WAIT_PARITY(a, ph) do { \
    uint32_t _m = (uint32_t)(a); uint32_t _p = (uint32_t)(ph); uint32_t _d; \
    asm volatile("{\n.reg .pred p;\nmbarrier.try_wait.parity.acquire.cta.shared::cta.b64 p, [%1], %2;\nselp.b32 %0,1,0,p;\n}" \
        : "=r"(_d) : "r"(_m), "r"(_p) : "memory"); \
    if (!_d) { \
        asm volatile("{\n.reg .pred P1;\nWL_%=:\nmbarrier.try_wait.parity.acquire.cta.shared::cta.b64 P1, [%0], %1, 0x989680;\n@P1 bra.uni WD_%=;\nbra.uni WL_%=;\nWD_%=:\n}" \
            :: "r"(_m), "r"(_p) : "memory"); \
    } } while (0)
#define TCGEN05_ALLOC(sa, n) \
    asm volatile("tcgen05.alloc.cta_group::1.sync.aligned.shared::cta.b32 [%0], %1;" \
        :: "r"((uint32_t)(sa)), "r"((uint32_t)(n)) : "memory")
#define TCGEN05_RELINQ() \
    asm volatile("tcgen05.relinquish_alloc_permit.cta_group::1.sync.aligned;")
#define TCGEN05_DEALLOC(t, n) \
    asm volatile("tcgen05.dealloc.cta_group::1.sync.aligned.b32 %0, %1;" :: "r"(t), "r"((uint32_t)(n)))
#define TCGEN05_COMMIT(a) \
    asm volatile("tcgen05.commit.cta_group::1.mbarrier::arrive::one.shared::cluster.b64 [%0];" \
        :: "r"((uint32_t)(a)) : "memory")
#define TCGEN05_FENCE_AFTER() asm volatile("tcgen05.fence::after_thread_sync;" ::: "memory")
#define TCGEN05_WAIT_LD() asm volatile("tcgen05.wait::ld.sync.aligned;" ::: "memory")
#define FENCE_ASYNC() asm volatile("fence.proxy.async.shared::cta;" ::: "memory")
#define STS128(r0, r1, r2, r3, a) \
    asm volatile("st.shared.v4.b32 [%0], {%1,%2,%3,%4};" :: "r"(a), "r"(r0), "r"(r1), "r"(r2), "r"(r3) : "memory")
#define TCGEN05_LD_X32(r, ta) \
    asm volatile("tcgen05.ld.sync.aligned.32x32b.x32.b32 " \
        "{%0,%1,%2,%3,%4,%5,%6,%7,%8,%9,%10,%11,%12,%13,%14,%15," \
        "%16,%17,%18,%19,%20,%21,%22,%23,%24,%25,%26,%27,%28,%29,%30,%31}, [%32];" \
        : "=r"((r)[0]), "=r"((r)[1]), "=r"((r)[2]), "=r"((r)[3]), "=r"((r)[4]), "=r"((r)[5]), \
          "=r"((r)[6]), "=r"((r)[7]), "=r"((r)[8]), "=r"((r)[9]), "=r"((r)[10]), "=r"((r)[11]), \
          "=r"((r)[12]), "=r"((r)[13]), "=r"((r)[14]), "=r"((r)[15]), "=r"((r)[16]), "=r"((r)[17]), \
          "=r"((r)[18]), "=r"((r)[19]), "=r"((r)[20]), "=r"((r)[21]), "=r"((r)[22]), "=r"((r)[23]), \
          "=r"((r)[24]), "=r"((r)[25]), "=r"((r)[26]), "=r"((r)[27]), "=r"((r)[28]), "=r"((r)[29]), \
          "=r"((r)[30]), "=r"((r)[31]) : "r"(ta))

static constexpr u64 SMEM_DESC_BASE =
    (u64(2) << 61) | (u64(1) << 46) | (u64(64) << 32) | (u64(1) << 16);
__device__ __forceinline__ u64 mkdesc(uint32_t sa) {
    return SMEM_DESC_BASE | ((u64)(sa >> 4) & 0x3FFF);
}
__device__ __forceinline__ void mma_f16_ss(uint32_t d, u64 ad, u64 bd, uint32_t idesc, bool acc) {
    uint32_t en = acc ? 1u : 0u;
    asm volatile(
        "{\n\t.reg .pred p;\n\tsetp.ne.u32 p, %4, 0;\n\t"
        "tcgen05.mma.cta_group::1.kind::f16 [%0], %1, %2, %3, {%5,%5,%5,%5}, p;\n\t}"
        :: "r"(d), "l"(ad), "l"(bd), "r"(idesc), "r"(en), "r"(0u) : "memory");
}
#endif

#define SWZ(b) ((b) ^ (((b) >> 3) & 0x70))
#define TCIDESC 0x08200490u   // dtype=F32, a=BF16, b=BF16, N=128, M=128

// ---------------- fp32 scratch ----------------
static constexpr size_t E_TOKD = (size_t)MP * DIMM;
static constexpr size_t E_TOKH = (size_t)MP * HIDD;
static constexpr size_t E_W    = (size_t)DIMM * HIDD;
static constexpr size_t E_A    = (size_t)DIMM * DIMM;
static constexpr size_t E_QKVW = (size_t)DIMM * 3 * DIMM;

__device__ float g_qkv [(size_t)NTOK * 3 * DIMM];
__device__ float g_kgv [(size_t)2 * NTOK * HIDD];
__device__ float g_h   [(size_t)NTOK * HIDD];
__device__ float g_r   [(size_t)NTOK * DIMM];
__device__ float g_GV  [2 * E_W];
__device__ float g_P   [E_W];
__device__ float g_grad[3 * E_W];
__device__ float g_X1  [3 * E_W];
__device__ float g_X2  [3 * E_W];
__device__ float g_A   [3 * E_A];
__device__ double g_nrm[3];

// ---------------- bf16 hi/lo pool ----------------
static constexpr size_t O_X    = 0;
static constexpr size_t O_K    = O_X    + E_TOKD * 4;
static constexpr size_t O_KT   = O_K    + E_TOKD * 4;
static constexpr size_t O_Q    = O_KT   + E_TOKD * 4;
static constexpr size_t O_RT   = O_Q    + E_TOKD * 4;
static constexpr size_t O_H    = O_RT   + E_TOKD * 4;
static constexpr size_t O_HT   = O_H    + E_TOKH * 4;
static constexpr size_t O_DKGT = O_HT   + E_TOKH * 4;
static constexpr size_t O_DKVT = O_DKGT + E_TOKH * 4;
static constexpr size_t O_WGT  = O_DKVT + E_TOKH * 4;
static constexpr size_t O_WVT  = O_WGT  + E_W * 4;
static constexpr size_t O_WP   = O_WVT  + E_W * 4;
static constexpr size_t O_WPT  = O_WP   + E_W * 4;
static constexpr size_t O_QKVW = O_WPT  + E_W * 4;
static constexpr size_t O_PRJW = O_QKVW + E_QKVW * 4;
static constexpr size_t O_NSX  = O_PRJW + E_A * 4;
static constexpr size_t O_NSXT = O_NSX  + 3 * E_W * 4;
static constexpr size_t O_NSA  = O_NSXT + 3 * E_W * 4;
static constexpr size_t O_NSA2 = O_NSA  + 3 * E_A * 4;
static constexpr size_t POOL_B = O_NSA2 + 3 * E_A * 4;
__device__ __align__(1024) unsigned char g_bf[POOL_B];

// ============ tcgen05 split-bf16 GEMM: 128x256 tile, cg1, double-buffered ======
// Stage layout (96KB): Ahi 16K | Alo 16K | Bhi 32K (256 rows) | Blo 32K
#define TC_STAGE 98304
#define TC_SMEM  (2 * TC_STAGE + 1024)

__global__ void __launch_bounds__(256, 1) tc_gemm(
    const bf16* __restrict__ Ahi, const bf16* __restrict__ Alo,
    const bf16* __restrict__ Bhi, const bf16* __restrict__ Blo,
    int Kp, float* __restrict__ C, int ldc,
    const float* __restrict__ E, int ldE,
    float alpha, float beta, int M,
    i64 az, i64 bz, i64 cz, i64 ez,
    bf16* __restrict__ Ohi, bf16* __restrict__ Olo, int ldo, i64 oz)
{
#if TC_HAS_TCGEN05
    extern __shared__ unsigned char dsm_raw[];
    __shared__ __align__(8) u64 s_mb[2];
    __shared__ uint32_t s_tmem[1];

    const int tid = threadIdx.x;
    const int wid = tid >> 5;
    const int lane = tid & 31;
    const i64 zz = blockIdx.z;
    Ahi += zz * az; Alo += zz * az;
    Bhi += zz * bz; Blo += zz * bz;
    if (C)   C   += zz * cz;
    if (E)   E   += zz * ez;
    if (Ohi) { Ohi += zz * oz; Olo += zz * oz; }

    const uint32_t sb  = (smem_u32(dsm_raw) + 1023) & ~1023u;
    const uint32_t mbB = smem_u32(&s_mb[0]);

    if (tid == 0) { MBARRIER_INIT(mbB, 1); MBARRIER_INIT(mbB + 8, 1); }
    if (wid == 0) {
        TCGEN05_ALLOC(smem_u32(s_tmem), 256);
        TCGEN05_RELINQ();
    }
    __syncthreads();
    const uint32_t tmem = s_tmem[0];

    const int m0 = blockIdx.y * 128;
    const int n0 = blockIdx.x * 256;

    // coalesced staging: thread handles rows r0+32k, byte-col (tid&7)*16
    const int r0    = tid >> 3;
    const int col16 = (tid & 7) * 16;
    const size_t rowB = (size_t)Kp * 2;
    const char* pAhi = (const char*)Ahi + (size_t)(m0 + r0) * rowB + col16;
    const char* pAlo = (const char*)Alo + (size_t)(m0 + r0) * rowB + col16;
    const char* pBhi = (const char*)Bhi + (size_t)(n0 + r0) * rowB + col16;
    const char* pBlo = (const char*)Blo + (size_t)(n0 + r0) * rowB + col16;
    uint32_t swA[4], swB[8];
#pragma unroll
    for (int k = 0; k < 4; ++k) swA[k] = SWZ((uint32_t)(r0 + 32 * k) * 128 + col16);
#pragma unroll
    for (int k = 0; k < 8; ++k) swB[k] = SWZ((uint32_t)(r0 + 32 * k) * 128 + col16);

    uint4 va[8], vb[16];
#define TCFETCH(cc) do { const size_t gb_ = (size_t)(cc) * 128;                         \
    _Pragma("unroll") for (int k_ = 0; k_ < 4; ++k_) {                                  \
        va[k_]     = *reinterpret_cast<const uint4*>(pAhi + (size_t)(32 * k_) * rowB + gb_); \
        va[4 + k_] = *reinterpret_cast<const uint4*>(pAlo + (size_t)(32 * k_) * rowB + gb_); \
    }                                                                                   \
    _Pragma("unroll") for (int k_ = 0; k_ < 8; ++k_) {                                  \
        vb[k_]     = *reinterpret_cast<const uint4*>(pBhi + (size_t)(32 * k_) * rowB + gb_); \
        vb[8 + k_] = *reinterpret_cast<const uint4*>(pBlo + (size_t)(32 * k_) * rowB + gb_); \
    } } while (0)

    const int NC = Kp >> 6;
    TCFETCH(0);
    for (int c = 0; c < NC; ++c) {
        const int s = c & 1;
        const int phase = c >> 1;
        const uint32_t mbs = mbB + (uint32_t)s * 8;
        const uint32_t stg = sb + (uint32_t)s * TC_STAGE;
        if (c >= 2) { MBARRIER_WAIT_PARITY(mbs, (phase - 1) & 1); }
#pragma unroll
        for (int k = 0; k < 4; ++k) {
            STS128(va[k].x, va[k].y, va[k].z, va[k].w, stg + swA[k]);
            STS128(va[4 + k].x, va[4 + k].y, va[4 + k].z, va[4 + k].w, stg + 16384u + swA[k]);
        }
#pragma unroll
        for (int k = 0; k < 8; ++k) {
            STS128(vb[k].x, vb[k].y, vb[k].z, vb[k].w, stg + 32768u + swB[k]);
            STS128(vb[8 + k].x, vb[8 + k].y, vb[8 + k].z, vb[8 + k].w, stg + 65536u + swB[k]);
        }
        if (c + 1 < NC) { TCFETCH(c + 1); }   // LDGs overlap sync + MMA below
        FENCE_ASYNC();
        __syncthreads();
        if (wid == 0 && elect1()) {
            u64 aH = mkdesc(stg);
            u64 aL = mkdesc(stg + 16384);
#pragma unroll
            for (int nh = 0; nh < 2; ++nh) {
                const uint32_t d = tmem + (uint32_t)nh * 128;
                u64 bH = mkdesc(stg + 32768 + (uint32_t)nh * 16384);
                u64 bL = mkdesc(stg + 65536 + (uint32_t)nh * 16384);
#pragma unroll
                for (int ks = 0; ks < 4; ++ks)
                    mma_f16_ss(d, aH + ks * 2, bH + ks * 2, TCIDESC, !(c == 0 && ks == 0));
#pragma unroll
                for (int ks = 0; ks < 4; ++ks)
                    mma_f16_ss(d, aH + ks * 2, bL + ks * 2, TCIDESC, true);
#pragma unroll
                for (int ks = 0; ks < 4; ++ks)
                    mma_f16_ss(d, aL + ks * 2, bH + ks * 2, TCIDESC, true);
            }
            TCGEN05_COMMIT(mbs);
        }
    }
    {
        const int cl = NC - 1;
        MBARRIER_WAIT_PARITY(mbB + (uint32_t)(cl & 1) * 8, (cl >> 1) & 1);
    }
    TCGEN05_FENCE_AFTER();

    // epilogue: 8 warps = 4 row-subsets x 2 col-halves; 4x LD_X32 each (256 cols)
    const int sub = wid & 3;
    const int colh = (wid >> 2) * 128;
    const int m = m0 + sub * 32 + lane;
#pragma unroll
    for (int qq = 0; qq < 4; ++qq) {
        uint32_t r32[32];
        TCGEN05_LD_X32(r32, tmem + colh + qq * 32);
        TCGEN05_WAIT_LD();
        if (m < M) {
            const int ncol = n0 + colh + qq * 32;
            float o[32];
            if (beta != 0.f) {
                const float* erow = E + (size_t)m * ldE + ncol;
#pragma unroll
                for (int j = 0; j < 32; j += 4) {
                    float4 e = *reinterpret_cast<const float4*>(erow + j);
                    o[j]     = alpha * __uint_as_float(r32[j])     + beta * e.x;
                    o[j + 1] = alpha * __uint_as_float(r32[j + 1]) + beta * e.y;
                    o[j + 2] = alpha * __uint_as_float(r32[j + 2]) + beta * e.z;
                    o[j + 3] = alpha * __uint_as_float(r32[j + 3]) + beta * e.w;
                }
            } else {
#pragma unroll
                for (int j = 0; j < 32; ++j) o[j] = alpha * __uint_as_float(r32[j]);
            }
            if (C) {
                float* crow = C + (size_t)m * ldc + ncol;
#pragma unroll
                for (int j = 0; j < 32; j += 4)
                    *reinterpret_cast<float4*>(crow + j) = make_float4(o[j], o[j+1], o[j+2], o[j+3]);
            }
            if (Ohi) {
                bf16* hrow = Ohi + (size_t)m * ldo + ncol;
                bf16* lrow = Olo + (size_t)m * ldo + ncol;
#pragma unroll
                for (int j = 0; j < 32; j += 4) {
                    __align__(8) bf16 hv[4];
                    __align__(8) bf16 lv[4];
#pragma unroll
                    for (int t = 0; t < 4; ++t) {
                        bf16 hb_ = __float2bfloat16(o[j + t]);
                        hv[t] = hb_;
                        lv[t] = __float2bfloat16(o[j + t] - __bfloat162float(hb_));
                    }
                    *reinterpret_cast<uint2*>(hrow + j) = *reinterpret_cast<const uint2*>(hv);
                    *reinterpret_cast<uint2*>(lrow + j) = *reinterpret_cast<const uint2*>(lv);
                }
            }
        }
    }
    __syncthreads();
    if (wid == 0) TCGEN05_DEALLOC(tmem, 256);
#undef TCFETCH
#endif
}

// ================= conversion kernels (z-batched) =================
__global__ void conv_k(const float* __restrict__ src, int ld, int R, int C,
                       bf16* __restrict__ hi, bf16* __restrict__ lo, int Cp,
                       i64 srcZ, i64 dstZ)
{
    const i64 z = blockIdx.z;
    src += z * srcZ; hi += z * dstZ; lo += z * dstZ;
    int c = (blockIdx.x * blockDim.x + threadIdx.x) * 4;
    int r = blockIdx.y;
    if (c >= Cp) return;
    __align__(8) bf16 h4[4];
    __align__(8) bf16 l4[4];
    if (r < R && c < C) {
        float4 fv = *reinterpret_cast<const float4*>(src + (size_t)r * ld + c);
        float vv[4] = {fv.x, fv.y, fv.z, fv.w};
#pragma unroll
        for (int j = 0; j < 4; j++) {
            bf16 h = __float2bfloat16(vv[j]);
            h4[j] = h;
            l4[j] = __float2bfloat16(vv[j] - __bfloat162float(h));
        }
    } else {
#pragma unroll
        for (int j = 0; j < 4; j++) { h4[j] = __float2bfloat16(0.f); l4[j] = h4[j]; }
    }
    size_t o = (size_t)r * Cp + c;
    *reinterpret_cast<uint2*>(hi + o) = *reinterpret_cast<const uint2*>(h4);
    *reinterpret_cast<uint2*>(lo + o) = *reinterpret_cast<const uint2*>(l4);
}

__global__ void convT_k(const float* __restrict__ src, int ld, int R, int C,
                        bf16* __restrict__ hi, bf16* __restrict__ lo, int Rp,
                        i64 srcZ, i64 dstZ)
{
    __shared__ float t[32][33];
    const i64 z = blockIdx.z;
    src += z * srcZ; hi += z * dstZ; lo += z * dstZ;
    int c0 = blockIdx.x * 32;
    int r0 = blockIdx.y * 32;
    int tx = threadIdx.x, ty = threadIdx.y;
#pragma unroll
    for (int j = 0; j < 32; j += 8) {
        int r = r0 + ty + j;
        t[ty + j][tx] = (r < R) ? src[(size_t)r * ld + c0 + tx] : 0.f;
    }
    __syncthreads();
#pragma unroll
    for (int j = 0; j < 32; j += 8) {
        float fv = t[tx][ty + j];
        size_t o = (size_t)(c0 + ty + j) * Rp + r0 + tx;
        bf16 h = __float2bfloat16(fv);
        hi[o] = h;
        lo[o] = __float2bfloat16(fv - __bfloat162float(h));
    }
}

// ================= elementwise / reductions =================
__global__ void norm_heads_k(float* __restrict__ base,
                             const float* __restrict__ sc, const float* __restrict__ bi)
{
    int w = (blockIdx.x * blockDim.x + threadIdx.x) >> 5;
    int lane = threadIdx.x & 31;
    if (w >= NTOK * 16) return;
    int rowi = w >> 4, head = w & 15;
    float* p = base + (size_t)rowi * (3 * DIMM) + head * 64;
    float x0 = p[lane], x1 = p[lane + 32];
    float ss = x0 * x0 + x1 * x1;
#pragma unroll
    for (int o = 16; o; o >>= 1) ss += __shfl_xor_sync(0xffffffffu, ss, o);
    float inv = 1.f / (sqrtf(ss) + 1e-6f);
    p[lane]      = x0 * inv * sc[lane]      + bi[lane];
    p[lane + 32] = x1 * inv * sc[lane + 32] + bi[lane + 32];
}

__global__ void swish_pair_k(const float4* __restrict__ kg, const float4* __restrict__ kv,
                             float4* __restrict__ h, bf16* __restrict__ hhi,
                             bf16* __restrict__ hlo, int n4)
{
    int i = blockIdx.x * blockDim.x + threadIdx.x;
    if (i >= n4) return;
    float4 g = kg[i], u = kv[i], o;
    o.x = g.x / (1.f + __expf(-g.x)) * u.x;
    o.y = g.y / (1.f + __expf(-g.y)) * u.y;
    o.z = g.z / (1.f + __expf(-g.z)) * u.z;
    o.w = g.w / (1.f + __expf(-g.w)) * u.w;
    h[i] = o;
    float vv[4] = {o.x, o.y, o.z, o.w};
    __align__(8) bf16 hv[4];
    __align__(8) bf16 lv[4];
#pragma unroll
    for (int j = 0; j < 4; j++) {
        bf16 hb_ = __float2bfloat16(vv[j]);
        hv[j] = hb_;
        lv[j] = __float2bfloat16(vv[j] - __bfloat162float(hb_));
    }
    reinterpret_cast<uint2*>(hhi)[i] = *reinterpret_cast<const uint2*>(hv);
    reinterpret_cast<uint2*>(hlo)[i] = *reinterpret_cast<const uint2*>(lv);
}

__global__ void bw_ew_k(const float4* __restrict__ dh,
                        float4* __restrict__ kg_io, float4* __restrict__ kv_io, int n4)
{
    int i = blockIdx.x * blockDim.x + threadIdx.x;
    if (i >= n4) return;
    float4 d = dh[i], g = kg_io[i], u = kv_io[i], dg, du;
#define BW1(c) { float s = 1.f/(1.f+__expf(-g.c)); float sw = g.c*s; \
                 du.c = d.c*sw; dg.c = d.c*u.c*s*(1.f + g.c*(1.f-s)); }
    BW1(x) BW1(y) BW1(z) BW1(w)
#undef BW1
    kv_io[i] = du;
    kg_io[i] = dg;
}

__global__ void zero3_k(double* p) { if (threadIdx.x < 3) p[threadIdx.x] = 0.0; }

__global__ void sumsq3_k(const float* __restrict__ x, int n, double* __restrict__ out)
{
    __shared__ double sm[256];
    const int z = blockIdx.y;
    x += (size_t)z * n;
    double a = 0.0;
    for (int i = blockIdx.x * blockDim.x + threadIdx.x; i < n; i += gridDim.x * blockDim.x) {
        float fv = x[i];
        a += (double)fv * (double)fv;
    }
    sm[threadIdx.x] = a;
    __syncthreads();
    for (int s = 128; s; s >>= 1) {
        if (threadIdx.x < s) sm[threadIdx.x] += sm[threadIdx.x + s];
        __syncthreads();
    }
    if (threadIdx.x == 0) atomicAdd(&out[z], sm[0]);
}

__global__ void scale3_k(const float4* __restrict__ g, float4* __restrict__ X, int n4,
                         const double* __restrict__ nrm)
{
    const int z = blockIdx.y;
    int i = blockIdx.x * blockDim.x + threadIdx.x;
    if (i >= n4) return;
    float inv = (float)(1.0 / (sqrt(nrm[z]) + 1e-7));
    float4 fv = g[(size_t)z * n4 + i];
    fv.x *= inv; fv.y *= inv; fv.z *= inv; fv.w *= inv;
    X[(size_t)z * n4 + i] = fv;
}

__global__ void transpose_k(const float* __restrict__ src, float* __restrict__ dst,
                            int R, int C)
{
    __shared__ float t[32][33];
    int c0 = blockIdx.x * 32, r0 = blockIdx.y * 32;
    int x = c0 + threadIdx.x;
#pragma unroll
    for (int j = 0; j < 32; j += 8)
        t[threadIdx.y + j][threadIdx.x] = src[(size_t)(r0 + threadIdx.y + j) * C + x];
    __syncthreads();
    int x2 = r0 + threadIdx.x;
#pragma unroll
    for (int j = 0; j < 32; j += 8)
        dst[(size_t)(c0 + threadIdx.y + j) * R + x2] = t[threadIdx.x][threadIdx.y + j];
}

__global__ void upd_k(float4* __restrict__ p, const float4* __restrict__ x, int n4)
{
    int i = blockIdx.x * blockDim.x + threadIdx.x;
    if (i >= n4) return;
    float4 a = p[i], bb = x[i];
    a.x -= LRATE * bb.x; a.y -= LRATE * bb.y; a.z -= LRATE * bb.z; a.w -= LRATE * bb.w;
    p[i] = a;
}

// ================= host orchestration =================
struct BP { bf16 *hi, *lo; };

static void* symaddr(const void* s) { void* p = nullptr; cudaGetSymbolAddress(&p, s); return p; }

static void tc(BP A, BP B, int Kp, float* C, int ldc, int M, int N,
               float alpha, float beta, const float* E, int ldE,
               int nz = 1, i64 az = 0, i64 bz = 0, i64 cz = 0, i64 ez = 0,
               BP O = {nullptr, nullptr}, int ldo = 0, i64 oz = 0)
{
    dim3 gr(N / 256, (M + 127) / 128, nz);
    tc_gemm<<<gr, 256, TC_SMEM>>>(A.hi, A.lo, B.hi, B.lo, Kp, C, ldc, E, ldE,
                                  alpha, beta, M, az, bz, cz, ez, O.hi, O.lo, ldo, oz);
}

static void conv(const float* s, int ld, int R, int C, BP d, int Rp, int Cp,
                 int nz = 1, i64 sZ = 0, i64 dZ = 0)
{
    dim3 gr((Cp / 4 + 255) / 256, Rp, nz);
    conv_k<<<gr, 256>>>(s, ld, R, C, d.hi, d.lo, Cp, sZ, dZ);
}

static void convT(const float* s, int ld, int R, int C, BP d, int Rp,
                  int nz = 1, i64 sZ = 0, i64 dZ = 0)
{
    dim3 gr(C / 32, Rp / 32, nz);
    convT_k<<<gr, dim3(32, 8)>>>(s, ld, R, C, d.hi, d.lo, Rp, sZ, dZ);
}

extern "C" void kernel_launch(void* const* d_in, const int* in_sizes, int n_in,
                              void* d_out, int out_size)
{
    const float* x        = (const float*)d_in[0];
    const float* qkv_w    = (const float*)d_in[1];
    const float* qkv_b    = (const float*)d_in[2];
    const float* qn_s     = (const float*)d_in[3];
    const float* qn_b     = (const float*)d_in[4];
    const float* kn_s     = (const float*)d_in[5];
    const float* kn_b     = (const float*)d_in[6];
    const float* ttt_gate = (const float*)d_in[7];
    const float* ttt_val  = (const float*)d_in[8];
    const float* ttt_proj = (const float*)d_in[9];
    const float* proj_w   = (const float*)d_in[10];
    const float* proj_b   = (const float*)d_in[11];
    float* out = (float*)d_out;

    cudaFuncSetAttribute(tc_gemm, cudaFuncAttributeMaxDynamicSharedMemorySize, TC_SMEM);

    float* qkv  = (float*)symaddr(g_qkv);
    float* kgv  = (float*)symaddr(g_kgv);
    float* h    = (float*)symaddr(g_h);
    float* r    = (float*)symaddr(g_r);
    float* GV   = (float*)symaddr(g_GV);
    float* P    = (float*)symaddr(g_P);
    float* grad = (float*)symaddr(g_grad);
    float* X1   = (float*)symaddr(g_X1);
    float* X2   = (float*)symaddr(g_X2);
    float* Amat = (float*)symaddr(g_A);
    double* nrm = (double*)symaddr(g_nrm);
    unsigned char* pool = (unsigned char*)symaddr(g_bf);

    auto bp = [&](size_t off, size_t elems) { BP b; b.hi = (bf16*)(pool + off); b.lo = b.hi + elems; return b; };

    BP xb    = bp(O_X, E_TOKD);
    BP kb    = bp(O_K, E_TOKD);
    BP kTb   = bp(O_KT, E_TOKD);
    BP qb    = bp(O_Q, E_TOKD);
    BP rTb   = bp(O_RT, E_TOKD);
    BP hb    = bp(O_H, E_TOKH);
    BP hTb   = bp(O_HT, E_TOKH);
    BP dkgT  = bp(O_DKGT, E_TOKH);
    BP wGt   = bp(O_WGT, E_W);
    BP wP    = bp(O_WP,  E_W);
    BP wPt   = bp(O_WPT, E_W);
    BP qkvwT = bp(O_QKVW, E_QKVW);
    BP projwT = bp(O_PRJW, E_A);
    BP nsX   = bp(O_NSX,  E_W);
    BP nsXT  = bp(O_NSXT, E_W);
    BP nsA   = bp(O_NSA,  E_A);
    BP nsA2  = bp(O_NSA2, E_A);

    const size_t TB = sizeof(float) * E_W;
    cudaMemcpyAsync(GV,       ttt_gate, TB, cudaMemcpyDeviceToDevice, 0);
    cudaMemcpyAsync(GV + E_W, ttt_val,  TB, cudaMemcpyDeviceToDevice, 0);
    cudaMemcpyAsync(P,        ttt_proj, TB, cudaMemcpyDeviceToDevice, 0);

    // ---- qkv = x @ qkv_w + b ----
    conv (x, DIMM, NTOK, DIMM, xb, MP, DIMM);
    convT(qkv_w, 3 * DIMM, DIMM, 3 * DIMM, qkvwT, DIMM);
    tc(xb, qkvwT, DIMM, qkv, 3 * DIMM, NTOK, 3 * DIMM, 1.f, 1.f, qkv_b, 0);

    {
        int nb = (NTOK * 16 * 32 + 255) / 256;
        norm_heads_k<<<nb, 256>>>(qkv, qn_s, qn_b);
        norm_heads_k<<<nb, 256>>>(qkv + DIMM, kn_s, kn_b);
    }

    const float* kmat = qkv + DIMM;
    const float* vmat = qkv + 2 * DIMM;
    conv (kmat, 3 * DIMM, NTOK, DIMM, kb, MP, DIMM);
    convT(kmat, 3 * DIMM, NTOK, DIMM, kTb, MP);
    conv (qkv, 3 * DIMM, NTOK, DIMM, qb, MP, DIMM);

    const int NH4 = NTOK * HIDD / 4;
    const int nbH = (NH4 + 255) / 256;
    const i64 ZW = 2 * (i64)E_W;
    const i64 ZA = 2 * (i64)E_A;
    const i64 ZTH = 2 * (i64)E_TOKH;
    const i64 KGV = (i64)NTOK * HIDD;

    for (int step = 0; step < 2; ++step) {
        convT(GV, HIDD, DIMM, HIDD, wGt, DIMM, 2, (i64)E_W, ZW);
        conv (P, DIMM, HIDD, DIMM, wP, HIDD, DIMM);
        convT(P, DIMM, HIDD, DIMM, wPt, HIDD);

        tc(kb, wGt, DIMM, kgv, HIDD, NTOK, HIDD, 1.f, 0.f, nullptr, 0,
           2, 0, ZW, KGV, 0);
        swish_pair_k<<<nbH, 256>>>((const float4*)kgv, (const float4*)(kgv + KGV),
                                   (float4*)h, hb.hi, hb.lo, NH4);
        convT(h, HIDD, NTOK, HIDD, hTb, MP);
        tc(hb, wPt, HIDD, r, DIMM, NTOK, DIMM, 1.f, -1.f, vmat, 3 * DIMM,
           1, 0, 0, 0, 0, xb, DIMM, 0);
        convT(r, DIMM, NTOK, DIMM, rTb, MP);
        tc(rTb, hTb, MP, grad + 2 * E_W, HIDD, DIMM, HIDD, 1.f, 0.f, nullptr, 0);
        tc(xb, wP, DIMM, h, HIDD, NTOK, HIDD, 1.f, 0.f, nullptr, 0);
        bw_ew_k<<<nbH, 256>>>((const float4*)h, (float4*)kgv, (float4*)(kgv + KGV), NH4);
        convT(kgv, HIDD, NTOK, HIDD, dkgT, MP, 2, KGV, ZTH);
        tc(kTb, dkgT, MP, grad, HIDD, DIMM, HIDD, 1.f, 0.f, nullptr, 0,
           2, 0, ZTH, (i64)E_W, 0);

        // ---- batched Newton-Schulz over {gG, gV, gP^T} ----
        zero3_k<<<1, 4>>>(nrm);
        sumsq3_k<<<dim3(256, 3), 256>>>(grad, (int)E_W, nrm);
        scale3_k<<<dim3(((int)E_W / 4 + 255) / 256, 3), 256>>>(
            (const float4*)grad, (float4*)X1, (int)E_W / 4, nrm);
        float* X = X1;
        float* Y = X2;
        conv (X, HIDD, DIMM, HIDD, nsX, DIMM, HIDD, 3, (i64)E_W, ZW);
        convT(X, HIDD, DIMM, HIDD, nsXT, DIMM, 3, (i64)E_W, ZW);
        for (int it = 0; it < 5; ++it) {
            tc(nsX, nsX, HIDD, Amat, DIMM, DIMM, DIMM, 1.f, 0.f, nullptr, 0,
               3, ZW, ZW, (i64)E_A, 0, nsA, DIMM, ZA);
            tc(nsA, nsA, DIMM, nullptr, 0, DIMM, DIMM, NS_C, NS_B, Amat, DIMM,
               3, ZA, ZA, 0, (i64)E_A, nsA2, DIMM, ZA);
            tc(nsA2, nsXT, DIMM, Y, HIDD, DIMM, HIDD, 1.f, NS_A, X, HIDD,
               3, ZA, ZW, (i64)E_W, (i64)E_W, nsX, HIDD, ZW);
            if (it < 4)
                convT(Y, HIDD, DIMM, HIDD, nsXT, DIMM, 3, (i64)E_W, ZW);
            float* t = X; X = Y; Y = t;
        }
        upd_k<<<((int)(2 * E_W / 4) + 255) / 256, 256>>>((float4*)GV, (const float4*)X, (int)(2 * E_W / 4));
        {
            dim3 gr(HIDD / 32, DIMM / 32);
            transpose_k<<<gr, dim3(32, 8)>>>(X + 2 * E_W, Y, DIMM, HIDD);
            upd_k<<<((int)(E_W / 4) + 255) / 256, 256>>>((float4*)P, (const float4*)Y, (int)(E_W / 4));
        }
    }

    // ---- final forward with q ----
    convT(GV, HIDD, DIMM, HIDD, wGt, DIMM, 2, (i64)E_W, ZW);
    convT(P, DIMM, HIDD, DIMM, wPt, HIDD);
    tc(qb, wGt, DIMM, kgv, HIDD, NTOK, HIDD, 1.f, 0.f, nullptr, 0,
       2, 0, ZW, KGV, 0);
    swish_pair_k<<<nbH, 256>>>((const float4*)kgv, (const float4*)(kgv + KGV),
                               (float4*)h, hb.hi, hb.lo, NH4);
    tc(hb, wPt, HIDD, nullptr, 0, NTOK, DIMM, 1.f, 0.f, nullptr, 0,
       1, 0, 0, 0, 0, xb, DIMM, 0);
    convT(proj_w, DIMM, DIMM, DIMM, projwT, DIMM);
    tc(xb, projwT, DIMM, out, DIMM, NTOK, DIMM, 1.f, 1.f, proj_b, 0);
}

// round 9
// speedup vs baseline: 7.4646x; 1.0222x over previous
#include <cuda_runtime.h>
#include <cuda_bf16.h>
#include <cstdint>
#include <cstddef>

// ---------------- problem constants ----------------
#define NTOK 10992
#define MP   11008
#define DIMM 1024
#define HIDD 4096
#define LRATE 0.1f
#define NS_A 3.4445f
#define NS_B (-4.7750f)
#define NS_C 2.0315f

typedef unsigned long long u64;
typedef long long i64;
typedef __nv_bfloat16 bf16;

#if !defined(__CUDA_ARCH__) || defined(__CUDA_ARCH_FEAT_SM103_ALL)
#define TC_HAS_TCGEN05 1
#else
#define TC_HAS_TCGEN05 0
#endif

// ================= PTX helpers (sm_103a) =================
#if TC_HAS_TCGEN05
__device__ __forceinline__ uint32_t smem_u32(const void* p) {
    uint32_t a;
    asm("{ .reg .u64 t; cvta.to.shared.u64 t, %1; cvt.u32.u64 %0, t; }" : "=r"(a) : "l"(p));
    return a;
}
__device__ __forceinline__ uint32_t elect1() {
    uint32_t p;
    asm volatile("{\n.reg .pred p;\nelect.sync _|p, 0xFFFFFFFF;\nselp.b32 %0,1,0,p;\n}" : "=r"(p));
    return p;
}
#define MBARRIER_INIT(a, c) \
    asm volatile("mbarrier.init.shared.b64 [%0], %1;" :: "r"((uint32_t)(a)), "r"((uint32_t)(c)) : "memory")
#define MBARRIER_WAIT_PARITY(a, ph) do { \
    uint32_t _m = (uint32_t)(a); uint32_t _p = (uint32_t)(ph); uint32_t _d; \
    asm volatile("{\n.reg .pred p;\nmbarrier.try_wait.parity.acquire.cta.shared::cta.b64 p, [%1], %2;\nselp.b32 %0,1,0,p;\n}" \
        : "=r"(_d) : "r"(_m), "r"(_p) : "memory"); \
    if (!_d) { \
        asm volatile("{\n.reg .pred P1;\nWL_%=:\nmbarrier.try_wait.parity.acquire.cta.shared::cta.b64 P1, [%0], %1, 0x989680;\n@P1 bra.uni WD_%=;\nbra.uni WL_%=;\nWD_%=:\n}" \
            :: "r"(_m), "r"(_p) : "memory"); \
    } } while (0)
#define TCGEN05_ALLOC(sa, n) \
    asm volatile("tcgen05.alloc.cta_group::1.sync.aligned.shared::cta.b32 [%0], %1;" \
        :: "r"((uint32_t)(sa)), "r"((uint32_t)(n)) : "memory")
#define TCGEN05_RELINQ() \
    asm volatile("tcgen05.relinquish_alloc_permit.cta_group::1.sync.aligned;")
#define TCGEN05_DEALLOC(t, n) \
    asm volatile("tcgen05.dealloc.cta_group::1.sync.aligned.b32 %0, %1;" :: "r"(t), "r"((uint32_t)(n)))
#define TCGEN05_COMMIT(a) \
    asm volatile("tcgen05.commit.cta_group::1.mbarrier::arrive::one.shared::cluster.b64 [%0];" \
        :: "r"((uint32_t)(a)) : "memory")
#define TCGEN05_FENCE_AFTER() asm volatile("tcgen05.fence::after_thread_sync;" ::: "memory")
#define TCGEN05_WAIT_LD() asm volatile("tcgen05.wait::ld.sync.aligned;" ::: "memory")
#define FENCE_ASYNC() asm volatile("fence.proxy.async.shared::cta;" ::: "memory")
#define STS128(r0, r1, r2, r3, a) \
    asm volatile("st.shared.v4.b32 [%0], {%1,%2,%3,%4};" :: "r"(a), "r"(r0), "r"(r1), "r"(r2), "r"(r3) : "memory")
#define TCGEN05_LD_X32(r, ta) \
    asm volatile("tcgen05.ld.sync.aligned.32x32b.x32.b32 " \
        "{%0,%1,%2,%3,%4,%5,%6,%7,%8,%9,%10,%11,%12,%13,%14,%15," \
        "%16,%17,%18,%19,%20,%21,%22,%23,%24,%25,%26,%27,%28,%29,%30,%31}, [%32];" \
        : "=r"((r)[0]), "=r"((r)[1]), "=r"((r)[2]), "=r"((r)[3]), "=r"((r)[4]), "=r"((r)[5]), \
          "=r"((r)[6]), "=r"((r)[7]), "=r"((r)[8]), "=r"((r)[9]), "=r"((r)[10]), "=r"((r)[11]), \
          "=r"((r)[12]), "=r"((r)[13]), "=r"((r)[14]), "=r"((r)[15]), "=r"((r)[16]), "=r"((r)[17]), \
          "=r"((r)[18]), "=r"((r)[19]), "=r"((r)[20]), "=r"((r)[21]), "=r"((r)[22]), "=r"((r)[23]), \
          "=r"((r)[24]), "=r"((r)[25]), "=r"((r)[26]), "=r"((r)[27]), "=r"((r)[28]), "=r"((r)[29]), \
          "=r"((r)[30]), "=r"((r)[31]) : "r"(ta))

static constexpr u64 SMEM_DESC_BASE =
    (u64(2) << 61) | (u64(1) << 46) | (u64(64) << 32) | (u64(1) << 16);
__device__ __forceinline__ u64 mkdesc(uint32_t sa) {
    return SMEM_DESC_BASE | ((u64)(sa >> 4) & 0x3FFF);
}
__device__ __forceinline__ void mma_f16_ss(uint32_t d, u64 ad, u64 bd, uint32_t idesc, bool acc) {
    uint32_t en = acc ? 1u : 0u;
    asm volatile(
        "{\n\t.reg .pred p;\n\tsetp.ne.u32 p, %4, 0;\n\t"
        "tcgen05.mma.cta_group::1.kind::f16 [%0], %1, %2, %3, {%5,%5,%5,%5}, p;\n\t}"
        :: "r"(d), "l"(ad), "l"(bd), "r"(idesc), "r"(en), "r"(0u) : "memory");
}
#endif

#define SWZ(b) ((b) ^ (((b) >> 3) & 0x70))
#define TCIDESC 0x08200490u   // dtype=F32, a=BF16, b=BF16, N=128, M=128

// ---------------- fp32 scratch ----------------
static constexpr size_t E_TOKD = (size_t)MP * DIMM;
static constexpr size_t E_TOKH = (size_t)MP * HIDD;
static constexpr size_t E_W    = (size_t)DIMM * HIDD;
static constexpr size_t E_A    = (size_t)DIMM * DIMM;
static constexpr size_t E_QKVW = (size_t)DIMM * 3 * DIMM;

__device__ float g_qkv [(size_t)NTOK * 3 * DIMM];
__device__ float g_kgv [(size_t)2 * NTOK * HIDD];
__device__ float g_h   [(size_t)NTOK * HIDD];
__device__ float g_r   [(size_t)NTOK * DIMM];
__device__ float g_GV  [2 * E_W];
__device__ float g_P   [E_W];
__device__ float g_grad[3 * E_W];
__device__ float g_X1  [3 * E_W];
__device__ float g_X2  [3 * E_W];
__device__ float g_A   [3 * E_A];
__device__ double g_nrm[3];

// ---------------- bf16 hi/lo pool ----------------
static constexpr size_t O_X    = 0;
static constexpr size_t O_K    = O_X    + E_TOKD * 4;
static constexpr size_t O_KT   = O_K    + E_TOKD * 4;
static constexpr size_t O_Q    = O_KT   + E_TOKD * 4;
static constexpr size_t O_RT   = O_Q    + E_TOKD * 4;
static constexpr size_t O_H    = O_RT   + E_TOKD * 4;
static constexpr size_t O_HT   = O_H    + E_TOKH * 4;
static constexpr size_t O_DKGT = O_HT   + E_TOKH * 4;
static constexpr size_t O_DKVT = O_DKGT + E_TOKH * 4;
static constexpr size_t O_WGT  = O_DKVT + E_TOKH * 4;
static constexpr size_t O_WVT  = O_WGT  + E_W * 4;
static constexpr size_t O_WP   = O_WVT  + E_W * 4;
static constexpr size_t O_WPT  = O_WP   + E_W * 4;
static constexpr size_t O_QKVW = O_WPT  + E_W * 4;
static constexpr size_t O_PRJW = O_QKVW + E_QKVW * 4;
static constexpr size_t O_NSX  = O_PRJW + E_A * 4;
static constexpr size_t O_NSXT = O_NSX  + 3 * E_W * 4;
static constexpr size_t O_NSA  = O_NSXT + 3 * E_W * 4;
static constexpr size_t O_NSA2 = O_NSA  + 3 * E_A * 4;
static constexpr size_t POOL_B = O_NSA2 + 3 * E_A * 4;
__device__ __align__(1024) unsigned char g_bf[POOL_B];

// ============ tcgen05 split-bf16 GEMM: 128x256 tile, cg1, double-buffered ======
#define TC_STAGE 98304
#define TC_SMEM  (2 * TC_STAGE + 1024)

__global__ void __launch_bounds__(256, 1) tc_gemm(
    const bf16* __restrict__ Ahi, const bf16* __restrict__ Alo,
    const bf16* __restrict__ Bhi, const bf16* __restrict__ Blo,
    int Kp, float* __restrict__ C, int ldc,
    const float* __restrict__ E, int ldE,
    float alpha, float beta, int M,
    i64 az, i64 bz, i64 cz, i64 ez,
    bf16* __restrict__ Ohi, bf16* __restrict__ Olo, int ldo, i64 oz)
{
#if TC_HAS_TCGEN05
    extern __shared__ unsigned char dsm_raw[];
    __shared__ __align__(8) u64 s_mb[2];
    __shared__ uint32_t s_tmem[1];

    const int tid = threadIdx.x;
    const int wid = tid >> 5;
    const int lane = tid & 31;
    const i64 zz = blockIdx.z;
    Ahi += zz * az; Alo += zz * az;
    Bhi += zz * bz; Blo += zz * bz;
    if (C)   C   += zz * cz;
    if (E)   E   += zz * ez;
    if (Ohi) { Ohi += zz * oz; Olo += zz * oz; }

    const uint32_t sb  = (smem_u32(dsm_raw) + 1023) & ~1023u;
    const uint32_t mbB = smem_u32(&s_mb[0]);

    if (tid == 0) { MBARRIER_INIT(mbB, 1); MBARRIER_INIT(mbB + 8, 1); }
    if (wid == 0) {
        TCGEN05_ALLOC(smem_u32(s_tmem), 256);
        TCGEN05_RELINQ();
    }
    __syncthreads();
    const uint32_t tmem = s_tmem[0];

    const int m0 = blockIdx.y * 128;
    const int n0 = blockIdx.x * 256;

    const int r0    = tid >> 3;
    const int col16 = (tid & 7) * 16;
    const size_t rowB = (size_t)Kp * 2;
    const char* pAhi = (const char*)Ahi + (size_t)(m0 + r0) * rowB + col16;
    const char* pAlo = (const char*)Alo + (size_t)(m0 + r0) * rowB + col16;
    const char* pBhi = (const char*)Bhi + (size_t)(n0 + r0) * rowB + col16;
    const char* pBlo = (const char*)Blo + (size_t)(n0 + r0) * rowB + col16;
    uint32_t swA[4], swB[8];
#pragma unroll
    for (int k = 0; k < 4; ++k) swA[k] = SWZ((uint32_t)(r0 + 32 * k) * 128 + col16);
#pragma unroll
    for (int k = 0; k < 8; ++k) swB[k] = SWZ((uint32_t)(r0 + 32 * k) * 128 + col16);

    uint4 va[8], vb[16];
#define TCFETCH(cc) do { const size_t gb_ = (size_t)(cc) * 128;                         \
    _Pragma("unroll") for (int k_ = 0; k_ < 4; ++k_) {                                  \
        va[k_]     = *reinterpret_cast<const uint4*>(pAhi + (size_t)(32 * k_) * rowB + gb_); \
        va[4 + k_] = *reinterpret_cast<const uint4*>(pAlo + (size_t)(32 * k_) * rowB + gb_); \
    }                                                                                   \
    _Pragma("unroll") for (int k_ = 0; k_ < 8; ++k_) {                                  \
        vb[k_]     = *reinterpret_cast<const uint4*>(pBhi + (size_t)(32 * k_) * rowB + gb_); \
        vb[8 + k_] = *reinterpret_cast<const uint4*>(pBlo + (size_t)(32 * k_) * rowB + gb_); \
    } } while (0)

    const int NC = Kp >> 6;
    TCFETCH(0);
    for (int c = 0; c < NC; ++c) {
        const int s = c & 1;
        const int phase = c >> 1;
        const uint32_t mbs = mbB + (uint32_t)s * 8;
        const uint32_t stg = sb + (uint32_t)s * TC_STAGE;
        if (c >= 2) { MBARRIER_WAIT_PARITY(mbs, (phase - 1) & 1); }
#pragma unroll
        for (int k = 0; k < 4; ++k) {
            STS128(va[k].x, va[k].y, va[k].z, va[k].w, stg + swA[k]);
            STS128(va[4 + k].x, va[4 + k].y, va[4 + k].z, va[4 + k].w, stg + 16384u + swA[k]);
        }
#pragma unroll
        for (int k = 0; k < 8; ++k) {
            STS128(vb[k].x, vb[k].y, vb[k].z, vb[k].w, stg + 32768u + swB[k]);
            STS128(vb[8 + k].x, vb[8 + k].y, vb[8 + k].z, vb[8 + k].w, stg + 65536u + swB[k]);
        }
        if (c + 1 < NC) { TCFETCH(c + 1); }
        FENCE_ASYNC();
        __syncthreads();
        if (wid == 0 && elect1()) {
            u64 aH = mkdesc(stg);
            u64 aL = mkdesc(stg + 16384);
#pragma unroll
            for (int nh = 0; nh < 2; ++nh) {
                const uint32_t d = tmem + (uint32_t)nh * 128;
                u64 bH = mkdesc(stg + 32768 + (uint32_t)nh * 16384);
                u64 bL = mkdesc(stg + 65536 + (uint32_t)nh * 16384);
#pragma unroll
                for (int ks = 0; ks < 4; ++ks)
                    mma_f16_ss(d, aH + ks * 2, bH + ks * 2, TCIDESC, !(c == 0 && ks == 0));
#pragma unroll
                for (int ks = 0; ks < 4; ++ks)
                    mma_f16_ss(d, aH + ks * 2, bL + ks * 2, TCIDESC, true);
#pragma unroll
                for (int ks = 0; ks < 4; ++ks)
                    mma_f16_ss(d, aL + ks * 2, bH + ks * 2, TCIDESC, true);
            }
            TCGEN05_COMMIT(mbs);
        }
    }
    {
        const int cl = NC - 1;
        MBARRIER_WAIT_PARITY(mbB + (uint32_t)(cl & 1) * 8, (cl >> 1) & 1);
    }
    TCGEN05_FENCE_AFTER();

    const int sub = wid & 3;
    const int colh = (wid >> 2) * 128;
    const int m = m0 + sub * 32 + lane;
#pragma unroll
    for (int qq = 0; qq < 4; ++qq) {
        uint32_t r32[32];
        TCGEN05_LD_X32(r32, tmem + colh + qq * 32);
        TCGEN05_WAIT_LD();
        if (m < M) {
            const int ncol = n0 + colh + qq * 32;
            float o[32];
            if (beta != 0.f) {
                const float* erow = E + (size_t)m * ldE + ncol;
#pragma unroll
                for (int j = 0; j < 32; j += 4) {
                    float4 e = *reinterpret_cast<const float4*>(erow + j);
                    o[j]     = alpha * __uint_as_float(r32[j])     + beta * e.x;
                    o[j + 1] = alpha * __uint_as_float(r32[j + 1]) + beta * e.y;
                    o[j + 2] = alpha * __uint_as_float(r32[j + 2]) + beta * e.z;
                    o[j + 3] = alpha * __uint_as_float(r32[j + 3]) + beta * e.w;
                }
            } else {
#pragma unroll
                for (int j = 0; j < 32; ++j) o[j] = alpha * __uint_as_float(r32[j]);
            }
            if (C) {
                float* crow = C + (size_t)m * ldc + ncol;
#pragma unroll
                for (int j = 0; j < 32; j += 4)
                    *reinterpret_cast<float4*>(crow + j) = make_float4(o[j], o[j+1], o[j+2], o[j+3]);
            }
            if (Ohi) {
                bf16* hrow = Ohi + (size_t)m * ldo + ncol;
                bf16* lrow = Olo + (size_t)m * ldo + ncol;
#pragma unroll
                for (int j = 0; j < 32; j += 4) {
                    __align__(8) bf16 hv[4];
                    __align__(8) bf16 lv[4];
#pragma unroll
                    for (int t = 0; t < 4; ++t) {
                        bf16 hb_ = __float2bfloat16(o[j + t]);
                        hv[t] = hb_;
                        lv[t] = __float2bfloat16(o[j + t] - __bfloat162float(hb_));
                    }
                    *reinterpret_cast<uint2*>(hrow + j) = *reinterpret_cast<const uint2*>(hv);
                    *reinterpret_cast<uint2*>(lrow + j) = *reinterpret_cast<const uint2*>(lv);
                }
            }
        }
    }
    __syncthreads();
    if (wid == 0) TCGEN05_DEALLOC(tmem, 256);
#undef TCFETCH
#endif
}

// ================= conversion kernels (z-batched) =================
__global__ void conv_k(const float* __restrict__ src, int ld, int R, int C,
                       bf16* __restrict__ hi, bf16* __restrict__ lo, int Cp,
                       i64 srcZ, i64 dstZ)
{
    const i64 z = blockIdx.z;
    src += z * srcZ; hi += z * dstZ; lo += z * dstZ;
    int c = (blockIdx.x * blockDim.x + threadIdx.x) * 4;
    int r = blockIdx.y;
    if (c >= Cp) return;
    __align__(8) bf16 h4[4];
    __align__(8) bf16 l4[4];
    if (r < R && c < C) {
        float4 fv = *reinterpret_cast<const float4*>(src + (size_t)r * ld + c);
        float vv[4] = {fv.x, fv.y, fv.z, fv.w};
#pragma unroll
        for (int j = 0; j < 4; j++) {
            bf16 h = __float2bfloat16(vv[j]);
            h4[j] = h;
            l4[j] = __float2bfloat16(vv[j] - __bfloat162float(h));
        }
    } else {
#pragma unroll
        for (int j = 0; j < 4; j++) { h4[j] = __float2bfloat16(0.f); l4[j] = h4[j]; }
    }
    size_t o = (size_t)r * Cp + c;
    *reinterpret_cast<uint2*>(hi + o) = *reinterpret_cast<const uint2*>(h4);
    *reinterpret_cast<uint2*>(lo + o) = *reinterpret_cast<const uint2*>(l4);
}

__global__ void convT_k(const float* __restrict__ src, int ld, int R, int C,
                        bf16* __restrict__ hi, bf16* __restrict__ lo, int Rp,
                        i64 srcZ, i64 dstZ)
{
    __shared__ float t[32][33];
    const i64 z = blockIdx.z;
    src += z * srcZ; hi += z * dstZ; lo += z * dstZ;
    int c0 = blockIdx.x * 32;
    int r0 = blockIdx.y * 32;
    int tx = threadIdx.x, ty = threadIdx.y;
#pragma unroll
    for (int j = 0; j < 32; j += 8) {
        int r = r0 + ty + j;
        t[ty + j][tx] = (r < R) ? src[(size_t)r * ld + c0 + tx] : 0.f;
    }
    __syncthreads();
#pragma unroll
    for (int j = 0; j < 32; j += 8) {
        float fv = t[tx][ty + j];
        size_t o = (size_t)(c0 + ty + j) * Rp + r0 + tx;
        bf16 h = __float2bfloat16(fv);
        hi[o] = h;
        lo[o] = __float2bfloat16(fv - __bfloat162float(h));
    }
}

// ================= fused activation + transpose kernels =================
// h = swish(kg)*kv. Writes row-major pairs [MP,HIDD] and (optionally) transposed
// pairs [HIDD,MP]. fp32 h is NOT written. grid (HIDD/32, MP/32), block (32,8).
__global__ void swishT_k(const float* __restrict__ kg, const float* __restrict__ kv,
                         bf16* __restrict__ hhi, bf16* __restrict__ hlo,
                         bf16* __restrict__ thi, bf16* __restrict__ tlo)
{
    __shared__ float t[32][33];
    int c0 = blockIdx.x * 32;   // HIDD
    int r0 = blockIdx.y * 32;   // MP
    int tx = threadIdx.x, ty = threadIdx.y;
#pragma unroll
    for (int j = 0; j < 32; j += 8) {
        int r = r0 + ty + j;
        float hv = 0.f;
        if (r < NTOK) {
            size_t idx = (size_t)r * HIDD + c0 + tx;
            float g = kg[idx], u = kv[idx];
            hv = g / (1.f + __expf(-g)) * u;
        }
        t[ty + j][tx] = hv;
        size_t o = (size_t)r * HIDD + c0 + tx;
        bf16 hb_ = __float2bfloat16(hv);
        hhi[o] = hb_;
        hlo[o] = __float2bfloat16(hv - __bfloat162float(hb_));
    }
    if (thi) {
        __syncthreads();
#pragma unroll
        for (int j = 0; j < 32; j += 8) {
            float fv = t[tx][ty + j];
            size_t o = (size_t)(c0 + ty + j) * MP + r0 + tx;
            bf16 hb_ = __float2bfloat16(fv);
            thi[o] = hb_;
            tlo[o] = __float2bfloat16(fv - __bfloat162float(hb_));
        }
    }
}

// dkg/dkv from (dh, kg, kv); writes ONLY transposed pairs [HIDD,MP].
__global__ void bw_ewT_k(const float* __restrict__ dh,
                         const float* __restrict__ kg, const float* __restrict__ kv,
                         bf16* __restrict__ gthi, bf16* __restrict__ gtlo,
                         bf16* __restrict__ vthi, bf16* __restrict__ vtlo)
{
    __shared__ float tg[32][33];
    __shared__ float tv[32][33];
    int c0 = blockIdx.x * 32;
    int r0 = blockIdx.y * 32;
    int tx = threadIdx.x, ty = threadIdx.y;
#pragma unroll
    for (int j = 0; j < 32; j += 8) {
        int r = r0 + ty + j;
        float dkg = 0.f, dkv = 0.f;
        if (r < NTOK) {
            size_t idx = (size_t)r * HIDD + c0 + tx;
            float d = dh[idx], g = kg[idx], u = kv[idx];
            float s = 1.f / (1.f + __expf(-g));
            dkv = d * g * s;
            dkg = d * u * s * (1.f + g * (1.f - s));
        }
        tg[ty + j][tx] = dkg;
        tv[ty + j][tx] = dkv;
    }
    __syncthreads();
#pragma unroll
    for (int j = 0; j < 32; j += 8) {
        size_t o = (size_t)(c0 + ty + j) * MP + r0 + tx;
        float fg = tg[tx][ty + j];
        float fv = tv[tx][ty + j];
        bf16 hg = __float2bfloat16(fg);
        gthi[o] = hg;
        gtlo[o] = __float2bfloat16(fg - __bfloat162float(hg));
        bf16 hv = __float2bfloat16(fv);
        vthi[o] = hv;
        vtlo[o] = __float2bfloat16(fv - __bfloat162float(hv));
    }
}

// ================= elementwise / reductions =================
__global__ void norm_heads_k(float* __restrict__ base,
                             const float* __restrict__ sc, const float* __restrict__ bi)
{
    int w = (blockIdx.x * blockDim.x + threadIdx.x) >> 5;
    int lane = threadIdx.x & 31;
    if (w >= NTOK * 16) return;
    int rowi = w >> 4, head = w & 15;
    float* p = base + (size_t)rowi * (3 * DIMM) + head * 64;
    float x0 = p[lane], x1 = p[lane + 32];
    float ss = x0 * x0 + x1 * x1;
#pragma unroll
    for (int o = 16; o; o >>= 1) ss += __shfl_xor_sync(0xffffffffu, ss, o);
    float inv = 1.f / (sqrtf(ss) + 1e-6f);
    p[lane]      = x0 * inv * sc[lane]      + bi[lane];
    p[lane + 32] = x1 * inv * sc[lane + 32] + bi[lane + 32];
}

__global__ void zero3_k(double* p) { if (threadIdx.x < 3) p[threadIdx.x] = 0.0; }

__global__ void sumsq3_k(const float* __restrict__ x, int n, double* __restrict__ out)
{
    __shared__ double sm[256];
    const int z = blockIdx.y;
    x += (size_t)z * n;
    double a = 0.0;
    for (int i = blockIdx.x * blockDim.x + threadIdx.x; i < n; i += gridDim.x * blockDim.x) {
        float fv = x[i];
        a += (double)fv * (double)fv;
    }
    sm[threadIdx.x] = a;
    __syncthreads();
    for (int s = 128; s; s >>= 1) {
        if (threadIdx.x < s) sm[threadIdx.x] += sm[threadIdx.x + s];
        __syncthreads();
    }
    if (threadIdx.x == 0) atomicAdd(&out[z], sm[0]);
}

__global__ void scale3_k(const float4* __restrict__ g, float4* __restrict__ X, int n4,
                         const double* __restrict__ nrm)
{
    const int z = blockIdx.y;
    int i = blockIdx.x * blockDim.x + threadIdx.x;
    if (i >= n4) return;
    float inv = (float)(1.0 / (sqrt(nrm[z]) + 1e-7));
    float4 fv = g[(size_t)z * n4 + i];
    fv.x *= inv; fv.y *= inv; fv.z *= inv; fv.w *= inv;
    X[(size_t)z * n4 + i] = fv;
}

__global__ void transpose_k(const float* __restrict__ src, float* __restrict__ dst,
                            int R, int C)
{
    __shared__ float t[32][33];
    int c0 = blockIdx.x * 32, r0 = blockIdx.y * 32;
    int x = c0 + threadIdx.x;
#pragma unroll
    for (int j = 0; j < 32; j += 8)
        t[threadIdx.y + j][threadIdx.x] = src[(size_t)(r0 + threadIdx.y + j) * C + x];
    __syncthreads();
    int x2 = r0 + threadIdx.x;
#pragma unroll
    for (int j = 0; j < 32; j += 8)
        dst[(size_t)(c0 + threadIdx.y + j) * R + x2] = t[threadIdx.x][threadIdx.y + j];
}

__global__ void upd_k(float4* __restrict__ p, const float4* __restrict__ x, int n4)
{
    int i = blockIdx.x * blockDim.x + threadIdx.x;
    if (i >= n4) return;
    float4 a = p[i], bb = x[i];
    a.x -= LRATE * bb.x; a.y -= LRATE * bb.y; a.z -= LRATE * bb.z; a.w -= LRATE * bb.w;
    p[i] = a;
}

// ================= host orchestration =================
struct BP { bf16 *hi, *lo; };

static void* symaddr(const void* s) { void* p = nullptr; cudaGetSymbolAddress(&p, s); return p; }

static void tc(BP A, BP B, int Kp, float* C, int ldc, int M, int N,
               float alpha, float beta, const float* E, int ldE,
               int nz = 1, i64 az = 0, i64 bz = 0, i64 cz = 0, i64 ez = 0,
               BP O = {nullptr, nullptr}, int ldo = 0, i64 oz = 0)
{
    dim3 gr(N / 256, (M + 127) / 128, nz);
    tc_gemm<<<gr, 256, TC_SMEM>>>(A.hi, A.lo, B.hi, B.lo, Kp, C, ldc, E, ldE,
                                  alpha, beta, M, az, bz, cz, ez, O.hi, O.lo, ldo, oz);
}

static void conv(const float* s, int ld, int R, int C, BP d, int Rp, int Cp,
                 int nz = 1, i64 sZ = 0, i64 dZ = 0)
{
    dim3 gr((Cp / 4 + 255) / 256, Rp, nz);
    conv_k<<<gr, 256>>>(s, ld, R, C, d.hi, d.lo, Cp, sZ, dZ);
}

static void convT(const float* s, int ld, int R, int C, BP d, int Rp,
                  int nz = 1, i64 sZ = 0, i64 dZ = 0)
{
    dim3 gr(C / 32, Rp / 32, nz);
    convT_k<<<gr, dim3(32, 8)>>>(s, ld, R, C, d.hi, d.lo, Rp, sZ, dZ);
}

extern "C" void kernel_launch(void* const* d_in, const int* in_sizes, int n_in,
                              void* d_out, int out_size)
{
    const float* x        = (const float*)d_in[0];
    const float* qkv_w    = (const float*)d_in[1];
    const float* qkv_b    = (const float*)d_in[2];
    const float* qn_s     = (const float*)d_in[3];
    const float* qn_b     = (const float*)d_in[4];
    const float* kn_s     = (const float*)d_in[5];
    const float* kn_b     = (const float*)d_in[6];
    const float* ttt_gate = (const float*)d_in[7];
    const float* ttt_val  = (const float*)d_in[8];
    const float* ttt_proj = (const float*)d_in[9];
    const float* proj_w   = (const float*)d_in[10];
    const float* proj_b   = (const float*)d_in[11];
    float* out = (float*)d_out;

    cudaFuncSetAttribute(tc_gemm, cudaFuncAttributeMaxDynamicSharedMemorySize, TC_SMEM);

    float* qkv  = (float*)symaddr(g_qkv);
    float* kgv  = (float*)symaddr(g_kgv);
    float* h    = (float*)symaddr(g_h);
    float* r    = (float*)symaddr(g_r);
    float* GV   = (float*)symaddr(g_GV);
    float* P    = (float*)symaddr(g_P);
    float* grad = (float*)symaddr(g_grad);
    float* X1   = (float*)symaddr(g_X1);
    float* X2   = (float*)symaddr(g_X2);
    float* Amat = (float*)symaddr(g_A);
    double* nrm = (double*)symaddr(g_nrm);
    unsigned char* pool = (unsigned char*)symaddr(g_bf);

    auto bp = [&](size_t off, size_t elems) { BP b; b.hi = (bf16*)(pool + off); b.lo = b.hi + elems; return b; };

    BP xb    = bp(O_X, E_TOKD);
    BP kb    = bp(O_K, E_TOKD);
    BP kTb   = bp(O_KT, E_TOKD);
    BP qb    = bp(O_Q, E_TOKD);
    BP rTb   = bp(O_RT, E_TOKD);
    BP hb    = bp(O_H, E_TOKH);
    BP hTb   = bp(O_HT, E_TOKH);
    BP dkgT  = bp(O_DKGT, E_TOKH);
    BP dkvT  = bp(O_DKVT, E_TOKH);
    BP wGt   = bp(O_WGT, E_W);
    BP wP    = bp(O_WP,  E_W);
    BP wPt   = bp(O_WPT, E_W);
    BP qkvwT = bp(O_QKVW, E_QKVW);
    BP projwT = bp(O_PRJW, E_A);
    BP nsX   = bp(O_NSX,  E_W);
    BP nsXT  = bp(O_NSXT, E_W);
    BP nsA   = bp(O_NSA,  E_A);
    BP nsA2  = bp(O_NSA2, E_A);

    const size_t TB = sizeof(float) * E_W;
    cudaMemcpyAsync(GV,       ttt_gate, TB, cudaMemcpyDeviceToDevice, 0);
    cudaMemcpyAsync(GV + E_W, ttt_val,  TB, cudaMemcpyDeviceToDevice, 0);
    cudaMemcpyAsync(P,        ttt_proj, TB, cudaMemcpyDeviceToDevice, 0);

    // ---- qkv = x @ qkv_w + b ----
    conv (x, DIMM, NTOK, DIMM, xb, MP, DIMM);
    convT(qkv_w, 3 * DIMM, DIMM, 3 * DIMM, qkvwT, DIMM);
    tc(xb, qkvwT, DIMM, qkv, 3 * DIMM, NTOK, 3 * DIMM, 1.f, 1.f, qkv_b, 0);

    {
        int nb = (NTOK * 16 * 32 + 255) / 256;
        norm_heads_k<<<nb, 256>>>(qkv, qn_s, qn_b);
        norm_heads_k<<<nb, 256>>>(qkv + DIMM, kn_s, kn_b);
    }

    const float* kmat = qkv + DIMM;
    const float* vmat = qkv + 2 * DIMM;
    conv (kmat, 3 * DIMM, NTOK, DIMM, kb, MP, DIMM);
    convT(kmat, 3 * DIMM, NTOK, DIMM, kTb, MP);
    conv (qkv, 3 * DIMM, NTOK, DIMM, qb, MP, DIMM);

    const dim3 grTH(HIDD / 32, MP / 32);
    const i64 ZW = 2 * (i64)E_W;
    const i64 ZA = 2 * (i64)E_A;
    const i64 KGV = (i64)NTOK * HIDD;

    for (int step = 0; step < 2; ++step) {
        convT(GV, HIDD, DIMM, HIDD, wGt, DIMM, 2, (i64)E_W, ZW);
        conv (P, DIMM, HIDD, DIMM, wP, HIDD, DIMM);
        convT(P, DIMM, HIDD, DIMM, wPt, HIDD);

        // kg|kv = k @ {G,V}
        tc(kb, wGt, DIMM, kgv, HIDD, NTOK, HIDD, 1.f, 0.f, nullptr, 0,
           2, 0, ZW, KGV, 0);
        // h pairs + transposed h pairs, fused (no fp32 h)
        swishT_k<<<grTH, dim3(32, 8)>>>(kgv, kgv + KGV, hb.hi, hb.lo, hTb.hi, hTb.lo);
        // r = h @ P - v   (+ r pairs into xb)
        tc(hb, wPt, HIDD, r, DIMM, NTOK, DIMM, 1.f, -1.f, vmat, 3 * DIMM,
           1, 0, 0, 0, 0, xb, DIMM, 0);
        convT(r, DIMM, NTOK, DIMM, rTb, MP);
        // gP^T = r^T @ h
        tc(rTb, hTb, MP, grad + 2 * E_W, HIDD, DIMM, HIDD, 1.f, 0.f, nullptr, 0);
        // dh = r @ P^T  -> h buffer
        tc(xb, wP, DIMM, h, HIDD, NTOK, HIDD, 1.f, 0.f, nullptr, 0);
        // dkg/dkv transposed pairs, fused (no fp32 dkg/dkv)
        bw_ewT_k<<<grTH, dim3(32, 8)>>>(h, kgv, kgv + KGV,
                                        dkgT.hi, dkgT.lo, dkvT.hi, dkvT.lo);
        // gG|gV = k^T @ {dkg,dkv}
        tc(kTb, dkgT, MP, grad, HIDD, DIMM, HIDD, 1.f, 0.f, nullptr, 0,
           2, 0, 2 * (i64)E_TOKH, (i64)E_W, 0);

        // ---- batched Newton-Schulz over {gG, gV, gP^T} ----
        zero3_k<<<1, 4>>>(nrm);
        sumsq3_k<<<dim3(256, 3), 256>>>(grad, (int)E_W, nrm);
        scale3_k<<<dim3(((int)E_W / 4 + 255) / 256, 3), 256>>>(
            (const float4*)grad, (float4*)X1, (int)E_W / 4, nrm);
        float* X = X1;
        float* Y = X2;
        conv (X, HIDD, DIMM, HIDD, nsX, DIMM, HIDD, 3, (i64)E_W, ZW);
        convT(X, HIDD, DIMM, HIDD, nsXT, DIMM, 3, (i64)E_W, ZW);
        for (int it = 0; it < 5; ++it) {
            tc(nsX, nsX, HIDD, Amat, DIMM, DIMM, DIMM, 1.f, 0.f, nullptr, 0,
               3, ZW, ZW, (i64)E_A, 0, nsA, DIMM, ZA);
            tc(nsA, nsA, DIMM, nullptr, 0, DIMM, DIMM, NS_C, NS_B, Amat, DIMM,
               3, ZA, ZA, 0, (i64)E_A, nsA2, DIMM, ZA);
            tc(nsA2, nsXT, DIMM, Y, HIDD, DIMM, HIDD, 1.f, NS_A, X, HIDD,
               3, ZA, ZW, (i64)E_W, (i64)E_W, nsX, HIDD, ZW);
            if (it < 4)
                convT(Y, HIDD, DIMM, HIDD, nsXT, DIMM, 3, (i64)E_W, ZW);
            float* t = X; X = Y; Y = t;
        }
        upd_k<<<((int)(2 * E_W / 4) + 255) / 256, 256>>>((float4*)GV, (const float4*)X, (int)(2 * E_W / 4));
        {
            dim3 gr(HIDD / 32, DIMM / 32);
            transpose_k<<<gr, dim3(32, 8)>>>(X + 2 * E_W, Y, DIMM, HIDD);
            upd_k<<<((int)(E_W / 4) + 255) / 256, 256>>>((float4*)P, (const float4*)Y, (int)(E_W / 4));
        }
    }

    // ---- final forward with q ----
    convT(GV, HIDD, DIMM, HIDD, wGt, DIMM, 2, (i64)E_W, ZW);
    convT(P, DIMM, HIDD, DIMM, wPt, HIDD);
    tc(qb, wGt, DIMM, kgv, HIDD, NTOK, HIDD, 1.f, 0.f, nullptr, 0,
       2, 0, ZW, KGV, 0);
    swishT_k<<<grTH, dim3(32, 8)>>>(kgv, kgv + KGV, hb.hi, hb.lo, nullptr, nullptr);
    tc(hb, wPt, HIDD, nullptr, 0, NTOK, DIMM, 1.f, 0.f, nullptr, 0,
       1, 0, 0, 0, 0, xb, DIMM, 0);
    convT(proj_w, DIMM, DIMM, DIMM, projwT, DIMM);
    tc(xb, projwT, DIMM, out, DIMM, NTOK, DIMM, 1.f, 1.f, proj_b, 0);
}

// round 12
// speedup vs baseline: 7.4832x; 1.0025x over previous
#include <cuda_runtime.h>
#include <cuda_bf16.h>
#include <cstdint>
#include <cstddef>

// ---------------- problem constants ----------------
#define NTOK 10992
#define MP   11008
#define DIMM 1024
#define HIDD 4096
#define LRATE 0.1f
#define NS_A 3.4445f
#define NS_B (-4.7750f)
#define NS_C 2.0315f

typedef unsigned long long u64;
typedef long long i64;
typedef __nv_bfloat16 bf16;

#if !defined(__CUDA_ARCH__) || defined(__CUDA_ARCH_FEAT_SM103_ALL)
#define TC_HAS_TCGEN05 1
#else
#define TC_HAS_TCGEN05 0
#endif

// ================= PTX helpers (sm_103a) =================
#if TC_HAS_TCGEN05
__device__ __forceinline__ uint32_t smem_u32(const void* p) {
    uint32_t a;
    asm("{ .reg .u64 t; cvta.to.shared.u64 t, %1; cvt.u32.u64 %0, t; }" : "=r"(a) : "l"(p));
    return a;
}
__device__ __forceinline__ uint32_t elect1() {
    uint32_t p;
    asm volatile("{\n.reg .pred p;\nelect.sync _|p, 0xFFFFFFFF;\nselp.b32 %0,1,0,p;\n}" : "=r"(p));
    return p;
}
#define MBARRIER_INIT(a, c) \
    asm volatile("mbarrier.init.shared.b64 [%0], %1;" :: "r"((uint32_t)(a)), "r"((uint32_t)(c)) : "memory")
#define MBARRIER_WAIT_PARITY(a, ph) do { \
    uint32_t _m = (uint32_t)(a); uint32_t _p = (uint32_t)(ph); uint32_t _d; \
    asm volatile("{\n.reg .pred p;\nmbarrier.try_wait.parity.acquire.cta.shared::cta.b64 p, [%1], %2;\nselp.b32 %0,1,0,p;\n}" \
        : "=r"(_d) : "r"(_m), "r"(_p) : "memory"); \
    if (!_d) { \
        asm volatile("{\n.reg .pred P1;\nWL_%=:\nmbarrier.try_wait.parity.acquire.cta.shared::cta.b64 P1, [%0], %1, 0x989680;\n@P1 bra.uni WD_%=;\nbra.uni WL_%=;\nWD_%=:\n}" \
            :: "r"(_m), "r"(_p) : "memory"); \
    } } while (0)
#define TCGEN05_ALLOC(sa, n) \
    asm volatile("tcgen05.alloc.cta_group::1.sync.aligned.shared::cta.b32 [%0], %1;" \
        :: "r"((uint32_t)(sa)), "r"((uint32_t)(n)) : "memory")
#define TCGEN05_RELINQ() \
    asm volatile("tcgen05.relinquish_alloc_permit.cta_group::1.sync.aligned;")
#define TCGEN05_DEALLOC(t, n) \
    asm volatile("tcgen05.dealloc.cta_group::1.sync.aligned.b32 %0, %1;" :: "r"(t), "r"((uint32_t)(n)))
#define TCGEN05_COMMIT(a) \
    asm volatile("tcgen05.commit.cta_group::1.mbarrier::arrive::one.shared::cluster.b64 [%0];" \
        :: "r"((uint32_t)(a)) : "memory")
#define TCGEN05_FENCE_AFTER() asm volatile("tcgen05.fence::after_thread_sync;" ::: "memory")
#define TCGEN05_WAIT_LD() asm volatile("tcgen05.wait::ld.sync.aligned;" ::: "memory")
#define FENCE_ASYNC() asm volatile("fence.proxy.async.shared::cta;" ::: "memory")
#define STS128(r0, r1, r2, r3, a) \
    asm volatile("st.shared.v4.b32 [%0], {%1,%2,%3,%4};" :: "r"(a), "r"(r0), "r"(r1), "r"(r2), "r"(r3) : "memory")
#define TCGEN05_LD_X32(r, ta) \
    asm volatile("tcgen05.ld.sync.aligned.32x32b.x32.b32 " \
        "{%0,%1,%2,%3,%4,%5,%6,%7,%8,%9,%10,%11,%12,%13,%14,%15," \
        "%16,%17,%18,%19,%20,%21,%22,%23,%24,%25,%26,%27,%28,%29,%30,%31}, [%32];" \
        : "=r"((r)[0]), "=r"((r)[1]), "=r"((r)[2]), "=r"((r)[3]), "=r"((r)[4]), "=r"((r)[5]), \
          "=r"((r)[6]), "=r"((r)[7]), "=r"((r)[8]), "=r"((r)[9]), "=r"((r)[10]), "=r"((r)[11]), \
          "=r"((r)[12]), "=r"((r)[13]), "=r"((r)[14]), "=r"((r)[15]), "=r"((r)[16]), "=r"((r)[17]), \
          "=r"((r)[18]), "=r"((r)[19]), "=r"((r)[20]), "=r"((r)[21]), "=r"((r)[22]), "=r"((r)[23]), \
          "=r"((r)[24]), "=r"((r)[25]), "=r"((r)[26]), "=r"((r)[27]), "=r"((r)[28]), "=r"((r)[29]), \
          "=r"((r)[30]), "=r"((r)[31]) : "r"(ta))

static constexpr u64 SMEM_DESC_BASE =
    (u64(2) << 61) | (u64(1) << 46) | (u64(64) << 32) | (u64(1) << 16);
__device__ __forceinline__ u64 mkdesc(uint32_t sa) {
    return SMEM_DESC_BASE | ((u64)(sa >> 4) & 0x3FFF);
}
__device__ __forceinline__ void mma_f16_ss(uint32_t d, u64 ad, u64 bd, uint32_t idesc, bool acc) {
    uint32_t en = acc ? 1u : 0u;
    asm volatile(
        "{\n\t.reg .pred p;\n\tsetp.ne.u32 p, %4, 0;\n\t"
        "tcgen05.mma.cta_group::1.kind::f16 [%0], %1, %2, %3, {%5,%5,%5,%5}, p;\n\t}"
        :: "r"(d), "l"(ad), "l"(bd), "r"(idesc), "r"(en), "r"(0u) : "memory");
}
#endif

#define SWZ(b) ((b) ^ (((b) >> 3) & 0x70))
#define TCIDESC 0x08200490u   // dtype=F32, a=BF16, b=BF16, N=128, M=128

// ---------------- fp32 scratch ----------------
static constexpr size_t E_TOKD = (size_t)MP * DIMM;
static constexpr size_t E_TOKH = (size_t)MP * HIDD;
static constexpr size_t E_W    = (size_t)DIMM * HIDD;
static constexpr size_t E_A    = (size_t)DIMM * DIMM;
static constexpr size_t E_QKVW = (size_t)DIMM * 3 * DIMM;

__device__ float g_qkv [(size_t)NTOK * 3 * DIMM];
__device__ float g_kgv [(size_t)2 * NTOK * HIDD];
__device__ float g_h   [(size_t)NTOK * HIDD];
__device__ float g_GV  [2 * E_W];
__device__ float g_P   [E_W];
__device__ float g_grad[3 * E_W];
__device__ float g_X1  [3 * E_W];
__device__ float g_X2  [3 * E_W];
__device__ float g_A   [3 * E_A];
__device__ double g_nrm[3];

// ---------------- bf16 hi/lo pool ----------------
static constexpr size_t O_X     = 0;
static constexpr size_t O_K     = O_X     + E_TOKD * 4;
static constexpr size_t O_KT    = O_K     + E_TOKD * 4;
static constexpr size_t O_Q     = O_KT    + E_TOKD * 4;
static constexpr size_t O_RT    = O_Q     + E_TOKD * 4;
static constexpr size_t O_H     = O_RT    + E_TOKD * 4;
static constexpr size_t O_HT    = O_H     + E_TOKH * 4;
static constexpr size_t O_DKGT  = O_HT    + E_TOKH * 4;
static constexpr size_t O_DKVT  = O_DKGT  + E_TOKH * 4;
static constexpr size_t O_WGT   = O_DKVT  + E_TOKH * 4;
static constexpr size_t O_WVT   = O_WGT   + E_W * 4;
static constexpr size_t O_WP    = O_WVT   + E_W * 4;
static constexpr size_t O_WPT   = O_WP    + E_W * 4;
static constexpr size_t O_QKVW  = O_WPT   + E_W * 4;
static constexpr size_t O_PRJW  = O_QKVW  + E_QKVW * 4;
static constexpr size_t O_NSX   = O_PRJW  + E_A * 4;
static constexpr size_t O_NSXT  = O_NSX   + 3 * E_W * 4;
static constexpr size_t O_NSXT2 = O_NSXT  + 3 * E_W * 4;
static constexpr size_t O_NSA   = O_NSXT2 + 3 * E_W * 4;
static constexpr size_t O_NSA2  = O_NSA   + 3 * E_A * 4;
static constexpr size_t POOL_B  = O_NSA2  + 3 * E_A * 4;
__device__ __align__(1024) unsigned char g_bf[POOL_B];

// ============ tcgen05 split-bf16 GEMM: 128x256 tile, cg1, double-buffered ======
#define TC_STAGE 98304
#define TC_SMEM  (2 * TC_STAGE + 1024)

__global__ void __launch_bounds__(256, 1) tc_gemm(
    const bf16* __restrict__ Ahi, const bf16* __restrict__ Alo,
    const bf16* __restrict__ Bhi, const bf16* __restrict__ Blo,
    int Kp, float* __restrict__ C, int ldc,
    const float* __restrict__ E, int ldE,
    float alpha, float beta, int M,
    i64 az, i64 bz, i64 cz, i64 ez,
    bf16* __restrict__ Ohi, bf16* __restrict__ Olo, int ldo, i64 oz,
    bf16* __restrict__ OThi, bf16* __restrict__ OTlo, int ldot, i64 ozt)
{
#if TC_HAS_TCGEN05
    extern __shared__ unsigned char dsm_raw[];
    __shared__ __align__(8) u64 s_mb[2];
    __shared__ uint32_t s_tmem[1];

    const int tid = threadIdx.x;
    const int wid = tid >> 5;
    const int lane = tid & 31;
    const i64 zz = blockIdx.z;
    Ahi += zz * az; Alo += zz * az;
    Bhi += zz * bz; Blo += zz * bz;
    if (C)    C    += zz * cz;
    if (E)    E    += zz * ez;
    if (Ohi)  { Ohi  += zz * oz;  Olo  += zz * oz; }
    if (OThi) { OThi += zz * ozt; OTlo += zz * ozt; }

    const uint32_t sb  = (smem_u32(dsm_raw) + 1023) & ~1023u;
    const uint32_t mbB = smem_u32(&s_mb[0]);
    unsigned char* tsb = (unsigned char*)(((uintptr_t)dsm_raw + 1023) & ~(uintptr_t)1023);

    if (tid == 0) { MBARRIER_INIT(mbB, 1); MBARRIER_INIT(mbB + 8, 1); }
    if (wid == 0) {
        TCGEN05_ALLOC(smem_u32(s_tmem), 256);
        TCGEN05_RELINQ();
    }
    __syncthreads();
    const uint32_t tmem = s_tmem[0];

    const int m0 = blockIdx.y * 128;
    const int n0 = blockIdx.x * 256;

    const int r0    = tid >> 3;
    const int col16 = (tid & 7) * 16;
    const size_t rowB = (size_t)Kp * 2;
    const char* pAhi = (const char*)Ahi + (size_t)(m0 + r0) * rowB + col16;
    const char* pAlo = (const char*)Alo + (size_t)(m0 + r0) * rowB + col16;
    const char* pBhi = (const char*)Bhi + (size_t)(n0 + r0) * rowB + col16;
    const char* pBlo = (const char*)Blo + (size_t)(n0 + r0) * rowB + col16;
    uint32_t swA[4], swB[8];
#pragma unroll
    for (int k = 0; k < 4; ++k) swA[k] = SWZ((uint32_t)(r0 + 32 * k) * 128 + col16);
#pragma unroll
    for (int k = 0; k < 8; ++k) swB[k] = SWZ((uint32_t)(r0 + 32 * k) * 128 + col16);

    uint4 va[8], vb[16];
#define TCFETCH(cc) do { const size_t gb_ = (size_t)(cc) * 128;                         \
    _Pragma("unroll") for (int k_ = 0; k_ < 4; ++k_) {                                  \
        va[k_]     = *reinterpret_cast<const uint4*>(pAhi + (size_t)(32 * k_) * rowB + gb_); \
        va[4 + k_] = *reinterpret_cast<const uint4*>(pAlo + (size_t)(32 * k_) * rowB + gb_); \
    }                                                                                   \
    _Pragma("unroll") for (int k_ = 0; k_ < 8; ++k_) {                                  \
        vb[k_]     = *reinterpret_cast<const uint4*>(pBhi + (size_t)(32 * k_) * rowB + gb_); \
        vb[8 + k_] = *reinterpret_cast<const uint4*>(pBlo + (size_t)(32 * k_) * rowB + gb_); \
    } } while (0)

    const int NC = Kp >> 6;
    TCFETCH(0);
    for (int c = 0; c < NC; ++c) {
        const int s = c & 1;
        const int phase = c >> 1;
        const uint32_t mbs = mbB + (uint32_t)s * 8;
        const uint32_t stg = sb + (uint32_t)s * TC_STAGE;
        if (c >= 2) { MBARRIER_WAIT_PARITY(mbs, (phase - 1) & 1); }
#pragma unroll
        for (int k = 0; k < 4; ++k) {
            STS128(va[k].x, va[k].y, va[k].z, va[k].w, stg + swA[k]);
            STS128(va[4 + k].x, va[4 + k].y, va[4 + k].z, va[4 + k].w, stg + 16384u + swA[k]);
        }
#pragma unroll
        for (int k = 0; k < 8; ++k) {
            STS128(vb[k].x, vb[k].y, vb[k].z, vb[k].w, stg + 32768u + swB[k]);
            STS128(vb[8 + k].x, vb[8 + k].y, vb[8 + k].z, vb[8 + k].w, stg + 65536u + swB[k]);
        }
        if (c + 1 < NC) { TCFETCH(c + 1); }
        FENCE_ASYNC();
        __syncthreads();
        if (wid == 0 && elect1()) {
            u64 aH = mkdesc(stg);
            u64 aL = mkdesc(stg + 16384);
#pragma unroll
            for (int nh = 0; nh < 2; ++nh) {
                const uint32_t d = tmem + (uint32_t)nh * 128;
                u64 bH = mkdesc(stg + 32768 + (uint32_t)nh * 16384);
                u64 bL = mkdesc(stg + 65536 + (uint32_t)nh * 16384);
#pragma unroll
                for (int ks = 0; ks < 4; ++ks)
                    mma_f16_ss(d, aH + ks * 2, bH + ks * 2, TCIDESC, !(c == 0 && ks == 0));
#pragma unroll
                for (int ks = 0; ks < 4; ++ks)
                    mma_f16_ss(d, aH + ks * 2, bL + ks * 2, TCIDESC, true);
#pragma unroll
                for (int ks = 0; ks < 4; ++ks)
                    mma_f16_ss(d, aL + ks * 2, bH + ks * 2, TCIDESC, true);
            }
            TCGEN05_COMMIT(mbs);
        }
    }
    {
        const int cl = NC - 1;
        MBARRIER_WAIT_PARITY(mbB + (uint32_t)(cl & 1) * 8, (cl >> 1) & 1);
    }
    TCGEN05_FENCE_AFTER();

    const bool hasT = (OThi != nullptr);
    const int sub = wid & 3;
    const int colh = (wid >> 2) * 128;
    const int mloc = sub * 32 + lane;
    const int m = m0 + mloc;
#pragma unroll
    for (int qq = 0; qq < 4; ++qq) {
        uint32_t r32[32];
        TCGEN05_LD_X32(r32, tmem + colh + qq * 32);
        TCGEN05_WAIT_LD();
        const int ncol = n0 + colh + qq * 32;
        float o[32];
        if (m < M) {
            if (beta != 0.f) {
                const float* erow = E + (size_t)m * ldE + ncol;
#pragma unroll
                for (int j = 0; j < 32; j += 4) {
                    float4 e = *reinterpret_cast<const float4*>(erow + j);
                    o[j]     = alpha * __uint_as_float(r32[j])     + beta * e.x;
                    o[j + 1] = alpha * __uint_as_float(r32[j + 1]) + beta * e.y;
                    o[j + 2] = alpha * __uint_as_float(r32[j + 2]) + beta * e.z;
                    o[j + 3] = alpha * __uint_as_float(r32[j + 3]) + beta * e.w;
                }
            } else {
#pragma unroll
                for (int j = 0; j < 32; ++j) o[j] = alpha * __uint_as_float(r32[j]);
            }
        } else {
#pragma unroll
            for (int j = 0; j < 32; ++j) o[j] = 0.f;
        }
        if (m < M && C) {
            float* crow = C + (size_t)m * ldc + ncol;
#pragma unroll
            for (int j = 0; j < 32; j += 4)
                *reinterpret_cast<float4*>(crow + j) = make_float4(o[j], o[j+1], o[j+2], o[j+3]);
        }
        if (m < M && Ohi) {
            bf16* hrow = Ohi + (size_t)m * ldo + ncol;
            bf16* lrow = Olo + (size_t)m * ldo + ncol;
#pragma unroll
            for (int j = 0; j < 32; j += 4) {
                __align__(8) bf16 hv[4];
                __align__(8) bf16 lv[4];
#pragma unroll
                for (int t = 0; t < 4; ++t) {
                    bf16 hb_ = __float2bfloat16(o[j + t]);
                    hv[t] = hb_;
                    lv[t] = __float2bfloat16(o[j + t] - __bfloat162float(hb_));
                }
                *reinterpret_cast<uint2*>(hrow + j) = *reinterpret_cast<const uint2*>(hv);
                *reinterpret_cast<uint2*>(lrow + j) = *reinterpret_cast<const uint2*>(lv);
            }
        }
        if (hasT) {
            // stage transposed bf16 hi/lo tiles: T[c][mloc], 256 rows x 128 cols
            bf16* th = (bf16*)tsb;
            bf16* tl = (bf16*)(tsb + 65536);
#pragma unroll
            for (int j = 0; j < 32; ++j) {
                const int cidx = colh + qq * 32 + j;
                bf16 hb_ = __float2bfloat16(o[j]);
                th[(size_t)cidx * 128 + mloc] = hb_;
                tl[(size_t)cidx * 128 + mloc] = __float2bfloat16(o[j] - __bfloat162float(hb_));
            }
        }
    }
    if (hasT) {
        __syncthreads();
        // each smem row is 128 bf16 = 256B -> 16 chunks of 16B
        const int chunk = tid & 15;       // 16B chunk within 256B row
        const int rbase = tid >> 4;       // 0..15
#pragma unroll
        for (int p = 0; p < 16; ++p) {
            const int cidx = p * 16 + rbase;
            uint4 vh = *reinterpret_cast<const uint4*>(tsb + (size_t)cidx * 256 + chunk * 16);
            uint4 vl = *reinterpret_cast<const uint4*>(tsb + 65536 + (size_t)cidx * 256 + chunk * 16);
            *reinterpret_cast<uint4*>(OThi + (size_t)(n0 + cidx) * ldot + m0 + chunk * 8) = vh;
            *reinterpret_cast<uint4*>(OTlo + (size_t)(n0 + cidx) * ldot + m0 + chunk * 8) = vl;
        }
    }
    __syncthreads();
    if (wid == 0) TCGEN05_DEALLOC(tmem, 256);
#undef TCFETCH
#endif
}

// ================= conversion kernels (z-batched) =================
__global__ void conv_k(const float* __restrict__ src, int ld, int R, int C,
                       bf16* __restrict__ hi, bf16* __restrict__ lo, int Cp,
                       i64 srcZ, i64 dstZ)
{
    const i64 z = blockIdx.z;
    src += z * srcZ; hi += z * dstZ; lo += z * dstZ;
    int c = (blockIdx.x * blockDim.x + threadIdx.x) * 4;
    int r = blockIdx.y;
    if (c >= Cp) return;
    __align__(8) bf16 h4[4];
    __align__(8) bf16 l4[4];
    if (r < R && c < C) {
        float4 fv = *reinterpret_cast<const float4*>(src + (size_t)r * ld + c);
        float vv[4] = {fv.x, fv.y, fv.z, fv.w};
#pragma unroll
        for (int j = 0; j < 4; j++) {
            bf16 h = __float2bfloat16(vv[j]);
            h4[j] = h;
            l4[j] = __float2bfloat16(vv[j] - __bfloat162float(h));
        }
    } else {
#pragma unroll
        for (int j = 0; j < 4; j++) { h4[j] = __float2bfloat16(0.f); l4[j] = h4[j]; }
    }
    size_t o = (size_t)r * Cp + c;
    *reinterpret_cast<uint2*>(hi + o) = *reinterpret_cast<const uint2*>(h4);
    *reinterpret_cast<uint2*>(lo + o) = *reinterpret_cast<const uint2*>(l4);
}

__global__ void convT_k(const float* __restrict__ src, int ld, int R, int C,
                        bf16* __restrict__ hi, bf16* __restrict__ lo, int Rp,
                        i64 srcZ, i64 dstZ)
{
    __shared__ float t[32][33];
    const i64 z = blockIdx.z;
    src += z * srcZ; hi += z * dstZ; lo += z * dstZ;
    int c0 = blockIdx.x * 32;
    int r0 = blockIdx.y * 32;
    int tx = threadIdx.x, ty = threadIdx.y;
#pragma unroll
    for (int j = 0; j < 32; j += 8) {
        int r = r0 + ty + j;
        t[ty + j][tx] = (r < R) ? src[(size_t)r * ld + c0 + tx] : 0.f;
    }
    __syncthreads();
#pragma unroll
    for (int j = 0; j < 32; j += 8) {
        float fv = t[tx][ty + j];
        size_t o = (size_t)(c0 + ty + j) * Rp + r0 + tx;
        bf16 h = __float2bfloat16(fv);
        hi[o] = h;
        lo[o] = __float2bfloat16(fv - __bfloat162float(h));
    }
}

// ================= fused activation + transpose kernels =================
__global__ void swishT_k(const float* __restrict__ kg, const float* __restrict__ kv,
                         bf16* __restrict__ hhi, bf16* __restrict__ hlo,
                         bf16* __restrict__ thi, bf16* __restrict__ tlo)
{
    __shared__ float t[32][33];
    int c0 = blockIdx.x * 32;
    int r0 = blockIdx.y * 32;
    int tx = threadIdx.x, ty = threadIdx.y;
#pragma unroll
    for (int j = 0; j < 32; j += 8) {
        int r = r0 + ty + j;
        float hv = 0.f;
        if (r < NTOK) {
            size_t idx = (size_t)r * HIDD + c0 + tx;
            float g = kg[idx], u = kv[idx];
            hv = g / (1.f + __expf(-g)) * u;
        }
        t[ty + j][tx] = hv;
        size_t o = (size_t)r * HIDD + c0 + tx;
        bf16 hb_ = __float2bfloat16(hv);
        hhi[o] = hb_;
        hlo[o] = __float2bfloat16(hv - __bfloat162float(hb_));
    }
    if (thi) {
        __syncthreads();
#pragma unroll
        for (int j = 0; j < 32; j += 8) {
            float fv = t[tx][ty + j];
            size_t o = (size_t)(c0 + ty + j) * MP + r0 + tx;
            bf16 hb_ = __float2bfloat16(fv);
            thi[o] = hb_;
            tlo[o] = __float2bfloat16(fv - __bfloat162float(hb_));
        }
    }
}

__global__ void bw_ewT_k(const float* __restrict__ dh,
                         const float* __restrict__ kg, const float* __restrict__ kv,
                         bf16* __restrict__ gthi, bf16* __restrict__ gtlo,
                         bf16* __restrict__ vthi, bf16* __restrict__ vtlo)
{
    __shared__ float tg[32][33];
    __shared__ float tv[32][33];
    int c0 = blockIdx.x * 32;
    int r0 = blockIdx.y * 32;
    int tx = threadIdx.x, ty = threadIdx.y;
#pragma unroll
    for (int j = 0; j < 32; j += 8) {
        int r = r0 + ty + j;
        float dkg = 0.f, dkv = 0.f;
        if (r < NTOK) {
            size_t idx = (size_t)r * HIDD + c0 + tx;
            float d = dh[idx], g = kg[idx], u = kv[idx];
            float s = 1.f / (1.f + __expf(-g));
            dkv = d * g * s;
            dkg = d * u * s * (1.f + g * (1.f - s));
        }
        tg[ty + j][tx] = dkg;
        tv[ty + j][tx] = dkv;
    }
    __syncthreads();
#pragma unroll
    for (int j = 0; j < 32; j += 8) {
        size_t o = (size_t)(c0 + ty + j) * MP + r0 + tx;
        float fg = tg[tx][ty + j];
        float fv = tv[tx][ty + j];
        bf16 hg = __float2bfloat16(fg);
        gthi[o] = hg;
        gtlo[o] = __float2bfloat16(fg - __bfloat162float(hg));
        bf16 hv = __float2bfloat16(fv);
        vthi[o] = hv;
        vtlo[o] = __float2bfloat16(fv - __bfloat162float(hv));
    }
}

// ================= elementwise / reductions =================
__global__ void norm_heads_k(float* __restrict__ base,
                             const float* __restrict__ sc, const float* __restrict__ bi)
{
    int w = (blockIdx.x * blockDim.x + threadIdx.x) >> 5;
    int lane = threadIdx.x & 31;
    if (w >= NTOK * 16) return;
    int rowi = w >> 4, head = w & 15;
    float* p = base + (size_t)rowi * (3 * DIMM) + head * 64;
    float x0 = p[lane], x1 = p[lane + 32];
    float ss = x0 * x0 + x1 * x1;
#pragma unroll
    for (int o = 16; o; o >>= 1) ss += __shfl_xor_sync(0xffffffffu, ss, o);
    float inv = 1.f / (sqrtf(ss) + 1e-6f);
    p[lane]      = x0 * inv * sc[lane]      + bi[lane];
    p[lane + 32] = x1 * inv * sc[lane + 32] + bi[lane + 32];
}

__global__ void zero3_k(double* p) { if (threadIdx.x < 3) p[threadIdx.x] = 0.0; }

__global__ void sumsq3_k(const float* __restrict__ x, int n, double* __restrict__ out)
{
    __shared__ double sm[256];
    const int z = blockIdx.y;
    x += (size_t)z * n;
    double a = 0.0;
    for (int i = blockIdx.x * blockDim.x + threadIdx.x; i < n; i += gridDim.x * blockDim.x) {
        float fv = x[i];
        a += (double)fv * (double)fv;
    }
    sm[threadIdx.x] = a;
    __syncthreads();
    for (int s = 128; s; s >>= 1) {
        if (threadIdx.x < s) sm[threadIdx.x] += sm[threadIdx.x + s];
        __syncthreads();
    }
    if (threadIdx.x == 0) atomicAdd(&out[z], sm[0]);
}

__global__ void scale3_k(const float4* __restrict__ g, float4* __restrict__ X, int n4,
                         const double* __restrict__ nrm)
{
    const int z = blockIdx.y;
    int i = blockIdx.x * blockDim.x + threadIdx.x;
    if (i >= n4) return;
    float inv = (float)(1.0 / (sqrt(nrm[z]) + 1e-7));
    float4 fv = g[(size_t)z * n4 + i];
    fv.x *= inv; fv.y *= inv; fv.z *= inv; fv.w *= inv;
    X[(size_t)z * n4 + i] = fv;
}

__global__ void transpose_k(const float* __restrict__ src, float* __restrict__ dst,
                            int R, int C)
{
    __shared__ float t[32][33];
    int c0 = blockIdx.x * 32, r0 = blockIdx.y * 32;
    int x = c0 + threadIdx.x;
#pragma unroll
    for (int j = 0; j < 32; j += 8)
        t[threadIdx.y + j][threadIdx.x] = src[(size_t)(r0 + threadIdx.y + j) * C + x];
    __syncthreads();
    int x2 = r0 + threadIdx.x;
#pragma unroll
    for (int j = 0; j < 32; j += 8)
        dst[(size_t)(c0 + threadIdx.y + j) * R + x2] = t[threadIdx.x][threadIdx.y + j];
}

__global__ void upd_k(float4* __restrict__ p, const float4* __restrict__ x, int n4)
{
    int i = blockIdx.x * blockDim.x + threadIdx.x;
    if (i >= n4) return;
    float4 a = p[i], bb = x[i];
    a.x -= LRATE * bb.x; a.y -= LRATE * bb.y; a.z -= LRATE * bb.z; a.w -= LRATE * bb.w;
    p[i] = a;
}

// ================= host orchestration =================
struct BP { bf16 *hi, *lo; };

static void* symaddr(const void* s) { void* p = nullptr; cudaGetSymbolAddress(&p, s); return p; }

static void tc(BP A, BP B, int Kp, float* C, int ldc, int M, int N,
               float alpha, float beta, const float* E, int ldE,
               int nz = 1, i64 az = 0, i64 bz = 0, i64 cz = 0, i64 ez = 0,
               BP O = {nullptr, nullptr}, int ldo = 0, i64 oz = 0,
               BP OT = {nullptr, nullptr}, int ldot = 0, i64 ozt = 0)
{
    dim3 gr(N / 256, (M + 127) / 128, nz);
    tc_gemm<<<gr, 256, TC_SMEM>>>(A.hi, A.lo, B.hi, B.lo, Kp, C, ldc, E, ldE,
                                  alpha, beta, M, az, bz, cz, ez, O.hi, O.lo, ldo, oz,
                                  OT.hi, OT.lo, ldot, ozt);
}

static void conv(const float* s, int ld, int R, int C, BP d, int Rp, int Cp,
                 int nz = 1, i64 sZ = 0, i64 dZ = 0)
{
    dim3 gr((Cp / 4 + 255) / 256, Rp, nz);
    conv_k<<<gr, 256>>>(s, ld, R, C, d.hi, d.lo, Cp, sZ, dZ);
}

static void convT(const float* s, int ld, int R, int C, BP d, int Rp,
                  int nz = 1, i64 sZ = 0, i64 dZ = 0)
{
    dim3 gr(C / 32, Rp / 32, nz);
    convT_k<<<gr, dim3(32, 8)>>>(s, ld, R, C, d.hi, d.lo, Rp, sZ, dZ);
}

extern "C" void kernel_launch(void* const* d_in, const int* in_sizes, int n_in,
                              void* d_out, int out_size)
{
    const float* x        = (const float*)d_in[0];
    const float* qkv_w    = (const float*)d_in[1];
    const float* qkv_b    = (const float*)d_in[2];
    const float* qn_s     = (const float*)d_in[3];
    const float* qn_b     = (const float*)d_in[4];
    const float* kn_s     = (const float*)d_in[5];
    const float* kn_b     = (const float*)d_in[6];
    const float* ttt_gate = (const float*)d_in[7];
    const float* ttt_val  = (const float*)d_in[8];
    const float* ttt_proj = (const float*)d_in[9];
    const float* proj_w   = (const float*)d_in[10];
    const float* proj_b   = (const float*)d_in[11];
    float* out = (float*)d_out;

    cudaFuncSetAttribute(tc_gemm, cudaFuncAttributeMaxDynamicSharedMemorySize, TC_SMEM);

    float* qkv  = (float*)symaddr(g_qkv);
    float* kgv  = (float*)symaddr(g_kgv);
    float* h    = (float*)symaddr(g_h);
    float* GV   = (float*)symaddr(g_GV);
    float* P    = (float*)symaddr(g_P);
    float* grad = (float*)symaddr(g_grad);
    float* X1   = (float*)symaddr(g_X1);
    float* X2   = (float*)symaddr(g_X2);
    float* Amat = (float*)symaddr(g_A);
    double* nrm = (double*)symaddr(g_nrm);
    unsigned char* pool = (unsigned char*)symaddr(g_bf);

    auto bp = [&](size_t off, size_t elems) { BP b; b.hi = (bf16*)(pool + off); b.lo = b.hi + elems; return b; };

    BP xb    = bp(O_X, E_TOKD);
    BP kb    = bp(O_K, E_TOKD);
    BP kTb   = bp(O_KT, E_TOKD);
    BP qb    = bp(O_Q, E_TOKD);
    BP rTb   = bp(O_RT, E_TOKD);
    BP hb    = bp(O_H, E_TOKH);
    BP hTb   = bp(O_HT, E_TOKH);
    BP dkgT  = bp(O_DKGT, E_TOKH);
    BP dkvT  = bp(O_DKVT, E_TOKH);
    BP wGt   = bp(O_WGT, E_W);
    BP wP    = bp(O_WP,  E_W);
    BP wPt   = bp(O_WPT, E_W);
    BP qkvwT = bp(O_QKVW, E_QKVW);
    BP projwT = bp(O_PRJW, E_A);
    BP nsX   = bp(O_NSX,  E_W);
    BP nsXTa = bp(O_NSXT, E_W);
    BP nsXTb = bp(O_NSXT2, E_W);
    BP nsA   = bp(O_NSA,  E_A);
    BP nsA2  = bp(O_NSA2, E_A);
    BP NOB   = {nullptr, nullptr};

    const size_t TB = sizeof(float) * E_W;
    cudaMemcpyAsync(GV,       ttt_gate, TB, cudaMemcpyDeviceToDevice, 0);
    cudaMemcpyAsync(GV + E_W, ttt_val,  TB, cudaMemcpyDeviceToDevice, 0);
    cudaMemcpyAsync(P,        ttt_proj, TB, cudaMemcpyDeviceToDevice, 0);

    // ---- qkv = x @ qkv_w + b ----
    conv (x, DIMM, NTOK, DIMM, xb, MP, DIMM);
    convT(qkv_w, 3 * DIMM, DIMM, 3 * DIMM, qkvwT, DIMM);
    tc(xb, qkvwT, DIMM, qkv, 3 * DIMM, NTOK, 3 * DIMM, 1.f, 1.f, qkv_b, 0);

    {
        int nb = (NTOK * 16 * 32 + 255) / 256;
        norm_heads_k<<<nb, 256>>>(qkv, qn_s, qn_b);
        norm_heads_k<<<nb, 256>>>(qkv + DIMM, kn_s, kn_b);
    }

    const float* kmat = qkv + DIMM;
    const float* vmat = qkv + 2 * DIMM;
    conv (kmat, 3 * DIMM, NTOK, DIMM, kb, MP, DIMM);
    convT(kmat, 3 * DIMM, NTOK, DIMM, kTb, MP);
    conv (qkv, 3 * DIMM, NTOK, DIMM, qb, MP, DIMM);

    const dim3 grTH(HIDD / 32, MP / 32);
    const i64 ZW = 2 * (i64)E_W;
    const i64 ZA = 2 * (i64)E_A;
    const i64 KGV = (i64)NTOK * HIDD;

    for (int step = 0; step < 2; ++step) {
        convT(GV, HIDD, DIMM, HIDD, wGt, DIMM, 2, (i64)E_W, ZW);
        conv (P, DIMM, HIDD, DIMM, wP, HIDD, DIMM);
        convT(P, DIMM, HIDD, DIMM, wPt, HIDD);

        // kg|kv = k @ {G,V}
        tc(kb, wGt, DIMM, kgv, HIDD, NTOK, HIDD, 1.f, 0.f, nullptr, 0,
           2, 0, ZW, KGV, 0);
        swishT_k<<<grTH, dim3(32, 8)>>>(kgv, kgv + KGV, hb.hi, hb.lo, hTb.hi, hTb.lo);
        // r = h @ P - v : pairs (xb) + transposed pairs (rTb), no fp32 C
        tc(hb, wPt, HIDD, nullptr, 0, NTOK, DIMM, 1.f, -1.f, vmat, 3 * DIMM,
           1, 0, 0, 0, 0, xb, DIMM, 0, rTb, MP, 0);
        // gP^T = r^T @ h
        tc(rTb, hTb, MP, grad + 2 * E_W, HIDD, DIMM, HIDD, 1.f, 0.f, nullptr, 0);
        // dh = r @ P^T  -> h buffer
        tc(xb, wP, DIMM, h, HIDD, NTOK, HIDD, 1.f, 0.f, nullptr, 0);
        bw_ewT_k<<<grTH, dim3(32, 8)>>>(h, kgv, kgv + KGV,
                                        dkgT.hi, dkgT.lo, dkvT.hi, dkvT.lo);
        // gG|gV = k^T @ {dkg,dkv}
        tc(kTb, dkgT, MP, grad, HIDD, DIMM, HIDD, 1.f, 0.f, nullptr, 0,
           2, 0, 2 * (i64)E_TOKH, (i64)E_W, 0);

        // ---- batched Newton-Schulz over {gG, gV, gP^T} ----
        zero3_k<<<1, 4>>>(nrm);
        sumsq3_k<<<dim3(256, 3), 256>>>(grad, (int)E_W, nrm);
        scale3_k<<<dim3(((int)E_W / 4 + 255) / 256, 3), 256>>>(
            (const float4*)grad, (float4*)X1, (int)E_W / 4, nrm);
        float* X = X1;
        float* Y = X2;
        conv (X, HIDD, DIMM, HIDD, nsX, DIMM, HIDD, 3, (i64)E_W, ZW);
        convT(X, HIDD, DIMM, HIDD, nsXTa, DIMM, 3, (i64)E_W, ZW);
        for (int it = 0; it < 5; ++it) {
            // ping-pong transposed-X buffers: read XTin, write XTout (NO aliasing)
            BP XTin  = (it & 1) ? nsXTb : nsXTa;
            BP XTout = (it & 1) ? nsXTa : nsXTb;
            tc(nsX, nsX, HIDD, Amat, DIMM, DIMM, DIMM, 1.f, 0.f, nullptr, 0,
               3, ZW, ZW, (i64)E_A, 0, nsA, DIMM, ZA);
            tc(nsA, nsA, DIMM, nullptr, 0, DIMM, DIMM, NS_C, NS_B, Amat, DIMM,
               3, ZA, ZA, 0, (i64)E_A, nsA2, DIMM, ZA);
            // Y = A2 @ X + a*X : fp32 Y + nsX pairs + XTout transposed pairs (fused)
            tc(nsA2, XTin, DIMM, Y, HIDD, DIMM, HIDD, 1.f, NS_A, X, HIDD,
               3, ZA, ZW, (i64)E_W, (i64)E_W, nsX, HIDD, ZW,
               (it < 4) ? XTout : NOB, DIMM, ZW);
            float* t = X; X = Y; Y = t;
        }
        upd_k<<<((int)(2 * E_W / 4) + 255) / 256, 256>>>((float4*)GV, (const float4*)X, (int)(2 * E_W / 4));
        {
            dim3 gr(HIDD / 32, DIMM / 32);
            transpose_k<<<gr, dim3(32, 8)>>>(X + 2 * E_W, Y, DIMM, HIDD);
            upd_k<<<((int)(E_W / 4) + 255) / 256, 256>>>((float4*)P, (const float4*)Y, (int)(E_W / 4));
        }
    }

    // ---- final forward with q ----
    convT(GV, HIDD, DIMM, HIDD, wGt, DIMM, 2, (i64)E_W, ZW);
    convT(P, DIMM, HIDD, DIMM, wPt, HIDD);
    tc(qb, wGt, DIMM, kgv, HIDD, NTOK, HIDD, 1.f, 0.f, nullptr, 0,
       2, 0, ZW, KGV, 0);
    swishT_k<<<grTH, dim3(32, 8)>>>(kgv, kgv + KGV, hb.hi, hb.lo, nullptr, nullptr);
    tc(hb, wPt, HIDD, nullptr, 0, NTOK, DIMM, 1.f, 0.f, nullptr, 0,
       1, 0, 0, 0, 0, xb, DIMM, 0);
    convT(proj_w, DIMM, DIMM, DIMM, projwT, DIMM);
    tc(xb, projwT, DIMM, out, DIMM, NTOK, DIMM, 1.f, 1.f, proj_b, 0);
}

// round 13
// speedup vs baseline: 7.7038x; 1.0295x over previous
#include <cuda_runtime.h>
#include <cuda_bf16.h>
#include <cstdint>
#include <cstddef>

// ---------------- problem constants ----------------
#define NTOK 10992
#define MP   11008
#define DIMM 1024
#define HIDD 4096
#define LRATE 0.1f
#define NS_A 3.4445f
#define NS_B (-4.7750f)
#define NS_C 2.0315f

typedef unsigned long long u64;
typedef long long i64;
typedef __nv_bfloat16 bf16;

#if !defined(__CUDA_ARCH__) || defined(__CUDA_ARCH_FEAT_SM103_ALL)
#define TC_HAS_TCGEN05 1
#else
#define TC_HAS_TCGEN05 0
#endif

// ================= PTX helpers (sm_103a) =================
#if TC_HAS_TCGEN05
__device__ __forceinline__ uint32_t smem_u32(const void* p) {
    uint32_t a;
    asm("{ .reg .u64 t; cvta.to.shared.u64 t, %1; cvt.u32.u64 %0, t; }" : "=r"(a) : "l"(p));
    return a;
}
__device__ __forceinline__ uint32_t elect1() {
    uint32_t p;
    asm volatile("{\n.reg .pred p;\nelect.sync _|p, 0xFFFFFFFF;\nselp.b32 %0,1,0,p;\n}" : "=r"(p));
    return p;
}
#define MBARRIER_INIT(a, c) \
    asm volatile("mbarrier.init.shared.b64 [%0], %1;" :: "r"((uint32_t)(a)), "r"((uint32_t)(c)) : "memory")
#define MBARRIER_WAIT_PARITY(a, ph) do { \
    uint32_t _m = (uint32_t)(a); uint32_t _p = (uint32_t)(ph); uint32_t _d; \
    asm volatile("{\n.reg .pred p;\nmbarrier.try_wait.parity.acquire.cta.shared::cta.b64 p, [%1], %2;\nselp.b32 %0,1,0,p;\n}" \
        : "=r"(_d) : "r"(_m), "r"(_p) : "memory"); \
    if (!_d) { \
        asm volatile("{\n.reg .pred P1;\nWL_%=:\nmbarrier.try_wait.parity.acquire.cta.shared::cta.b64 P1, [%0], %1, 0x989680;\n@P1 bra.uni WD_%=;\nbra.uni WL_%=;\nWD_%=:\n}" \
            :: "r"(_m), "r"(_p) : "memory"); \
    } } while (0)
#define TCGEN05_ALLOC(sa, n) \
    asm volatile("tcgen05.alloc.cta_group::1.sync.aligned.shared::cta.b32 [%0], %1;" \
        :: "r"((uint32_t)(sa)), "r"((uint32_t)(n)) : "memory")
#define TCGEN05_RELINQ() \
    asm volatile("tcgen05.relinquish_alloc_permit.cta_group::1.sync.aligned;")
#define TCGEN05_DEALLOC(t, n) \
    asm volatile("tcgen05.dealloc.cta_group::1.sync.aligned.b32 %0, %1;" :: "r"(t), "r"((uint32_t)(n)))
#define TCGEN05_COMMIT(a) \
    asm volatile("tcgen05.commit.cta_group::1.mbarrier::arrive::one.shared::cluster.b64 [%0];" \
        :: "r"((uint32_t)(a)) : "memory")
#define TCGEN05_FENCE_AFTER() asm volatile("tcgen05.fence::after_thread_sync;" ::: "memory")
#define TCGEN05_WAIT_LD() asm volatile("tcgen05.wait::ld.sync.aligned;" ::: "memory")
#define FENCE_ASYNC() asm volatile("fence.proxy.async.shared::cta;" ::: "memory")
#define STS128(r0, r1, r2, r3, a) \
    asm volatile("st.shared.v4.b32 [%0], {%1,%2,%3,%4};" :: "r"(a), "r"(r0), "r"(r1), "r"(r2), "r"(r3) : "memory")
#define TCGEN05_LD_X32(r, ta) \
    asm volatile("tcgen05.ld.sync.aligned.32x32b.x32.b32 " \
        "{%0,%1,%2,%3,%4,%5,%6,%7,%8,%9,%10,%11,%12,%13,%14,%15," \
        "%16,%17,%18,%19,%20,%21,%22,%23,%24,%25,%26,%27,%28,%29,%30,%31}, [%32];" \
        : "=r"((r)[0]), "=r"((r)[1]), "=r"((r)[2]), "=r"((r)[3]), "=r"((r)[4]), "=r"((r)[5]), \
          "=r"((r)[6]), "=r"((r)[7]), "=r"((r)[8]), "=r"((r)[9]), "=r"((r)[10]), "=r"((r)[11]), \
          "=r"((r)[12]), "=r"((r)[13]), "=r"((r)[14]), "=r"((r)[15]), "=r"((r)[16]), "=r"((r)[17]), \
          "=r"((r)[18]), "=r"((r)[19]), "=r"((r)[20]), "=r"((r)[21]), "=r"((r)[22]), "=r"((r)[23]), \
          "=r"((r)[24]), "=r"((r)[25]), "=r"((r)[26]), "=r"((r)[27]), "=r"((r)[28]), "=r"((r)[29]), \
          "=r"((r)[30]), "=r"((r)[31]) : "r"(ta))

static constexpr u64 SMEM_DESC_BASE =
    (u64(2) << 61) | (u64(1) << 46) | (u64(64) << 32) | (u64(1) << 16);
__device__ __forceinline__ u64 mkdesc(uint32_t sa) {
    return SMEM_DESC_BASE | ((u64)(sa >> 4) & 0x3FFF);
}
__device__ __forceinline__ void mma_f16_ss(uint32_t d, u64 ad, u64 bd, uint32_t idesc, bool acc) {
    uint32_t en = acc ? 1u : 0u;
    asm volatile(
        "{\n\t.reg .pred p;\n\tsetp.ne.u32 p, %4, 0;\n\t"
        "tcgen05.mma.cta_group::1.kind::f16 [%0], %1, %2, %3, {%5,%5,%5,%5}, p;\n\t}"
        :: "r"(d), "l"(ad), "l"(bd), "r"(idesc), "r"(en), "r"(0u) : "memory");
}
#endif

#define SWZ(b) ((b) ^ (((b) >> 3) & 0x70))
#define TCIDESC 0x08200490u   // dtype=F32, a=BF16, b=BF16, N=128, M=128

// ---------------- fp32 scratch ----------------
static constexpr size_t E_TOKD = (size_t)MP * DIMM;
static constexpr size_t E_TOKH = (size_t)MP * HIDD;
static constexpr size_t E_W    = (size_t)DIMM * HIDD;
static constexpr size_t E_A    = (size_t)DIMM * DIMM;
static constexpr size_t E_QKVW = (size_t)DIMM * 3 * DIMM;

__device__ float g_qkv [(size_t)NTOK * 3 * DIMM];
__device__ float g_kgv [(size_t)2 * NTOK * HIDD];
__device__ float g_h   [(size_t)NTOK * HIDD];
__device__ float g_GV  [2 * E_W];
__device__ float g_P   [E_W];
__device__ float g_grad[3 * E_W];
__device__ float g_X1  [3 * E_W];
__device__ float g_X2  [3 * E_W];
__device__ float g_A   [3 * E_A];
__device__ double g_nrm[3];

// ---------------- bf16 hi/lo pool ----------------
static constexpr size_t O_X     = 0;
static constexpr size_t O_K     = O_X     + E_TOKD * 4;
static constexpr size_t O_KT    = O_K     + E_TOKD * 4;
static constexpr size_t O_Q     = O_KT    + E_TOKD * 4;
static constexpr size_t O_RT    = O_Q     + E_TOKD * 4;
static constexpr size_t O_H     = O_RT    + E_TOKD * 4;
static constexpr size_t O_HT    = O_H     + E_TOKH * 4;
static constexpr size_t O_DKGT  = O_HT    + E_TOKH * 4;
static constexpr size_t O_DKVT  = O_DKGT  + E_TOKH * 4;
static constexpr size_t O_WGT   = O_DKVT  + E_TOKH * 4;
static constexpr size_t O_WVT   = O_WGT   + E_W * 4;
static constexpr size_t O_WP    = O_WVT   + E_W * 4;
static constexpr size_t O_WPT   = O_WP    + E_W * 4;
static constexpr size_t O_QKVW  = O_WPT   + E_W * 4;
static constexpr size_t O_PRJW  = O_QKVW  + E_QKVW * 4;
static constexpr size_t O_NSX   = O_PRJW  + E_A * 4;
static constexpr size_t O_NSXT  = O_NSX   + 3 * E_W * 4;
static constexpr size_t O_NSXT2 = O_NSXT  + 3 * E_W * 4;
static constexpr size_t O_NSA   = O_NSXT2 + 3 * E_W * 4;
static constexpr size_t O_NSA2  = O_NSA   + 3 * E_A * 4;
static constexpr size_t POOL_B  = O_NSA2  + 3 * E_A * 4;
__device__ __align__(1024) unsigned char g_bf[POOL_B];

// ============ tcgen05 split-bf16 GEMM: 128x256 tile, cg1, double-buffered ======
#define TC_STAGE 98304
#define TC_SMEM  (2 * TC_STAGE + 1024)

__global__ void __launch_bounds__(256, 1) tc_gemm(
    const bf16* __restrict__ Ahi, const bf16* __restrict__ Alo,
    const bf16* __restrict__ Bhi, const bf16* __restrict__ Blo,
    int Kp, float* __restrict__ C, int ldc,
    const float* __restrict__ E, int ldE,
    float alpha, float beta, int M,
    i64 az, i64 bz, i64 cz, i64 ez,
    bf16* __restrict__ Ohi, bf16* __restrict__ Olo, int ldo, i64 oz,
    bf16* __restrict__ OThi, bf16* __restrict__ OTlo, int ldot, i64 ozt)
{
#if TC_HAS_TCGEN05
    extern __shared__ unsigned char dsm_raw[];
    __shared__ __align__(8) u64 s_mb[2];
    __shared__ uint32_t s_tmem[1];

    const int tid = threadIdx.x;
    const int wid = tid >> 5;
    const int lane = tid & 31;
    const i64 zz = blockIdx.z;
    Ahi += zz * az; Alo += zz * az;
    Bhi += zz * bz; Blo += zz * bz;
    if (C)    C    += zz * cz;
    if (E)    E    += zz * ez;
    if (Ohi)  { Ohi  += zz * oz;  Olo  += zz * oz; }
    if (OThi) { OThi += zz * ozt; OTlo += zz * ozt; }

    const uint32_t sb  = (smem_u32(dsm_raw) + 1023) & ~1023u;
    const uint32_t mbB = smem_u32(&s_mb[0]);
    unsigned char* tsb = (unsigned char*)(((uintptr_t)dsm_raw + 1023) & ~(uintptr_t)1023);

    if (tid == 0) { MBARRIER_INIT(mbB, 1); MBARRIER_INIT(mbB + 8, 1); }
    if (wid == 0) {
        TCGEN05_ALLOC(smem_u32(s_tmem), 256);
        TCGEN05_RELINQ();
    }
    __syncthreads();
    const uint32_t tmem = s_tmem[0];

    const int m0 = blockIdx.y * 128;
    const int n0 = blockIdx.x * 256;

    const int r0    = tid >> 3;
    const int col16 = (tid & 7) * 16;
    const size_t rowB = (size_t)Kp * 2;
    const char* pAhi = (const char*)Ahi + (size_t)(m0 + r0) * rowB + col16;
    const char* pAlo = (const char*)Alo + (size_t)(m0 + r0) * rowB + col16;
    const char* pBhi = (const char*)Bhi + (size_t)(n0 + r0) * rowB + col16;
    const char* pBlo = (const char*)Blo + (size_t)(n0 + r0) * rowB + col16;
    uint32_t swA[4], swB[8];
#pragma unroll
    for (int k = 0; k < 4; ++k) swA[k] = SWZ((uint32_t)(r0 + 32 * k) * 128 + col16);
#pragma unroll
    for (int k = 0; k < 8; ++k) swB[k] = SWZ((uint32_t)(r0 + 32 * k) * 128 + col16);

    uint4 va[8], vb[16];
#define TCFETCH(cc) do { const size_t gb_ = (size_t)(cc) * 128;                         \
    _Pragma("unroll") for (int k_ = 0; k_ < 4; ++k_) {                                  \
        va[k_]     = *reinterpret_cast<const uint4*>(pAhi + (size_t)(32 * k_) * rowB + gb_); \
        va[4 + k_] = *reinterpret_cast<const uint4*>(pAlo + (size_t)(32 * k_) * rowB + gb_); \
    }                                                                                   \
    _Pragma("unroll") for (int k_ = 0; k_ < 8; ++k_) {                                  \
        vb[k_]     = *reinterpret_cast<const uint4*>(pBhi + (size_t)(32 * k_) * rowB + gb_); \
        vb[8 + k_] = *reinterpret_cast<const uint4*>(pBlo + (size_t)(32 * k_) * rowB + gb_); \
    } } while (0)

    const int NC = Kp >> 6;
    TCFETCH(0);
    for (int c = 0; c < NC; ++c) {
        const int s = c & 1;
        const int phase = c >> 1;
        const uint32_t mbs = mbB + (uint32_t)s * 8;
        const uint32_t stg = sb + (uint32_t)s * TC_STAGE;
        if (c >= 2) { MBARRIER_WAIT_PARITY(mbs, (phase - 1) & 1); }
#pragma unroll
        for (int k = 0; k < 4; ++k) {
            STS128(va[k].x, va[k].y, va[k].z, va[k].w, stg + swA[k]);
            STS128(va[4 + k].x, va[4 + k].y, va[4 + k].z, va[4 + k].w, stg + 16384u + swA[k]);
        }
#pragma unroll
        for (int k = 0; k < 8; ++k) {
            STS128(vb[k].x, vb[k].y, vb[k].z, vb[k].w, stg + 32768u + swB[k]);
            STS128(vb[8 + k].x, vb[8 + k].y, vb[8 + k].z, vb[8 + k].w, stg + 65536u + swB[k]);
        }
        if (c + 1 < NC) { TCFETCH(c + 1); }
        FENCE_ASYNC();
        __syncthreads();
        if (wid == 0 && elect1()) {
            u64 aH = mkdesc(stg);
            u64 aL = mkdesc(stg + 16384);
#pragma unroll
            for (int nh = 0; nh < 2; ++nh) {
                const uint32_t d = tmem + (uint32_t)nh * 128;
                u64 bH = mkdesc(stg + 32768 + (uint32_t)nh * 16384);
                u64 bL = mkdesc(stg + 65536 + (uint32_t)nh * 16384);
#pragma unroll
                for (int ks = 0; ks < 4; ++ks)
                    mma_f16_ss(d, aH + ks * 2, bH + ks * 2, TCIDESC, !(c == 0 && ks == 0));
#pragma unroll
                for (int ks = 0; ks < 4; ++ks)
                    mma_f16_ss(d, aH + ks * 2, bL + ks * 2, TCIDESC, true);
#pragma unroll
                for (int ks = 0; ks < 4; ++ks)
                    mma_f16_ss(d, aL + ks * 2, bH + ks * 2, TCIDESC, true);
            }
            TCGEN05_COMMIT(mbs);
        }
    }
    {
        const int cl = NC - 1;
        MBARRIER_WAIT_PARITY(mbB + (uint32_t)(cl & 1) * 8, (cl >> 1) & 1);
    }
    TCGEN05_FENCE_AFTER();

    const bool hasT = (OThi != nullptr);
    const int sub = wid & 3;
    const int colh = (wid >> 2) * 128;
    const int mloc = sub * 32 + lane;
    const int m = m0 + mloc;
#pragma unroll
    for (int qq = 0; qq < 4; ++qq) {
        uint32_t r32[32];
        TCGEN05_LD_X32(r32, tmem + colh + qq * 32);
        TCGEN05_WAIT_LD();
        const int ncol = n0 + colh + qq * 32;
        float o[32];
        if (m < M) {
            if (beta != 0.f) {
                const float* erow = E + (size_t)m * ldE + ncol;
#pragma unroll
                for (int j = 0; j < 32; j += 4) {
                    float4 e = *reinterpret_cast<const float4*>(erow + j);
                    o[j]     = alpha * __uint_as_float(r32[j])     + beta * e.x;
                    o[j + 1] = alpha * __uint_as_float(r32[j + 1]) + beta * e.y;
                    o[j + 2] = alpha * __uint_as_float(r32[j + 2]) + beta * e.z;
                    o[j + 3] = alpha * __uint_as_float(r32[j + 3]) + beta * e.w;
                }
            } else {
#pragma unroll
                for (int j = 0; j < 32; ++j) o[j] = alpha * __uint_as_float(r32[j]);
            }
        } else {
#pragma unroll
            for (int j = 0; j < 32; ++j) o[j] = 0.f;
        }
        if (m < M && C) {
            float* crow = C + (size_t)m * ldc + ncol;
#pragma unroll
            for (int j = 0; j < 32; j += 4)
                *reinterpret_cast<float4*>(crow + j) = make_float4(o[j], o[j+1], o[j+2], o[j+3]);
        }
        if (m < M && Ohi) {
            bf16* hrow = Ohi + (size_t)m * ldo + ncol;
            bf16* lrow = Olo + (size_t)m * ldo + ncol;
#pragma unroll
            for (int j = 0; j < 32; j += 4) {
                __align__(8) bf16 hv[4];
                __align__(8) bf16 lv[4];
#pragma unroll
                for (int t = 0; t < 4; ++t) {
                    bf16 hb_ = __float2bfloat16(o[j + t]);
                    hv[t] = hb_;
                    lv[t] = __float2bfloat16(o[j + t] - __bfloat162float(hb_));
                }
                *reinterpret_cast<uint2*>(hrow + j) = *reinterpret_cast<const uint2*>(hv);
                *reinterpret_cast<uint2*>(lrow + j) = *reinterpret_cast<const uint2*>(lv);
            }
        }
        if (hasT) {
            bf16* th = (bf16*)tsb;
            bf16* tl = (bf16*)(tsb + 65536);
#pragma unroll
            for (int j = 0; j < 32; ++j) {
                const int cidx = colh + qq * 32 + j;
                bf16 hb_ = __float2bfloat16(o[j]);
                th[(size_t)cidx * 128 + mloc] = hb_;
                tl[(size_t)cidx * 128 + mloc] = __float2bfloat16(o[j] - __bfloat162float(hb_));
            }
        }
    }
    if (hasT) {
        __syncthreads();
        const int chunk = tid & 15;       // 16B chunk within 256B row
        const int rbase = tid >> 4;       // 0..15
#pragma unroll
        for (int p = 0; p < 16; ++p) {
            const int cidx = p * 16 + rbase;
            uint4 vh = *reinterpret_cast<const uint4*>(tsb + (size_t)cidx * 256 + chunk * 16);
            uint4 vl = *reinterpret_cast<const uint4*>(tsb + 65536 + (size_t)cidx * 256 + chunk * 16);
            *reinterpret_cast<uint4*>(OThi + (size_t)(n0 + cidx) * ldot + m0 + chunk * 8) = vh;
            *reinterpret_cast<uint4*>(OTlo + (size_t)(n0 + cidx) * ldot + m0 + chunk * 8) = vl;
        }
    }
    __syncthreads();
    if (wid == 0) TCGEN05_DEALLOC(tmem, 256);
#undef TCFETCH
#endif
}

// ================= conversion kernels (z-batched) =================
__global__ void conv_k(const float* __restrict__ src, int ld, int R, int C,
                       bf16* __restrict__ hi, bf16* __restrict__ lo, int Cp,
                       i64 srcZ, i64 dstZ)
{
    const i64 z = blockIdx.z;
    src += z * srcZ; hi += z * dstZ; lo += z * dstZ;
    int c = (blockIdx.x * blockDim.x + threadIdx.x) * 4;
    int r = blockIdx.y;
    if (c >= Cp) return;
    __align__(8) bf16 h4[4];
    __align__(8) bf16 l4[4];
    if (r < R && c < C) {
        float4 fv = *reinterpret_cast<const float4*>(src + (size_t)r * ld + c);
        float vv[4] = {fv.x, fv.y, fv.z, fv.w};
#pragma unroll
        for (int j = 0; j < 4; j++) {
            bf16 h = __float2bfloat16(vv[j]);
            h4[j] = h;
            l4[j] = __float2bfloat16(vv[j] - __bfloat162float(h));
        }
    } else {
#pragma unroll
        for (int j = 0; j < 4; j++) { h4[j] = __float2bfloat16(0.f); l4[j] = h4[j]; }
    }
    size_t o = (size_t)r * Cp + c;
    *reinterpret_cast<uint2*>(hi + o) = *reinterpret_cast<const uint2*>(h4);
    *reinterpret_cast<uint2*>(lo + o) = *reinterpret_cast<const uint2*>(l4);
}

__global__ void convT_k(const float* __restrict__ src, int ld, int R, int C,
                        bf16* __restrict__ hi, bf16* __restrict__ lo, int Rp,
                        i64 srcZ, i64 dstZ)
{
    __shared__ float t[32][33];
    const i64 z = blockIdx.z;
    src += z * srcZ; hi += z * dstZ; lo += z * dstZ;
    int c0 = blockIdx.x * 32;
    int r0 = blockIdx.y * 32;
    int tx = threadIdx.x, ty = threadIdx.y;
#pragma unroll
    for (int j = 0; j < 32; j += 8) {
        int r = r0 + ty + j;
        t[ty + j][tx] = (r < R) ? src[(size_t)r * ld + c0 + tx] : 0.f;
    }
    __syncthreads();
#pragma unroll
    for (int j = 0; j < 32; j += 8) {
        float fv = t[tx][ty + j];
        size_t o = (size_t)(c0 + ty + j) * Rp + r0 + tx;
        bf16 h = __float2bfloat16(fv);
        hi[o] = h;
        lo[o] = __float2bfloat16(fv - __bfloat162float(h));
    }
}

// ================= fused activation + transpose kernels (vectorized) =========
// split 8 floats into bf16 hi/lo packed uint4s
__device__ __forceinline__ void split8(const float* v, uint4& hq, uint4& lq)
{
    __align__(16) bf16 hv[8];
    __align__(16) bf16 lv[8];
#pragma unroll
    for (int j = 0; j < 8; ++j) {
        bf16 hb_ = __float2bfloat16(v[j]);
        hv[j] = hb_;
        lv[j] = __float2bfloat16(v[j] - __bfloat162float(hb_));
    }
    hq = *reinterpret_cast<const uint4*>(hv);
    lq = *reinterpret_cast<const uint4*>(lv);
}

// h = swish(kg)*kv. Tile: 32 tokens x 64 hidden. grid (HIDD/64, MP/32), 256 thr.
// Row-major pairs always; transposed pairs optional.
__global__ void __launch_bounds__(256) swishT_k(
    const float* __restrict__ kg, const float* __restrict__ kv,
    bf16* __restrict__ hhi, bf16* __restrict__ hlo,
    bf16* __restrict__ thi, bf16* __restrict__ tlo)
{
    __shared__ float t[64][33];
    const int c0 = blockIdx.x * 64;
    const int r0 = blockIdx.y * 32;
    const int tid = threadIdx.x;
    const int cg = tid & 7;          // 8-col group
    const int r  = tid >> 3;         // 0..31
    const int row = r0 + r;
    const int col = c0 + cg * 8;

    float h8[8];
    if (row < NTOK) {
        const float* pg = kg + (size_t)row * HIDD + col;
        const float* pv = kv + (size_t)row * HIDD + col;
        float4 g0 = *reinterpret_cast<const float4*>(pg);
        float4 g1 = *reinterpret_cast<const float4*>(pg + 4);
        float4 v0 = *reinterpret_cast<const float4*>(pv);
        float4 v1 = *reinterpret_cast<const float4*>(pv + 4);
        float gs[8] = {g0.x, g0.y, g0.z, g0.w, g1.x, g1.y, g1.z, g1.w};
        float vs[8] = {v0.x, v0.y, v0.z, v0.w, v1.x, v1.y, v1.z, v1.w};
#pragma unroll
        for (int j = 0; j < 8; ++j)
            h8[j] = gs[j] / (1.f + __expf(-gs[j])) * vs[j];
    } else {
#pragma unroll
        for (int j = 0; j < 8; ++j) h8[j] = 0.f;
    }
    {
        uint4 hq, lq;
        split8(h8, hq, lq);
        size_t o = (size_t)row * HIDD + col;
        *reinterpret_cast<uint4*>(hhi + o) = hq;
        *reinterpret_cast<uint4*>(hlo + o) = lq;
    }
    if (thi) {
#pragma unroll
        for (int j = 0; j < 8; ++j) t[cg * 8 + j][r] = h8[j];
        __syncthreads();
        const int orow = tid >> 2;      // 0..63 hidden-col within tile
        const int seg  = tid & 3;       // 8-token segment
        float v8[8];
#pragma unroll
        for (int j = 0; j < 8; ++j) v8[j] = t[orow][seg * 8 + j];
        uint4 hq, lq;
        split8(v8, hq, lq);
        size_t o = (size_t)(c0 + orow) * MP + r0 + seg * 8;
        *reinterpret_cast<uint4*>(thi + o) = hq;
        *reinterpret_cast<uint4*>(tlo + o) = lq;
    }
}

// dkg/dkv from (dh, kg, kv); transposed pairs ONLY. Same tiling as swishT_k.
__global__ void __launch_bounds__(256) bw_ewT_k(
    const float* __restrict__ dh,
    const float* __restrict__ kg, const float* __restrict__ kv,
    bf16* __restrict__ gthi, bf16* __restrict__ gtlo,
    bf16* __restrict__ vthi, bf16* __restrict__ vtlo)
{
    __shared__ float tg[64][33];
    __shared__ float tv[64][33];
    const int c0 = blockIdx.x * 64;
    const int r0 = blockIdx.y * 32;
    const int tid = threadIdx.x;
    const int cg = tid & 7;
    const int r  = tid >> 3;
    const int row = r0 + r;
    const int col = c0 + cg * 8;

    if (row < NTOK) {
        const float* pd = dh + (size_t)row * HIDD + col;
        const float* pg = kg + (size_t)row * HIDD + col;
        const float* pv = kv + (size_t)row * HIDD + col;
        float4 d0 = *reinterpret_cast<const float4*>(pd);
        float4 d1 = *reinterpret_cast<const float4*>(pd + 4);
        float4 g0 = *reinterpret_cast<const float4*>(pg);
        float4 g1 = *reinterpret_cast<const float4*>(pg + 4);
        float4 v0 = *reinterpret_cast<const float4*>(pv);
        float4 v1 = *reinterpret_cast<const float4*>(pv + 4);
        float ds[8] = {d0.x, d0.y, d0.z, d0.w, d1.x, d1.y, d1.z, d1.w};
        float gs[8] = {g0.x, g0.y, g0.z, g0.w, g1.x, g1.y, g1.z, g1.w};
        float vs[8] = {v0.x, v0.y, v0.z, v0.w, v1.x, v1.y, v1.z, v1.w};
#pragma unroll
        for (int j = 0; j < 8; ++j) {
            float s = 1.f / (1.f + __expf(-gs[j]));
            tv[cg * 8 + j][r] = ds[j] * gs[j] * s;
            tg[cg * 8 + j][r] = ds[j] * vs[j] * s * (1.f + gs[j] * (1.f - s));
        }
    } else {
#pragma unroll
        for (int j = 0; j < 8; ++j) { tg[cg * 8 + j][r] = 0.f; tv[cg * 8 + j][r] = 0.f; }
    }
    __syncthreads();
    const int orow = tid >> 2;
    const int seg  = tid & 3;
    const size_t o = (size_t)(c0 + orow) * MP + r0 + seg * 8;
    {
        float v8[8];
#pragma unroll
        for (int j = 0; j < 8; ++j) v8[j] = tg[orow][seg * 8 + j];
        uint4 hq, lq;
        split8(v8, hq, lq);
        *reinterpret_cast<uint4*>(gthi + o) = hq;
        *reinterpret_cast<uint4*>(gtlo + o) = lq;
    }
    {
        float v8[8];
#pragma unroll
        for (int j = 0; j < 8; ++j) v8[j] = tv[orow][seg * 8 + j];
        uint4 hq, lq;
        split8(v8, hq, lq);
        *reinterpret_cast<uint4*>(vthi + o) = hq;
        *reinterpret_cast<uint4*>(vtlo + o) = lq;
    }
}

// ================= elementwise / reductions =================
__global__ void norm_heads_k(float* __restrict__ base,
                             const float* __restrict__ sc, const float* __restrict__ bi)
{
    int w = (blockIdx.x * blockDim.x + threadIdx.x) >> 5;
    int lane = threadIdx.x & 31;
    if (w >= NTOK * 16) return;
    int rowi = w >> 4, head = w & 15;
    float* p = base + (size_t)rowi * (3 * DIMM) + head * 64;
    float x0 = p[lane], x1 = p[lane + 32];
    float ss = x0 * x0 + x1 * x1;
#pragma unroll
    for (int o = 16; o; o >>= 1) ss += __shfl_xor_sync(0xffffffffu, ss, o);
    float inv = 1.f / (sqrtf(ss) + 1e-6f);
    p[lane]      = x0 * inv * sc[lane]      + bi[lane];
    p[lane + 32] = x1 * inv * sc[lane + 32] + bi[lane + 32];
}

__global__ void zero3_k(double* p) { if (threadIdx.x < 3) p[threadIdx.x] = 0.0; }

__global__ void sumsq3_k(const float* __restrict__ x, int n, double* __restrict__ out)
{
    __shared__ double sm[256];
    const int z = blockIdx.y;
    x += (size_t)z * n;
    double a = 0.0;
    for (int i = blockIdx.x * blockDim.x + threadIdx.x; i < n; i += gridDim.x * blockDim.x) {
        float fv = x[i];
        a += (double)fv * (double)fv;
    }
    sm[threadIdx.x] = a;
    __syncthreads();
    for (int s = 128; s; s >>= 1) {
        if (threadIdx.x < s) sm[threadIdx.x] += sm[threadIdx.x + s];
        __syncthreads();
    }
    if (threadIdx.x == 0) atomicAdd(&out[z], sm[0]);
}

__global__ void scale3_k(const float4* __restrict__ g, float4* __restrict__ X, int n4,
                         const double* __restrict__ nrm)
{
    const int z = blockIdx.y;
    int i = blockIdx.x * blockDim.x + threadIdx.x;
    if (i >= n4) return;
    float inv = (float)(1.0 / (sqrt(nrm[z]) + 1e-7));
    float4 fv = g[(size_t)z * n4 + i];
    fv.x *= inv; fv.y *= inv; fv.z *= inv; fv.w *= inv;
    X[(size_t)z * n4 + i] = fv;
}

__global__ void transpose_k(const float* __restrict__ src, float* __restrict__ dst,
                            int R, int C)
{
    __shared__ float t[32][33];
    int c0 = blockIdx.x * 32, r0 = blockIdx.y * 32;
    int x = c0 + threadIdx.x;
#pragma unroll
    for (int j = 0; j < 32; j += 8)
        t[threadIdx.y + j][threadIdx.x] = src[(size_t)(r0 + threadIdx.y + j) * C + x];
    __syncthreads();
    int x2 = r0 + threadIdx.x;
#pragma unroll
    for (int j = 0; j < 32; j += 8)
        dst[(size_t)(c0 + threadIdx.y + j) * R + x2] = t[threadIdx.x][threadIdx.y + j];
}

__global__ void upd_k(float4* __restrict__ p, const float4* __restrict__ x, int n4)
{
    int i = blockIdx.x * blockDim.x + threadIdx.x;
    if (i >= n4) return;
    float4 a = p[i], bb = x[i];
    a.x -= LRATE * bb.x; a.y -= LRATE * bb.y; a.z -= LRATE * bb.z; a.w -= LRATE * bb.w;
    p[i] = a;
}

// ================= host orchestration =================
struct BP { bf16 *hi, *lo; };

static void* symaddr(const void* s) { void* p = nullptr; cudaGetSymbolAddress(&p, s); return p; }

static void tc(BP A, BP B, int Kp, float* C, int ldc, int M, int N,
               float alpha, float beta, const float* E, int ldE,
               int nz = 1, i64 az = 0, i64 bz = 0, i64 cz = 0, i64 ez = 0,
               BP O = {nullptr, nullptr}, int ldo = 0, i64 oz = 0,
               BP OT = {nullptr, nullptr}, int ldot = 0, i64 ozt = 0)
{
    dim3 gr(N / 256, (M + 127) / 128, nz);
    tc_gemm<<<gr, 256, TC_SMEM>>>(A.hi, A.lo, B.hi, B.lo, Kp, C, ldc, E, ldE,
                                  alpha, beta, M, az, bz, cz, ez, O.hi, O.lo, ldo, oz,
                                  OT.hi, OT.lo, ldot, ozt);
}

static void conv(const float* s, int ld, int R, int C, BP d, int Rp, int Cp,
                 int nz = 1, i64 sZ = 0, i64 dZ = 0)
{
    dim3 gr((Cp / 4 + 255) / 256, Rp, nz);
    conv_k<<<gr, 256>>>(s, ld, R, C, d.hi, d.lo, Cp, sZ, dZ);
}

static void convT(const float* s, int ld, int R, int C, BP d, int Rp,
                  int nz = 1, i64 sZ = 0, i64 dZ = 0)
{
    dim3 gr(C / 32, Rp / 32, nz);
    convT_k<<<gr, dim3(32, 8)>>>(s, ld, R, C, d.hi, d.lo, Rp, sZ, dZ);
}

extern "C" void kernel_launch(void* const* d_in, const int* in_sizes, int n_in,
                              void* d_out, int out_size)
{
    const float* x        = (const float*)d_in[0];
    const float* qkv_w    = (const float*)d_in[1];
    const float* qkv_b    = (const float*)d_in[2];
    const float* qn_s     = (const float*)d_in[3];
    const float* qn_b     = (const float*)d_in[4];
    const float* kn_s     = (const float*)d_in[5];
    const float* kn_b     = (const float*)d_in[6];
    const float* ttt_gate = (const float*)d_in[7];
    const float* ttt_val  = (const float*)d_in[8];
    const float* ttt_proj = (const float*)d_in[9];
    const float* proj_w   = (const float*)d_in[10];
    const float* proj_b   = (const float*)d_in[11];
    float* out = (float*)d_out;

    cudaFuncSetAttribute(tc_gemm, cudaFuncAttributeMaxDynamicSharedMemorySize, TC_SMEM);

    float* qkv  = (float*)symaddr(g_qkv);
    float* kgv  = (float*)symaddr(g_kgv);
    float* h    = (float*)symaddr(g_h);
    float* GV   = (float*)symaddr(g_GV);
    float* P    = (float*)symaddr(g_P);
    float* grad = (float*)symaddr(g_grad);
    float* X1   = (float*)symaddr(g_X1);
    float* X2   = (float*)symaddr(g_X2);
    float* Amat = (float*)symaddr(g_A);
    double* nrm = (double*)symaddr(g_nrm);
    unsigned char* pool = (unsigned char*)symaddr(g_bf);

    auto bp = [&](size_t off, size_t elems) { BP b; b.hi = (bf16*)(pool + off); b.lo = b.hi + elems; return b; };

    BP xb    = bp(O_X, E_TOKD);
    BP kb    = bp(O_K, E_TOKD);
    BP kTb   = bp(O_KT, E_TOKD);
    BP qb    = bp(O_Q, E_TOKD);
    BP rTb   = bp(O_RT, E_TOKD);
    BP hb    = bp(O_H, E_TOKH);
    BP hTb   = bp(O_HT, E_TOKH);
    BP dkgT  = bp(O_DKGT, E_TOKH);
    BP dkvT  = bp(O_DKVT, E_TOKH);
    BP wGt   = bp(O_WGT, E_W);
    BP wP    = bp(O_WP,  E_W);
    BP wPt   = bp(O_WPT, E_W);
    BP qkvwT = bp(O_QKVW, E_QKVW);
    BP projwT = bp(O_PRJW, E_A);
    BP nsX   = bp(O_NSX,  E_W);
    BP nsXTa = bp(O_NSXT, E_W);
    BP nsXTb = bp(O_NSXT2, E_W);
    BP nsA   = bp(O_NSA,  E_A);
    BP nsA2  = bp(O_NSA2, E_A);
    BP NOB   = {nullptr, nullptr};

    const size_t TB = sizeof(float) * E_W;
    cudaMemcpyAsync(GV,       ttt_gate, TB, cudaMemcpyDeviceToDevice, 0);
    cudaMemcpyAsync(GV + E_W, ttt_val,  TB, cudaMemcpyDeviceToDevice, 0);
    cudaMemcpyAsync(P,        ttt_proj, TB, cudaMemcpyDeviceToDevice, 0);

    // ---- qkv = x @ qkv_w + b ----
    conv (x, DIMM, NTOK, DIMM, xb, MP, DIMM);
    convT(qkv_w, 3 * DIMM, DIMM, 3 * DIMM, qkvwT, DIMM);
    tc(xb, qkvwT, DIMM, qkv, 3 * DIMM, NTOK, 3 * DIMM, 1.f, 1.f, qkv_b, 0);

    {
        int nb = (NTOK * 16 * 32 + 255) / 256;
        norm_heads_k<<<nb, 256>>>(qkv, qn_s, qn_b);
        norm_heads_k<<<nb, 256>>>(qkv + DIMM, kn_s, kn_b);
    }

    const float* kmat = qkv + DIMM;
    const float* vmat = qkv + 2 * DIMM;
    conv (kmat, 3 * DIMM, NTOK, DIMM, kb, MP, DIMM);
    convT(kmat, 3 * DIMM, NTOK, DIMM, kTb, MP);
    conv (qkv, 3 * DIMM, NTOK, DIMM, qb, MP, DIMM);

    const dim3 grTH(HIDD / 64, MP / 32);
    const i64 ZW = 2 * (i64)E_W;
    const i64 ZA = 2 * (i64)E_A;
    const i64 KGV = (i64)NTOK * HIDD;

    for (int step = 0; step < 2; ++step) {
        convT(GV, HIDD, DIMM, HIDD, wGt, DIMM, 2, (i64)E_W, ZW);
        conv (P, DIMM, HIDD, DIMM, wP, HIDD, DIMM);
        convT(P, DIMM, HIDD, DIMM, wPt, HIDD);

        // kg|kv = k @ {G,V}
        tc(kb, wGt, DIMM, kgv, HIDD, NTOK, HIDD, 1.f, 0.f, nullptr, 0,
           2, 0, ZW, KGV, 0);
        swishT_k<<<grTH, 256>>>(kgv, kgv + KGV, hb.hi, hb.lo, hTb.hi, hTb.lo);
        // r = h @ P - v : pairs (xb) + transposed pairs (rTb), no fp32 C
        tc(hb, wPt, HIDD, nullptr, 0, NTOK, DIMM, 1.f, -1.f, vmat, 3 * DIMM,
           1, 0, 0, 0, 0, xb, DIMM, 0, rTb, MP, 0);
        // gP^T = r^T @ h
        tc(rTb, hTb, MP, grad + 2 * E_W, HIDD, DIMM, HIDD, 1.f, 0.f, nullptr, 0);
        // dh = r @ P^T  -> h buffer
        tc(xb, wP, DIMM, h, HIDD, NTOK, HIDD, 1.f, 0.f, nullptr, 0);
        bw_ewT_k<<<grTH, 256>>>(h, kgv, kgv + KGV,
                                dkgT.hi, dkgT.lo, dkvT.hi, dkvT.lo);
        // gG|gV = k^T @ {dkg,dkv}
        tc(kTb, dkgT, MP, grad, HIDD, DIMM, HIDD, 1.f, 0.f, nullptr, 0,
           2, 0, 2 * (i64)E_TOKH, (i64)E_W, 0);

        // ---- batched Newton-Schulz over {gG, gV, gP^T} ----
        zero3_k<<<1, 4>>>(nrm);
        sumsq3_k<<<dim3(256, 3), 256>>>(grad, (int)E_W, nrm);
        scale3_k<<<dim3(((int)E_W / 4 + 255) / 256, 3), 256>>>(
            (const float4*)grad, (float4*)X1, (int)E_W / 4, nrm);
        float* X = X1;
        float* Y = X2;
        conv (X, HIDD, DIMM, HIDD, nsX, DIMM, HIDD, 3, (i64)E_W, ZW);
        convT(X, HIDD, DIMM, HIDD, nsXTa, DIMM, 3, (i64)E_W, ZW);
        for (int it = 0; it < 5; ++it) {
            BP XTin  = (it & 1) ? nsXTb : nsXTa;
            BP XTout = (it & 1) ? nsXTa : nsXTb;
            tc(nsX, nsX, HIDD, Amat, DIMM, DIMM, DIMM, 1.f, 0.f, nullptr, 0,
               3, ZW, ZW, (i64)E_A, 0, nsA, DIMM, ZA);
            tc(nsA, nsA, DIMM, nullptr, 0, DIMM, DIMM, NS_C, NS_B, Amat, DIMM,
               3, ZA, ZA, 0, (i64)E_A, nsA2, DIMM, ZA);
            tc(nsA2, XTin, DIMM, Y, HIDD, DIMM, HIDD, 1.f, NS_A, X, HIDD,
               3, ZA, ZW, (i64)E_W, (i64)E_W, nsX, HIDD, ZW,
               (it < 4) ? XTout : NOB, DIMM, ZW);
            float* t = X; X = Y; Y = t;
        }
        upd_k<<<((int)(2 * E_W / 4) + 255) / 256, 256>>>((float4*)GV, (const float4*)X, (int)(2 * E_W / 4));
        {
            dim3 gr(HIDD / 32, DIMM / 32);
            transpose_k<<<gr, dim3(32, 8)>>>(X + 2 * E_W, Y, DIMM, HIDD);
            upd_k<<<((int)(E_W / 4) + 255) / 256, 256>>>((float4*)P, (const float4*)Y, (int)(E_W / 4));
        }
    }

    // ---- final forward with q ----
    convT(GV, HIDD, DIMM, HIDD, wGt, DIMM, 2, (i64)E_W, ZW);
    convT(P, DIMM, HIDD, DIMM, wPt, HIDD);
    tc(qb, wGt, DIMM, kgv, HIDD, NTOK, HIDD, 1.f, 0.f, nullptr, 0,
       2, 0, ZW, KGV, 0);
    swishT_k<<<grTH, 256>>>(kgv, kgv + KGV, hb.hi, hb.lo, nullptr, nullptr);
    tc(hb, wPt, HIDD, nullptr, 0, NTOK, DIMM, 1.f, 0.f, nullptr, 0,
       1, 0, 0, 0, 0, xb, DIMM, 0);
    convT(proj_w, DIMM, DIMM, DIMM, projwT, DIMM);
    tc(xb, projwT, DIMM, out, DIMM, NTOK, DIMM, 1.f, 1.f, proj_b, 0);
}

// round 14
// speedup vs baseline: 8.0543x; 1.0455x over previous
#include <cuda_runtime.h>
#include <cuda_bf16.h>
#include <cstdint>
#include <cstddef>

// ---------------- problem constants ----------------
#define NTOK 10992
#define MP   11008
#define DIMM 1024
#define HIDD 4096
#define LRATE 0.1f
#define NS_A 3.4445f
#define NS_B (-4.7750f)
#define NS_C 2.0315f

typedef unsigned long long u64;
typedef long long i64;
typedef __nv_bfloat16 bf16;

#if !defined(__CUDA_ARCH__) || defined(__CUDA_ARCH_FEAT_SM103_ALL)
#define TC_HAS_TCGEN05 1
#else
#define TC_HAS_TCGEN05 0
#endif

// ================= PTX helpers (sm_103a) =================
#if TC_HAS_TCGEN05
__device__ __forceinline__ uint32_t smem_u32(const void* p) {
    uint32_t a;
    asm("{ .reg .u64 t; cvta.to.shared.u64 t, %1; cvt.u32.u64 %0, t; }" : "=r"(a) : "l"(p));
    return a;
}
__device__ __forceinline__ uint32_t elect1() {
    uint32_t p;
    asm volatile("{\n.reg .pred p;\nelect.sync _|p, 0xFFFFFFFF;\nselp.b32 %0,1,0,p;\n}" : "=r"(p));
    return p;
}
#define MBARRIER_INIT(a, c) \
    asm volatile("mbarrier.init.shared.b64 [%0], %1;" :: "r"((uint32_t)(a)), "r"((uint32_t)(c)) : "memory")
#define MBARRIER_WAIT_PARITY(a, ph) do { \
    uint32_t _m = (uint32_t)(a); uint32_t _p = (uint32_t)(ph); uint32_t _d; \
    asm volatile("{\n.reg .pred p;\nmbarrier.try_wait.parity.acquire.cta.shared::cta.b64 p, [%1], %2;\nselp.b32 %0,1,0,p;\n}" \
        : "=r"(_d) : "r"(_m), "r"(_p) : "memory"); \
    if (!_d) { \
        asm volatile("{\n.reg .pred P1;\nWL_%=:\nmbarrier.try_wait.parity.acquire.cta.shared::cta.b64 P1, [%0], %1, 0x989680;\n@P1 bra.uni WD_%=;\nbra.uni WL_%=;\nWD_%=:\n}" \
            :: "r"(_m), "r"(_p) : "memory"); \
    } } while (0)
#define TCGEN05_ALLOC(sa, n) \
    asm volatile("tcgen05.alloc.cta_group::1.sync.aligned.shared::cta.b32 [%0], %1;" \
        :: "r"((uint32_t)(sa)), "r"((uint32_t)(n)) : "memory")
#define TCGEN05_RELINQ() \
    asm volatile("tcgen05.relinquish_alloc_permit.cta_group::1.sync.aligned;")
#define TCGEN05_DEALLOC(t, n) \
    asm volatile("tcgen05.dealloc.cta_group::1.sync.aligned.b32 %0, %1;" :: "r"(t), "r"((uint32_t)(n)))
#define TCGEN05_COMMIT(a) \
    asm volatile("tcgen05.commit.cta_group::1.mbarrier::arrive::one.shared::cluster.b64 [%0];" \
        :: "r"((uint32_t)(a)) : "memory")
#define TCGEN05_FENCE_AFTER() asm volatile("tcgen05.fence::after_thread_sync;" ::: "memory")
#define TCGEN05_WAIT_LD() asm volatile("tcgen05.wait::ld.sync.aligned;" ::: "memory")
#define FENCE_ASYNC() asm volatile("fence.proxy.async.shared::cta;" ::: "memory")
#define STS128(r0, r1, r2, r3, a) \
    asm volatile("st.shared.v4.b32 [%0], {%1,%2,%3,%4};" :: "r"(a), "r"(r0), "r"(r1), "r"(r2), "r"(r3) : "memory")
#define TCGEN05_LD_X32(r, ta) \
    asm volatile("tcgen05.ld.sync.aligned.32x32b.x32.b32 " \
        "{%0,%1,%2,%3,%4,%5,%6,%7,%8,%9,%10,%11,%12,%13,%14,%15," \
        "%16,%17,%18,%19,%20,%21,%22,%23,%24,%25,%26,%27,%28,%29,%30,%31}, [%32];" \
        : "=r"((r)[0]), "=r"((r)[1]), "=r"((r)[2]), "=r"((r)[3]), "=r"((r)[4]), "=r"((r)[5]), \
          "=r"((r)[6]), "=r"((r)[7]), "=r"((r)[8]), "=r"((r)[9]), "=r"((r)[10]), "=r"((r)[11]), \
          "=r"((r)[12]), "=r"((r)[13]), "=r"((r)[14]), "=r"((r)[15]), "=r"((r)[16]), "=r"((r)[17]), \
          "=r"((r)[18]), "=r"((r)[19]), "=r"((r)[20]), "=r"((r)[21]), "=r"((r)[22]), "=r"((r)[23]), \
          "=r"((r)[24]), "=r"((r)[25]), "=r"((r)[26]), "=r"((r)[27]), "=r"((r)[28]), "=r"((r)[29]), \
          "=r"((r)[30]), "=r"((r)[31]) : "r"(ta))

static constexpr u64 SMEM_DESC_BASE =
    (u64(2) << 61) | (u64(1) << 46) | (u64(64) << 32) | (u64(1) << 16);
__device__ __forceinline__ u64 mkdesc(uint32_t sa) {
    return SMEM_DESC_BASE | ((u64)(sa >> 4) & 0x3FFF);
}
__device__ __forceinline__ void mma_f16_ss(uint32_t d, u64 ad, u64 bd, uint32_t idesc, bool acc) {
    uint32_t en = acc ? 1u : 0u;
    asm volatile(
        "{\n\t.reg .pred p;\n\tsetp.ne.u32 p, %4, 0;\n\t"
        "tcgen05.mma.cta_group::1.kind::f16 [%0], %1, %2, %3, {%5,%5,%5,%5}, p;\n\t}"
        :: "r"(d), "l"(ad), "l"(bd), "r"(idesc), "r"(en), "r"(0u) : "memory");
}
#endif

#define SWZ(b) ((b) ^ (((b) >> 3) & 0x70))
#define TCIDESC 0x08200490u   // dtype=F32, a=BF16, b=BF16, N=128, M=128

// ---------------- fp32 scratch ----------------
static constexpr size_t E_TOKD = (size_t)MP * DIMM;
static constexpr size_t E_TOKH = (size_t)MP * HIDD;
static constexpr size_t E_W    = (size_t)DIMM * HIDD;
static constexpr size_t E_A    = (size_t)DIMM * DIMM;
static constexpr size_t E_QKVW = (size_t)DIMM * 3 * DIMM;

__device__ float g_qkv [(size_t)NTOK * 3 * DIMM];
__device__ float g_kgv [(size_t)2 * NTOK * HIDD];
__device__ float g_h   [(size_t)NTOK * HIDD];
__device__ float g_GV  [2 * E_W];
__device__ float g_P   [E_W];
__device__ float g_grad[3 * E_W];
__device__ float g_X1  [3 * E_W];
__device__ float g_X2  [3 * E_W];
__device__ float g_A   [3 * E_A];
__device__ double g_nrm[3];

// ---------------- bf16 hi/lo pool ----------------
static constexpr size_t O_X     = 0;
static constexpr size_t O_K     = O_X     + E_TOKD * 4;
static constexpr size_t O_KT    = O_K     + E_TOKD * 4;
static constexpr size_t O_Q     = O_KT    + E_TOKD * 4;
static constexpr size_t O_RT    = O_Q     + E_TOKD * 4;
static constexpr size_t O_H     = O_RT    + E_TOKD * 4;
static constexpr size_t O_HT    = O_H     + E_TOKH * 4;
static constexpr size_t O_DKGT  = O_HT    + E_TOKH * 4;
static constexpr size_t O_DKVT  = O_DKGT  + E_TOKH * 4;
static constexpr size_t O_WGT   = O_DKVT  + E_TOKH * 4;
static constexpr size_t O_WVT   = O_WGT   + E_W * 4;
static constexpr size_t O_WP    = O_WVT   + E_W * 4;
static constexpr size_t O_WPT   = O_WP    + E_W * 4;
static constexpr size_t O_QKVW  = O_WPT   + E_W * 4;
static constexpr size_t O_PRJW  = O_QKVW  + E_QKVW * 4;
static constexpr size_t O_NSX   = O_PRJW  + E_A * 4;
static constexpr size_t O_NSXT  = O_NSX   + 3 * E_W * 4;
static constexpr size_t O_NSXT2 = O_NSXT  + 3 * E_W * 4;
static constexpr size_t O_NSA   = O_NSXT2 + 3 * E_W * 4;
static constexpr size_t O_NSA2  = O_NSA   + 3 * E_A * 4;
static constexpr size_t POOL_B  = O_NSA2  + 3 * E_A * 4;
__device__ __align__(1024) unsigned char g_bf[POOL_B];

// ============ tcgen05 split-bf16 GEMM: 128x256 tile, cg1, double-buffered ======
// terms==3: full hi/lo split (hi*hi + hi*lo + lo*hi). terms==1: hi*hi only
// (lo staging skipped entirely).
#define TC_STAGE 98304
#define TC_SMEM  (2 * TC_STAGE + 1024)

__global__ void __launch_bounds__(256, 1) tc_gemm(
    const bf16* __restrict__ Ahi, const bf16* __restrict__ Alo,
    const bf16* __restrict__ Bhi, const bf16* __restrict__ Blo,
    int Kp, float* __restrict__ C, int ldc,
    const float* __restrict__ E, int ldE,
    float alpha, float beta, int M,
    i64 az, i64 bz, i64 cz, i64 ez,
    bf16* __restrict__ Ohi, bf16* __restrict__ Olo, int ldo, i64 oz,
    bf16* __restrict__ OThi, bf16* __restrict__ OTlo, int ldot, i64 ozt,
    int terms)
{
#if TC_HAS_TCGEN05
    extern __shared__ unsigned char dsm_raw[];
    __shared__ __align__(8) u64 s_mb[2];
    __shared__ uint32_t s_tmem[1];

    const int tid = threadIdx.x;
    const int wid = tid >> 5;
    const int lane = tid & 31;
    const i64 zz = blockIdx.z;
    Ahi += zz * az; Alo += zz * az;
    Bhi += zz * bz; Blo += zz * bz;
    if (C)    C    += zz * cz;
    if (E)    E    += zz * ez;
    if (Ohi)  { Ohi  += zz * oz;  Olo  += zz * oz; }
    if (OThi) { OThi += zz * ozt; OTlo += zz * ozt; }
    const bool full = (terms == 3);

    const uint32_t sb  = (smem_u32(dsm_raw) + 1023) & ~1023u;
    const uint32_t mbB = smem_u32(&s_mb[0]);
    unsigned char* tsb = (unsigned char*)(((uintptr_t)dsm_raw + 1023) & ~(uintptr_t)1023);

    if (tid == 0) { MBARRIER_INIT(mbB, 1); MBARRIER_INIT(mbB + 8, 1); }
    if (wid == 0) {
        TCGEN05_ALLOC(smem_u32(s_tmem), 256);
        TCGEN05_RELINQ();
    }
    __syncthreads();
    const uint32_t tmem = s_tmem[0];

    const int m0 = blockIdx.y * 128;
    const int n0 = blockIdx.x * 256;

    const int r0    = tid >> 3;
    const int col16 = (tid & 7) * 16;
    const size_t rowB = (size_t)Kp * 2;
    const char* pAhi = (const char*)Ahi + (size_t)(m0 + r0) * rowB + col16;
    const char* pAlo = (const char*)Alo + (size_t)(m0 + r0) * rowB + col16;
    const char* pBhi = (const char*)Bhi + (size_t)(n0 + r0) * rowB + col16;
    const char* pBlo = (const char*)Blo + (size_t)(n0 + r0) * rowB + col16;
    uint32_t swA[4], swB[8];
#pragma unroll
    for (int k = 0; k < 4; ++k) swA[k] = SWZ((uint32_t)(r0 + 32 * k) * 128 + col16);
#pragma unroll
    for (int k = 0; k < 8; ++k) swB[k] = SWZ((uint32_t)(r0 + 32 * k) * 128 + col16);

    uint4 va[8], vb[16];
#define TCFETCH(cc) do { const size_t gb_ = (size_t)(cc) * 128;                         \
    _Pragma("unroll") for (int k_ = 0; k_ < 4; ++k_)                                    \
        va[k_] = *reinterpret_cast<const uint4*>(pAhi + (size_t)(32 * k_) * rowB + gb_); \
    _Pragma("unroll") for (int k_ = 0; k_ < 8; ++k_)                                    \
        vb[k_] = *reinterpret_cast<const uint4*>(pBhi + (size_t)(32 * k_) * rowB + gb_); \
    if (full) {                                                                          \
        _Pragma("unroll") for (int k_ = 0; k_ < 4; ++k_)                                 \
            va[4 + k_] = *reinterpret_cast<const uint4*>(pAlo + (size_t)(32 * k_) * rowB + gb_); \
        _Pragma("unroll") for (int k_ = 0; k_ < 8; ++k_)                                 \
            vb[8 + k_] = *reinterpret_cast<const uint4*>(pBlo + (size_t)(32 * k_) * rowB + gb_); \
    } } while (0)

    const int NC = Kp >> 6;
    TCFETCH(0);
    for (int c = 0; c < NC; ++c) {
        const int s = c & 1;
        const int phase = c >> 1;
        const uint32_t mbs = mbB + (uint32_t)s * 8;
        const uint32_t stg = sb + (uint32_t)s * TC_STAGE;
        if (c >= 2) { MBARRIER_WAIT_PARITY(mbs, (phase - 1) & 1); }
#pragma unroll
        for (int k = 0; k < 4; ++k)
            STS128(va[k].x, va[k].y, va[k].z, va[k].w, stg + swA[k]);
#pragma unroll
        for (int k = 0; k < 8; ++k)
            STS128(vb[k].x, vb[k].y, vb[k].z, vb[k].w, stg + 32768u + swB[k]);
        if (full) {
#pragma unroll
            for (int k = 0; k < 4; ++k)
                STS128(va[4 + k].x, va[4 + k].y, va[4 + k].z, va[4 + k].w, stg + 16384u + swA[k]);
#pragma unroll
            for (int k = 0; k < 8; ++k)
                STS128(vb[8 + k].x, vb[8 + k].y, vb[8 + k].z, vb[8 + k].w, stg + 65536u + swB[k]);
        }
        if (c + 1 < NC) { TCFETCH(c + 1); }
        FENCE_ASYNC();
        __syncthreads();
        if (wid == 0 && elect1()) {
            u64 aH = mkdesc(stg);
            u64 aL = mkdesc(stg + 16384);
#pragma unroll
            for (int nh = 0; nh < 2; ++nh) {
                const uint32_t d = tmem + (uint32_t)nh * 128;
                u64 bH = mkdesc(stg + 32768 + (uint32_t)nh * 16384);
                u64 bL = mkdesc(stg + 65536 + (uint32_t)nh * 16384);
#pragma unroll
                for (int ks = 0; ks < 4; ++ks)
                    mma_f16_ss(d, aH + ks * 2, bH + ks * 2, TCIDESC, !(c == 0 && ks == 0));
                if (full) {
#pragma unroll
                    for (int ks = 0; ks < 4; ++ks)
                        mma_f16_ss(d, aH + ks * 2, bL + ks * 2, TCIDESC, true);
#pragma unroll
                    for (int ks = 0; ks < 4; ++ks)
                        mma_f16_ss(d, aL + ks * 2, bH + ks * 2, TCIDESC, true);
                }
            }
            TCGEN05_COMMIT(mbs);
        }
    }
    {
        const int cl = NC - 1;
        MBARRIER_WAIT_PARITY(mbB + (uint32_t)(cl & 1) * 8, (cl >> 1) & 1);
    }
    TCGEN05_FENCE_AFTER();

    const bool hasT = (OThi != nullptr);
    const int sub = wid & 3;
    const int colh = (wid >> 2) * 128;
    const int mloc = sub * 32 + lane;
    const int m = m0 + mloc;
#pragma unroll
    for (int qq = 0; qq < 4; ++qq) {
        uint32_t r32[32];
        TCGEN05_LD_X32(r32, tmem + colh + qq * 32);
        TCGEN05_WAIT_LD();
        const int ncol = n0 + colh + qq * 32;
        float o[32];
        if (m < M) {
            if (beta != 0.f) {
                const float* erow = E + (size_t)m * ldE + ncol;
#pragma unroll
                for (int j = 0; j < 32; j += 4) {
                    float4 e = *reinterpret_cast<const float4*>(erow + j);
                    o[j]     = alpha * __uint_as_float(r32[j])     + beta * e.x;
                    o[j + 1] = alpha * __uint_as_float(r32[j + 1]) + beta * e.y;
                    o[j + 2] = alpha * __uint_as_float(r32[j + 2]) + beta * e.z;
                    o[j + 3] = alpha * __uint_as_float(r32[j + 3]) + beta * e.w;
                }
            } else {
#pragma unroll
                for (int j = 0; j < 32; ++j) o[j] = alpha * __uint_as_float(r32[j]);
            }
        } else {
#pragma unroll
            for (int j = 0; j < 32; ++j) o[j] = 0.f;
        }
        if (m < M && C) {
            float* crow = C + (size_t)m * ldc + ncol;
#pragma unroll
            for (int j = 0; j < 32; j += 4)
                *reinterpret_cast<float4*>(crow + j) = make_float4(o[j], o[j+1], o[j+2], o[j+3]);
        }
        if (m < M && Ohi) {
            bf16* hrow = Ohi + (size_t)m * ldo + ncol;
            bf16* lrow = Olo + (size_t)m * ldo + ncol;
#pragma unroll
            for (int j = 0; j < 32; j += 4) {
                __align__(8) bf16 hv[4];
                __align__(8) bf16 lv[4];
#pragma unroll
                for (int t = 0; t < 4; ++t) {
                    bf16 hb_ = __float2bfloat16(o[j + t]);
                    hv[t] = hb_;
                    lv[t] = __float2bfloat16(o[j + t] - __bfloat162float(hb_));
                }
                *reinterpret_cast<uint2*>(hrow + j) = *reinterpret_cast<const uint2*>(hv);
                *reinterpret_cast<uint2*>(lrow + j) = *reinterpret_cast<const uint2*>(lv);
            }
        }
        if (hasT) {
            bf16* th = (bf16*)tsb;
            bf16* tl = (bf16*)(tsb + 65536);
#pragma unroll
            for (int j = 0; j < 32; ++j) {
                const int cidx = colh + qq * 32 + j;
                bf16 hb_ = __float2bfloat16(o[j]);
                th[(size_t)cidx * 128 + mloc] = hb_;
                tl[(size_t)cidx * 128 + mloc] = __float2bfloat16(o[j] - __bfloat162float(hb_));
            }
        }
    }
    if (hasT) {
        __syncthreads();
        const int chunk = tid & 15;
        const int rbase = tid >> 4;
#pragma unroll
        for (int p = 0; p < 16; ++p) {
            const int cidx = p * 16 + rbase;
            uint4 vh = *reinterpret_cast<const uint4*>(tsb + (size_t)cidx * 256 + chunk * 16);
            uint4 vl = *reinterpret_cast<const uint4*>(tsb + 65536 + (size_t)cidx * 256 + chunk * 16);
            *reinterpret_cast<uint4*>(OThi + (size_t)(n0 + cidx) * ldot + m0 + chunk * 8) = vh;
            *reinterpret_cast<uint4*>(OTlo + (size_t)(n0 + cidx) * ldot + m0 + chunk * 8) = vl;
        }
    }
    __syncthreads();
    if (wid == 0) TCGEN05_DEALLOC(tmem, 256);
#undef TCFETCH
#endif
}

// ================= conversion kernels (z-batched) =================
__global__ void conv_k(const float* __restrict__ src, int ld, int R, int C,
                       bf16* __restrict__ hi, bf16* __restrict__ lo, int Cp,
                       i64 srcZ, i64 dstZ)
{
    const i64 z = blockIdx.z;
    src += z * srcZ; hi += z * dstZ; lo += z * dstZ;
    int c = (blockIdx.x * blockDim.x + threadIdx.x) * 4;
    int r = blockIdx.y;
    if (c >= Cp) return;
    __align__(8) bf16 h4[4];
    __align__(8) bf16 l4[4];
    if (r < R && c < C) {
        float4 fv = *reinterpret_cast<const float4*>(src + (size_t)r * ld + c);
        float vv[4] = {fv.x, fv.y, fv.z, fv.w};
#pragma unroll
        for (int j = 0; j < 4; j++) {
            bf16 h = __float2bfloat16(vv[j]);
            h4[j] = h;
            l4[j] = __float2bfloat16(vv[j] - __bfloat162float(h));
        }
    } else {
#pragma unroll
        for (int j = 0; j < 4; j++) { h4[j] = __float2bfloat16(0.f); l4[j] = h4[j]; }
    }
    size_t o = (size_t)r * Cp + c;
    *reinterpret_cast<uint2*>(hi + o) = *reinterpret_cast<const uint2*>(h4);
    *reinterpret_cast<uint2*>(lo + o) = *reinterpret_cast<const uint2*>(l4);
}

__global__ void convT_k(const float* __restrict__ src, int ld, int R, int C,
                        bf16* __restrict__ hi, bf16* __restrict__ lo, int Rp,
                        i64 srcZ, i64 dstZ)
{
    __shared__ float t[32][33];
    const i64 z = blockIdx.z;
    src += z * srcZ; hi += z * dstZ; lo += z * dstZ;
    int c0 = blockIdx.x * 32;
    int r0 = blockIdx.y * 32;
    int tx = threadIdx.x, ty = threadIdx.y;
#pragma unroll
    for (int j = 0; j < 32; j += 8) {
        int r = r0 + ty + j;
        t[ty + j][tx] = (r < R) ? src[(size_t)r * ld + c0 + tx] : 0.f;
    }
    __syncthreads();
#pragma unroll
    for (int j = 0; j < 32; j += 8) {
        float fv = t[tx][ty + j];
        size_t o = (size_t)(c0 + ty + j) * Rp + r0 + tx;
        bf16 h = __float2bfloat16(fv);
        hi[o] = h;
        lo[o] = __float2bfloat16(fv - __bfloat162float(h));
    }
}

// ================= fused activation + transpose kernels (vectorized) =========
__device__ __forceinline__ void split8(const float* v, uint4& hq, uint4& lq)
{
    __align__(16) bf16 hv[8];
    __align__(16) bf16 lv[8];
#pragma unroll
    for (int j = 0; j < 8; ++j) {
        bf16 hb_ = __float2bfloat16(v[j]);
        hv[j] = hb_;
        lv[j] = __float2bfloat16(v[j] - __bfloat162float(hb_));
    }
    hq = *reinterpret_cast<const uint4*>(hv);
    lq = *reinterpret_cast<const uint4*>(lv);
}

__global__ void __launch_bounds__(256) swishT_k(
    const float* __restrict__ kg, const float* __restrict__ kv,
    bf16* __restrict__ hhi, bf16* __restrict__ hlo,
    bf16* __restrict__ thi, bf16* __restrict__ tlo)
{
    __shared__ float t[64][33];
    const int c0 = blockIdx.x * 64;
    const int r0 = blockIdx.y * 32;
    const int tid = threadIdx.x;
    const int cg = tid & 7;
    const int r  = tid >> 3;
    const int row = r0 + r;
    const int col = c0 + cg * 8;

    float h8[8];
    if (row < NTOK) {
        const float* pg = kg + (size_t)row * HIDD + col;
        const float* pv = kv + (size_t)row * HIDD + col;
        float4 g0 = *reinterpret_cast<const float4*>(pg);
        float4 g1 = *reinterpret_cast<const float4*>(pg + 4);
        float4 v0 = *reinterpret_cast<const float4*>(pv);
        float4 v1 = *reinterpret_cast<const float4*>(pv + 4);
        float gs[8] = {g0.x, g0.y, g0.z, g0.w, g1.x, g1.y, g1.z, g1.w};
        float vs[8] = {v0.x, v0.y, v0.z, v0.w, v1.x, v1.y, v1.z, v1.w};
#pragma unroll
        for (int j = 0; j < 8; ++j)
            h8[j] = gs[j] / (1.f + __expf(-gs[j])) * vs[j];
    } else {
#pragma unroll
        for (int j = 0; j < 8; ++j) h8[j] = 0.f;
    }
    {
        uint4 hq, lq;
        split8(h8, hq, lq);
        size_t o = (size_t)row * HIDD + col;
        *reinterpret_cast<uint4*>(hhi + o) = hq;
        *reinterpret_cast<uint4*>(hlo + o) = lq;
    }
    if (thi) {
#pragma unroll
        for (int j = 0; j < 8; ++j) t[cg * 8 + j][r] = h8[j];
        __syncthreads();
        const int orow = tid >> 2;
        const int seg  = tid & 3;
        float v8[8];
#pragma unroll
        for (int j = 0; j < 8; ++j) v8[j] = t[orow][seg * 8 + j];
        uint4 hq, lq;
        split8(v8, hq, lq);
        size_t o = (size_t)(c0 + orow) * MP + r0 + seg * 8;
        *reinterpret_cast<uint4*>(thi + o) = hq;
        *reinterpret_cast<uint4*>(tlo + o) = lq;
    }
}

__global__ void __launch_bounds__(256) bw_ewT_k(
    const float* __restrict__ dh,
    const float* __restrict__ kg, const float* __restrict__ kv,
    bf16* __restrict__ gthi, bf16* __restrict__ gtlo,
    bf16* __restrict__ vthi, bf16* __restrict__ vtlo)
{
    __shared__ float tg[64][33];
    __shared__ float tv[64][33];
    const int c0 = blockIdx.x * 64;
    const int r0 = blockIdx.y * 32;
    const int tid = threadIdx.x;
    const int cg = tid & 7;
    const int r  = tid >> 3;
    const int row = r0 + r;
    const int col = c0 + cg * 8;

    if (row < NTOK) {
        const float* pd = dh + (size_t)row * HIDD + col;
        const float* pg = kg + (size_t)row * HIDD + col;
        const float* pv = kv + (size_t)row * HIDD + col;
        float4 d0 = *reinterpret_cast<const float4*>(pd);
        float4 d1 = *reinterpret_cast<const float4*>(pd + 4);
        float4 g0 = *reinterpret_cast<const float4*>(pg);
        float4 g1 = *reinterpret_cast<const float4*>(pg + 4);
        float4 v0 = *reinterpret_cast<const float4*>(pv);
        float4 v1 = *reinterpret_cast<const float4*>(pv + 4);
        float ds[8] = {d0.x, d0.y, d0.z, d0.w, d1.x, d1.y, d1.z, d1.w};
        float gs[8] = {g0.x, g0.y, g0.z, g0.w, g1.x, g1.y, g1.z, g1.w};
        float vs[8] = {v0.x, v0.y, v0.z, v0.w, v1.x, v1.y, v1.z, v1.w};
#pragma unroll
        for (int j = 0; j < 8; ++j) {
            float s = 1.f / (1.f + __expf(-gs[j]));
            tv[cg * 8 + j][r] = ds[j] * gs[j] * s;
            tg[cg * 8 + j][r] = ds[j] * vs[j] * s * (1.f + gs[j] * (1.f - s));
        }
    } else {
#pragma unroll
        for (int j = 0; j < 8; ++j) { tg[cg * 8 + j][r] = 0.f; tv[cg * 8 + j][r] = 0.f; }
    }
    __syncthreads();
    const int orow = tid >> 2;
    const int seg  = tid & 3;
    const size_t o = (size_t)(c0 + orow) * MP + r0 + seg * 8;
    {
        float v8[8];
#pragma unroll
        for (int j = 0; j < 8; ++j) v8[j] = tg[orow][seg * 8 + j];
        uint4 hq, lq;
        split8(v8, hq, lq);
        *reinterpret_cast<uint4*>(gthi + o) = hq;
        *reinterpret_cast<uint4*>(gtlo + o) = lq;
    }
    {
        float v8[8];
#pragma unroll
        for (int j = 0; j < 8; ++j) v8[j] = tv[orow][seg * 8 + j];
        uint4 hq, lq;
        split8(v8, hq, lq);
        *reinterpret_cast<uint4*>(vthi + o) = hq;
        *reinterpret_cast<uint4*>(vtlo + o) = lq;
    }
}

// ================= elementwise / reductions =================
__global__ void norm_heads_k(float* __restrict__ base,
                             const float* __restrict__ sc, const float* __restrict__ bi)
{
    int w = (blockIdx.x * blockDim.x + threadIdx.x) >> 5;
    int lane = threadIdx.x & 31;
    if (w >= NTOK * 16) return;
    int rowi = w >> 4, head = w & 15;
    float* p = base + (size_t)rowi * (3 * DIMM) + head * 64;
    float x0 = p[lane], x1 = p[lane + 32];
    float ss = x0 * x0 + x1 * x1;
#pragma unroll
    for (int o = 16; o; o >>= 1) ss += __shfl_xor_sync(0xffffffffu, ss, o);
    float inv = 1.f / (sqrtf(ss) + 1e-6f);
    p[lane]      = x0 * inv * sc[lane]      + bi[lane];
    p[lane + 32] = x1 * inv * sc[lane + 32] + bi[lane + 32];
}

__global__ void zero3_k(double* p) { if (threadIdx.x < 3) p[threadIdx.x] = 0.0; }

__global__ void sumsq3_k(const float* __restrict__ x, int n, double* __restrict__ out)
{
    __shared__ double sm[256];
    const int z = blockIdx.y;
    x += (size_t)z * n;
    double a = 0.0;
    for (int i = blockIdx.x * blockDim.x + threadIdx.x; i < n; i += gridDim.x * blockDim.x) {
        float fv = x[i];
        a += (double)fv * (double)fv;
    }
    sm[threadIdx.x] = a;
    __syncthreads();
    for (int s = 128; s; s >>= 1) {
        if (threadIdx.x < s) sm[threadIdx.x] += sm[threadIdx.x + s];
        __syncthreads();
    }
    if (threadIdx.x == 0) atomicAdd(&out[z], sm[0]);
}

__global__ void scale3_k(const float4* __restrict__ g, float4* __restrict__ X, int n4,
                         const double* __restrict__ nrm)
{
    const int z = blockIdx.y;
    int i = blockIdx.x * blockDim.x + threadIdx.x;
    if (i >= n4) return;
    float inv = (float)(1.0 / (sqrt(nrm[z]) + 1e-7));
    float4 fv = g[(size_t)z * n4 + i];
    fv.x *= inv; fv.y *= inv; fv.z *= inv; fv.w *= inv;
    X[(size_t)z * n4 + i] = fv;
}

__global__ void transpose_k(const float* __restrict__ src, float* __restrict__ dst,
                            int R, int C)
{
    __shared__ float t[32][33];
    int c0 = blockIdx.x * 32, r0 = blockIdx.y * 32;
    int x = c0 + threadIdx.x;
#pragma unroll
    for (int j = 0; j < 32; j += 8)
        t[threadIdx.y + j][threadIdx.x] = src[(size_t)(r0 + threadIdx.y + j) * C + x];
    __syncthreads();
    int x2 = r0 + threadIdx.x;
#pragma unroll
    for (int j = 0; j < 32; j += 8)
        dst[(size_t)(c0 + threadIdx.y + j) * R + x2] = t[threadIdx.x][threadIdx.y + j];
}

__global__ void upd_k(float4* __restrict__ p, const float4* __restrict__ x, int n4)
{
    int i = blockIdx.x * blockDim.x + threadIdx.x;
    if (i >= n4) return;
    float4 a = p[i], bb = x[i];
    a.x -= LRATE * bb.x; a.y -= LRATE * bb.y; a.z -= LRATE * bb.z; a.w -= LRATE * bb.w;
    p[i] = a;
}

// ================= host orchestration =================
struct BP { bf16 *hi, *lo; };

static void* symaddr(const void* s) { void* p = nullptr; cudaGetSymbolAddress(&p, s); return p; }

static void tc(BP A, BP B, int Kp, float* C, int ldc, int M, int N,
               float alpha, float beta, const float* E, int ldE,
               int nz = 1, i64 az = 0, i64 bz = 0, i64 cz = 0, i64 ez = 0,
               BP O = {nullptr, nullptr}, int ldo = 0, i64 oz = 0,
               BP OT = {nullptr, nullptr}, int ldot = 0, i64 ozt = 0,
               int terms = 3)
{
    dim3 gr(N / 256, (M + 127) / 128, nz);
    tc_gemm<<<gr, 256, TC_SMEM>>>(A.hi, A.lo, B.hi, B.lo, Kp, C, ldc, E, ldE,
                                  alpha, beta, M, az, bz, cz, ez, O.hi, O.lo, ldo, oz,
                                  OT.hi, OT.lo, ldot, ozt, terms);
}

static void conv(const float* s, int ld, int R, int C, BP d, int Rp, int Cp,
                 int nz = 1, i64 sZ = 0, i64 dZ = 0)
{
    dim3 gr((Cp / 4 + 255) / 256, Rp, nz);
    conv_k<<<gr, 256>>>(s, ld, R, C, d.hi, d.lo, Cp, sZ, dZ);
}

static void convT(const float* s, int ld, int R, int C, BP d, int Rp,
                  int nz = 1, i64 sZ = 0, i64 dZ = 0)
{
    dim3 gr(C / 32, Rp / 32, nz);
    convT_k<<<gr, dim3(32, 8)>>>(s, ld, R, C, d.hi, d.lo, Rp, sZ, dZ);
}

extern "C" void kernel_launch(void* const* d_in, const int* in_sizes, int n_in,
                              void* d_out, int out_size)
{
    const float* x        = (const float*)d_in[0];
    const float* qkv_w    = (const float*)d_in[1];
    const float* qkv_b    = (const float*)d_in[2];
    const float* qn_s     = (const float*)d_in[3];
    const float* qn_b     = (const float*)d_in[4];
    const float* kn_s     = (const float*)d_in[5];
    const float* kn_b     = (const float*)d_in[6];
    const float* ttt_gate = (const float*)d_in[7];
    const float* ttt_val  = (const float*)d_in[8];
    const float* ttt_proj = (const float*)d_in[9];
    const float* proj_w   = (const float*)d_in[10];
    const float* proj_b   = (const float*)d_in[11];
    float* out = (float*)d_out;

    cudaFuncSetAttribute(tc_gemm, cudaFuncAttributeMaxDynamicSharedMemorySize, TC_SMEM);

    float* qkv  = (float*)symaddr(g_qkv);
    float* kgv  = (float*)symaddr(g_kgv);
    float* h    = (float*)symaddr(g_h);
    float* GV   = (float*)symaddr(g_GV);
    float* P    = (float*)symaddr(g_P);
    float* grad = (float*)symaddr(g_grad);
    float* X1   = (float*)symaddr(g_X1);
    float* X2   = (float*)symaddr(g_X2);
    float* Amat = (float*)symaddr(g_A);
    double* nrm = (double*)symaddr(g_nrm);
    unsigned char* pool = (unsigned char*)symaddr(g_bf);

    auto bp = [&](size_t off, size_t elems) { BP b; b.hi = (bf16*)(pool + off); b.lo = b.hi + elems; return b; };

    BP xb    = bp(O_X, E_TOKD);
    BP kb    = bp(O_K, E_TOKD);
    BP kTb   = bp(O_KT, E_TOKD);
    BP qb    = bp(O_Q, E_TOKD);
    BP rTb   = bp(O_RT, E_TOKD);
    BP hb    = bp(O_H, E_TOKH);
    BP hTb   = bp(O_HT, E_TOKH);
    BP dkgT  = bp(O_DKGT, E_TOKH);
    BP dkvT  = bp(O_DKVT, E_TOKH);
    BP wGt   = bp(O_WGT, E_W);
    BP wP    = bp(O_WP,  E_W);
    BP wPt   = bp(O_WPT, E_W);
    BP qkvwT = bp(O_QKVW, E_QKVW);
    BP projwT = bp(O_PRJW, E_A);
    BP nsX   = bp(O_NSX,  E_W);
    BP nsXTa = bp(O_NSXT, E_W);
    BP nsXTb = bp(O_NSXT2, E_W);
    BP nsA   = bp(O_NSA,  E_A);
    BP nsA2  = bp(O_NSA2, E_A);
    BP NOB   = {nullptr, nullptr};

    const size_t TB = sizeof(float) * E_W;
    cudaMemcpyAsync(GV,       ttt_gate, TB, cudaMemcpyDeviceToDevice, 0);
    cudaMemcpyAsync(GV + E_W, ttt_val,  TB, cudaMemcpyDeviceToDevice, 0);
    cudaMemcpyAsync(P,        ttt_proj, TB, cudaMemcpyDeviceToDevice, 0);

    // ---- qkv = x @ qkv_w + b ----
    conv (x, DIMM, NTOK, DIMM, xb, MP, DIMM);
    convT(qkv_w, 3 * DIMM, DIMM, 3 * DIMM, qkvwT, DIMM);
    tc(xb, qkvwT, DIMM, qkv, 3 * DIMM, NTOK, 3 * DIMM, 1.f, 1.f, qkv_b, 0);

    {
        int nb = (NTOK * 16 * 32 + 255) / 256;
        norm_heads_k<<<nb, 256>>>(qkv, qn_s, qn_b);
        norm_heads_k<<<nb, 256>>>(qkv + DIMM, kn_s, kn_b);
    }

    const float* kmat = qkv + DIMM;
    const float* vmat = qkv + 2 * DIMM;
    conv (kmat, 3 * DIMM, NTOK, DIMM, kb, MP, DIMM);
    convT(kmat, 3 * DIMM, NTOK, DIMM, kTb, MP);
    conv (qkv, 3 * DIMM, NTOK, DIMM, qb, MP, DIMM);

    const dim3 grTH(HIDD / 64, MP / 32);
    const i64 ZW = 2 * (i64)E_W;
    const i64 ZA = 2 * (i64)E_A;
    const i64 KGV = (i64)NTOK * HIDD;

    for (int step = 0; step < 2; ++step) {
        convT(GV, HIDD, DIMM, HIDD, wGt, DIMM, 2, (i64)E_W, ZW);
        conv (P, DIMM, HIDD, DIMM, wP, HIDD, DIMM);
        convT(P, DIMM, HIDD, DIMM, wPt, HIDD);

        // kg|kv = k @ {G,V}
        tc(kb, wGt, DIMM, kgv, HIDD, NTOK, HIDD, 1.f, 0.f, nullptr, 0,
           2, 0, ZW, KGV, 0);
        swishT_k<<<grTH, 256>>>(kgv, kgv + KGV, hb.hi, hb.lo, hTb.hi, hTb.lo);
        // r = h @ P - v : pairs (xb) + transposed pairs (rTb), no fp32 C
        tc(hb, wPt, HIDD, nullptr, 0, NTOK, DIMM, 1.f, -1.f, vmat, 3 * DIMM,
           1, 0, 0, 0, 0, xb, DIMM, 0, rTb, MP, 0);
        // gP^T = r^T @ h
        tc(rTb, hTb, MP, grad + 2 * E_W, HIDD, DIMM, HIDD, 1.f, 0.f, nullptr, 0);
        // dh = r @ P^T  -> h buffer
        tc(xb, wP, DIMM, h, HIDD, NTOK, HIDD, 1.f, 0.f, nullptr, 0);
        bw_ewT_k<<<grTH, 256>>>(h, kgv, kgv + KGV,
                                dkgT.hi, dkgT.lo, dkvT.hi, dkvT.lo);
        // gG|gV = k^T @ {dkg,dkv}
        tc(kTb, dkgT, MP, grad, HIDD, DIMM, HIDD, 1.f, 0.f, nullptr, 0,
           2, 0, 2 * (i64)E_TOKH, (i64)E_W, 0);

        // ---- batched Newton-Schulz over {gG, gV, gP^T} ----
        zero3_k<<<1, 4>>>(nrm);
        sumsq3_k<<<dim3(256, 3), 256>>>(grad, (int)E_W, nrm);
        scale3_k<<<dim3(((int)E_W / 4 + 255) / 256, 3), 256>>>(
            (const float4*)grad, (float4*)X1, (int)E_W / 4, nrm);
        float* X = X1;
        float* Y = X2;
        conv (X, HIDD, DIMM, HIDD, nsX, DIMM, HIDD, 3, (i64)E_W, ZW);
        convT(X, HIDD, DIMM, HIDD, nsXTa, DIMM, 3, (i64)E_W, ZW);
        for (int it = 0; it < 5; ++it) {
            BP XTin  = (it & 1) ? nsXTb : nsXTa;
            BP XTout = (it & 1) ? nsXTa : nsXTb;
            // early iterations: hi-only MMA (NS damps the error); last two: full split
            const int tm = (it < 3) ? 1 : 3;
            tc(nsX, nsX, HIDD, Amat, DIMM, DIMM, DIMM, 1.f, 0.f, nullptr, 0,
               3, ZW, ZW, (i64)E_A, 0, nsA, DIMM, ZA, NOB, 0, 0, tm);
            tc(nsA, nsA, DIMM, nullptr, 0, DIMM, DIMM, NS_C, NS_B, Amat, DIMM,
               3, ZA, ZA, 0, (i64)E_A, nsA2, DIMM, ZA, NOB, 0, 0, tm);
            tc(nsA2, XTin, DIMM, Y, HIDD, DIMM, HIDD, 1.f, NS_A, X, HIDD,
               3, ZA, ZW, (i64)E_W, (i64)E_W, nsX, HIDD, ZW,
               (it < 4) ? XTout : NOB, DIMM, ZW, tm);
            float* t = X; X = Y; Y = t;
        }
        upd_k<<<((int)(2 * E_W / 4) + 255) / 256, 256>>>((float4*)GV, (const float4*)X, (int)(2 * E_W / 4));
        {
            dim3 gr(HIDD / 32, DIMM / 32);
            transpose_k<<<gr, dim3(32, 8)>>>(X + 2 * E_W, Y, DIMM, HIDD);
            upd_k<<<((int)(E_W / 4) + 255) / 256, 256>>>((float4*)P, (const float4*)Y, (int)(E_W / 4));
        }
    }

    // ---- final forward with q ----
    convT(GV, HIDD, DIMM, HIDD, wGt, DIMM, 2, (i64)E_W, ZW);
    convT(P, DIMM, HIDD, DIMM, wPt, HIDD);
    tc(qb, wGt, DIMM, kgv, HIDD, NTOK, HIDD, 1.f, 0.f, nullptr, 0,
       2, 0, ZW, KGV, 0);
    swishT_k<<<grTH, 256>>>(kgv, kgv + KGV, hb.hi, hb.lo, nullptr, nullptr);
    tc(hb, wPt, HIDD, nullptr, 0, NTOK, DIMM, 1.f, 0.f, nullptr, 0,
       1, 0, 0, 0, 0, xb, DIMM, 0);
    convT(proj_w, DIMM, DIMM, DIMM, projwT, DIMM);
    tc(xb, projwT, DIMM, out, DIMM, NTOK, DIMM, 1.f, 1.f, proj_b, 0);
}

// round 17
// speedup vs baseline: 8.0735x; 1.0024x over previous
#include <cuda_runtime.h>
#include <cuda_bf16.h>
#include <cstdint>
#include <cstddef>

// ---------------- problem constants ----------------
#define NTOK 10992
#define MP   11008
#define DIMM 1024
#define HIDD 4096
#define LRATE 0.1f
#define NS_A 3.4445f
#define NS_B (-4.7750f)
#define NS_C 2.0315f

typedef unsigned long long u64;
typedef long long i64;
typedef __nv_bfloat16 bf16;

#if !defined(__CUDA_ARCH__) || defined(__CUDA_ARCH_FEAT_SM103_ALL)
#define TC_HAS_TCGEN05 1
#else
#define TC_HAS_TCGEN05 0
#endif

// ================= PTX helpers (sm_103a) =================
#if TC_HAS_TCGEN05
__device__ __forceinline__ uint32_t smem_u32(const void* p) {
    uint32_t a;
    asm("{ .reg .u64 t; cvta.to.shared.u64 t, %1; cvt.u32.u64 %0, t; }" : "=r"(a) : "l"(p));
    return a;
}
__device__ __forceinline__ uint32_t elect1() {
    uint32_t p;
    asm volatile("{\n.reg .pred p;\nelect.sync _|p, 0xFFFFFFFF;\nselp.b32 %0,1,0,p;\n}" : "=r"(p));
    return p;
}
#define MBARRIER_INIT(a, c) \
    asm volatile("mbarrier.init.shared.b64 [%0], %1;" :: "r"((uint32_t)(a)), "r"((uint32_t)(c)) : "memory")
#define MBARRIER_WAIT_PARITY(a, ph) do { \
    uint32_t _m = (uint32_t)(a); uint32_t _p = (uint32_t)(ph); uint32_t _d; \
    asm volatile("{\n.reg .pred p;\nmbarrier.try_wait.parity.acquire.cta.shared::cta.b64 p, [%1], %2;\nselp.b32 %0,1,0,p;\n}" \
        : "=r"(_d) : "r"(_m), "r"(_p) : "memory"); \
    if (!_d) { \
        asm volatile("{\n.reg .pred P1;\nWL_%=:\nmbarrier.try_wait.parity.acquire.cta.shared::cta.b64 P1, [%0], %1, 0x989680;\n@P1 bra.uni WD_%=;\nbra.uni WL_%=;\nWD_%=:\n}" \
            :: "r"(_m), "r"(_p) : "memory"); \
    } } while (0)
#define TCGEN05_ALLOC(sa, n) \
    asm volatile("tcgen05.alloc.cta_group::1.sync.aligned.shared::cta.b32 [%0], %1;" \
        :: "r"((uint32_t)(sa)), "r"((uint32_t)(n)) : "memory")
#define TCGEN05_RELINQ() \
    asm volatile("tcgen05.relinquish_alloc_permit.cta_group::1.sync.aligned;")
#define TCGEN05_DEALLOC(t, n) \
    asm volatile("tcgen05.dealloc.cta_group::1.sync.aligned.b32 %0, %1;" :: "r"(t), "r"((uint32_t)(n)))
#define TCGEN05_COMMIT(a) \
    asm volatile("tcgen05.commit.cta_group::1.mbarrier::arrive::one.shared::cluster.b64 [%0];" \
        :: "r"((uint32_t)(a)) : "memory")
#define TCGEN05_FENCE_AFTER() asm volatile("tcgen05.fence::after_thread_sync;" ::: "memory")
#define TCGEN05_WAIT_LD() asm volatile("tcgen05.wait::ld.sync.aligned;" ::: "memory")
#define FENCE_ASYNC() asm volatile("fence.proxy.async.shared::cta;" ::: "memory")
#define STS128(r0, r1, r2, r3, a) \
    asm volatile("st.shared.v4.b32 [%0], {%1,%2,%3,%4};" :: "r"(a), "r"(r0), "r"(r1), "r"(r2), "r"(r3) : "memory")
#define TCGEN05_LD_X32(r, ta) \
    asm volatile("tcgen05.ld.sync.aligned.32x32b.x32.b32 " \
        "{%0,%1,%2,%3,%4,%5,%6,%7,%8,%9,%10,%11,%12,%13,%14,%15," \
        "%16,%17,%18,%19,%20,%21,%22,%23,%24,%25,%26,%27,%28,%29,%30,%31}, [%32];" \
        : "=r"((r)[0]), "=r"((r)[1]), "=r"((r)[2]), "=r"((r)[3]), "=r"((r)[4]), "=r"((r)[5]), \
          "=r"((r)[6]), "=r"((r)[7]), "=r"((r)[8]), "=r"((r)[9]), "=r"((r)[10]), "=r"((r)[11]), \
          "=r"((r)[12]), "=r"((r)[13]), "=r"((r)[14]), "=r"((r)[15]), "=r"((r)[16]), "=r"((r)[17]), \
          "=r"((r)[18]), "=r"((r)[19]), "=r"((r)[20]), "=r"((r)[21]), "=r"((r)[22]), "=r"((r)[23]), \
          "=r"((r)[24]), "=r"((r)[25]), "=r"((r)[26]), "=r"((r)[27]), "=r"((r)[28]), "=r"((r)[29]), \
          "=r"((r)[30]), "=r"((r)[31]) : "r"(ta))

static constexpr u64 SMEM_DESC_BASE =
    (u64(2) << 61) | (u64(1) << 46) | (u64(64) << 32) | (u64(1) << 16);
__device__ __forceinline__ u64 mkdesc(uint32_t sa) {
    return SMEM_DESC_BASE | ((u64)(sa >> 4) & 0x3FFF);
}
__device__ __forceinline__ void mma_f16_ss(uint32_t d, u64 ad, u64 bd, uint32_t idesc, bool acc) {
    uint32_t en = acc ? 1u : 0u;
    asm volatile(
        "{\n\t.reg .pred p;\n\tsetp.ne.u32 p, %4, 0;\n\t"
        "tcgen05.mma.cta_group::1.kind::f16 [%0], %1, %2, %3, {%5,%5,%5,%5}, p;\n\t}"
        :: "r"(d), "l"(ad), "l"(bd), "r"(idesc), "r"(en), "r"(0u) : "memory");
}
#endif

#define SWZ(b) ((b) ^ (((b) >> 3) & 0x70))
#define TCIDESC 0x08200490u   // dtype=F32, a=BF16, b=BF16, N=128, M=128

// ---------------- fp32 scratch ----------------
static constexpr size_t E_TOKD = (size_t)MP * DIMM;
static constexpr size_t E_TOKH = (size_t)MP * HIDD;
static constexpr size_t E_W    = (size_t)DIMM * HIDD;
static constexpr size_t E_A    = (size_t)DIMM * DIMM;
static constexpr size_t E_QKVW = (size_t)DIMM * 3 * DIMM;

__device__ float g_qkv [(size_t)NTOK * 3 * DIMM];
__device__ float g_kgv [(size_t)2 * NTOK * HIDD];
__device__ float g_h   [(size_t)NTOK * HIDD];
__device__ float g_GV  [2 * E_W];
__device__ float g_P   [E_W];
__device__ float g_grad[3 * E_W];
__device__ float g_X1  [3 * E_W];
__device__ float g_X2  [3 * E_W];
__device__ float g_A   [3 * E_A];
__device__ double g_nrm[3];

// ---------------- bf16 hi/lo pool ----------------
static constexpr size_t O_X     = 0;
static constexpr size_t O_K     = O_X     + E_TOKD * 4;
static constexpr size_t O_KT    = O_K     + E_TOKD * 4;
static constexpr size_t O_Q     = O_KT    + E_TOKD * 4;
static constexpr size_t O_RT    = O_Q     + E_TOKD * 4;
static constexpr size_t O_H     = O_RT    + E_TOKD * 4;
static constexpr size_t O_HT    = O_H     + E_TOKH * 4;
static constexpr size_t O_DKGT  = O_HT    + E_TOKH * 4;
static constexpr size_t O_DKVT  = O_DKGT  + E_TOKH * 4;
static constexpr size_t O_WGT   = O_DKVT  + E_TOKH * 4;
static constexpr size_t O_WVT   = O_WGT   + E_W * 4;
static constexpr size_t O_WP    = O_WVT   + E_W * 4;
static constexpr size_t O_WPT   = O_WP    + E_W * 4;
static constexpr size_t O_QKVW  = O_WPT   + E_W * 4;
static constexpr size_t O_PRJW  = O_QKVW  + E_QKVW * 4;
static constexpr size_t O_NSX   = O_PRJW  + E_A * 4;
static constexpr size_t O_NSXT  = O_NSX   + 3 * E_W * 4;
static constexpr size_t O_NSXT2 = O_NSXT  + 3 * E_W * 4;
static constexpr size_t O_NSA   = O_NSXT2 + 3 * E_W * 4;
static constexpr size_t O_NSA2  = O_NSA   + 3 * E_A * 4;
static constexpr size_t POOL_B  = O_NSA2  + 3 * E_A * 4;
__device__ __align__(1024) unsigned char g_bf[POOL_B];

// ============ tcgen05 split-bf16 GEMM: 128x256 tile, cg1, double-buffered ======
// terms==3: full hi/lo split. terms==1: hi*hi only (lo staging skipped).
#define TC_STAGE 98304
#define TC_SMEM  (2 * TC_STAGE + 1024)

__global__ void __launch_bounds__(256, 1) tc_gemm(
    const bf16* __restrict__ Ahi, const bf16* __restrict__ Alo,
    const bf16* __restrict__ Bhi, const bf16* __restrict__ Blo,
    int Kp, float* __restrict__ C, int ldc,
    const float* __restrict__ E, int ldE,
    float alpha, float beta, int M,
    i64 az, i64 bz, i64 cz, i64 ez,
    bf16* __restrict__ Ohi, bf16* __restrict__ Olo, int ldo, i64 oz,
    bf16* __restrict__ OThi, bf16* __restrict__ OTlo, int ldot, i64 ozt,
    int terms)
{
#if TC_HAS_TCGEN05
    extern __shared__ unsigned char dsm_raw[];
    __shared__ __align__(8) u64 s_mb[2];
    __shared__ uint32_t s_tmem[1];

    const int tid = threadIdx.x;
    const int wid = tid >> 5;
    const int lane = tid & 31;
    const i64 zz = blockIdx.z;
    Ahi += zz * az; Alo += zz * az;
    Bhi += zz * bz; Blo += zz * bz;
    if (C)    C    += zz * cz;
    if (E)    E    += zz * ez;
    if (Ohi)  { Ohi  += zz * oz;  Olo  += zz * oz; }
    if (OThi) { OThi += zz * ozt; OTlo += zz * ozt; }
    const bool full = (terms == 3);

    const uint32_t sb  = (smem_u32(dsm_raw) + 1023) & ~1023u;
    const uint32_t mbB = smem_u32(&s_mb[0]);
    unsigned char* tsb = (unsigned char*)(((uintptr_t)dsm_raw + 1023) & ~(uintptr_t)1023);

    if (tid == 0) { MBARRIER_INIT(mbB, 1); MBARRIER_INIT(mbB + 8, 1); }
    if (wid == 0) {
        TCGEN05_ALLOC(smem_u32(s_tmem), 256);
        TCGEN05_RELINQ();
    }
    __syncthreads();
    const uint32_t tmem = s_tmem[0];

    const int m0 = blockIdx.y * 128;
    const int n0 = blockIdx.x * 256;

    const int r0    = tid >> 3;
    const int col16 = (tid & 7) * 16;
    const size_t rowB = (size_t)Kp * 2;
    const char* pAhi = (const char*)Ahi + (size_t)(m0 + r0) * rowB + col16;
    const char* pAlo = (const char*)Alo + (size_t)(m0 + r0) * rowB + col16;
    const char* pBhi = (const char*)Bhi + (size_t)(n0 + r0) * rowB + col16;
    const char* pBlo = (const char*)Blo + (size_t)(n0 + r0) * rowB + col16;
    uint32_t swA[4], swB[8];
#pragma unroll
    for (int k = 0; k < 4; ++k) swA[k] = SWZ((uint32_t)(r0 + 32 * k) * 128 + col16);
#pragma unroll
    for (int k = 0; k < 8; ++k) swB[k] = SWZ((uint32_t)(r0 + 32 * k) * 128 + col16);

    uint4 va[8], vb[16];
#define TCFETCH(cc) do { const size_t gb_ = (size_t)(cc) * 128;                         \
    _Pragma("unroll") for (int k_ = 0; k_ < 4; ++k_)                                    \
        va[k_] = *reinterpret_cast<const uint4*>(pAhi + (size_t)(32 * k_) * rowB + gb_); \
    _Pragma("unroll") for (int k_ = 0; k_ < 8; ++k_)                                    \
        vb[k_] = *reinterpret_cast<const uint4*>(pBhi + (size_t)(32 * k_) * rowB + gb_); \
    if (full) {                                                                          \
        _Pragma("unroll") for (int k_ = 0; k_ < 4; ++k_)                                 \
            va[4 + k_] = *reinterpret_cast<const uint4*>(pAlo + (size_t)(32 * k_) * rowB + gb_); \
        _Pragma("unroll") for (int k_ = 0; k_ < 8; ++k_)                                 \
            vb[8 + k_] = *reinterpret_cast<const uint4*>(pBlo + (size_t)(32 * k_) * rowB + gb_); \
    } } while (0)

    const int NC = Kp >> 6;
    TCFETCH(0);
    for (int c = 0; c < NC; ++c) {
        const int s = c & 1;
        const int phase = c >> 1;
        const uint32_t mbs = mbB + (uint32_t)s * 8;
        const uint32_t stg = sb + (uint32_t)s * TC_STAGE;
        if (c >= 2) { MBARRIER_WAIT_PARITY(mbs, (phase - 1) & 1); }
#pragma unroll
        for (int k = 0; k < 4; ++k)
            STS128(va[k].x, va[k].y, va[k].z, va[k].w, stg + swA[k]);
#pragma unroll
        for (int k = 0; k < 8; ++k)
            STS128(vb[k].x, vb[k].y, vb[k].z, vb[k].w, stg + 32768u + swB[k]);
        if (full) {
#pragma unroll
            for (int k = 0; k < 4; ++k)
                STS128(va[4 + k].x, va[4 + k].y, va[4 + k].z, va[4 + k].w, stg + 16384u + swA[k]);
#pragma unroll
            for (int k = 0; k < 8; ++k)
                STS128(vb[8 + k].x, vb[8 + k].y, vb[8 + k].z, vb[8 + k].w, stg + 65536u + swB[k]);
        }
        if (c + 1 < NC) { TCFETCH(c + 1); }
        FENCE_ASYNC();
        __syncthreads();
        if (wid == 0 && elect1()) {
            u64 aH = mkdesc(stg);
            u64 aL = mkdesc(stg + 16384);
#pragma unroll
            for (int nh = 0; nh < 2; ++nh) {
                const uint32_t d = tmem + (uint32_t)nh * 128;
                u64 bH = mkdesc(stg + 32768 + (uint32_t)nh * 16384);
                u64 bL = mkdesc(stg + 65536 + (uint32_t)nh * 16384);
#pragma unroll
                for (int ks = 0; ks < 4; ++ks)
                    mma_f16_ss(d, aH + ks * 2, bH + ks * 2, TCIDESC, !(c == 0 && ks == 0));
                if (full) {
#pragma unroll
                    for (int ks = 0; ks < 4; ++ks)
                        mma_f16_ss(d, aH + ks * 2, bL + ks * 2, TCIDESC, true);
#pragma unroll
                    for (int ks = 0; ks < 4; ++ks)
                        mma_f16_ss(d, aL + ks * 2, bH + ks * 2, TCIDESC, true);
                }
            }
            TCGEN05_COMMIT(mbs);
        }
    }
    {
        const int cl = NC - 1;
        MBARRIER_WAIT_PARITY(mbB + (uint32_t)(cl & 1) * 8, (cl >> 1) & 1);
    }
    TCGEN05_FENCE_AFTER();

    const bool hasT = (OThi != nullptr);
    const int sub = wid & 3;
    const int colh = (wid >> 2) * 128;
    const int mloc = sub * 32 + lane;
    const int m = m0 + mloc;
#pragma unroll
    for (int qq = 0; qq < 4; ++qq) {
        uint32_t r32[32];
        TCGEN05_LD_X32(r32, tmem + colh + qq * 32);
        TCGEN05_WAIT_LD();
        const int ncol = n0 + colh + qq * 32;
        float o[32];
        if (m < M) {
            if (beta != 0.f) {
                const float* erow = E + (size_t)m * ldE + ncol;
#pragma unroll
                for (int j = 0; j < 32; j += 4) {
                    float4 e = *reinterpret_cast<const float4*>(erow + j);
                    o[j]     = alpha * __uint_as_float(r32[j])     + beta * e.x;
                    o[j + 1] = alpha * __uint_as_float(r32[j + 1]) + beta * e.y;
                    o[j + 2] = alpha * __uint_as_float(r32[j + 2]) + beta * e.z;
                    o[j + 3] = alpha * __uint_as_float(r32[j + 3]) + beta * e.w;
                }
            } else {
#pragma unroll
                for (int j = 0; j < 32; ++j) o[j] = alpha * __uint_as_float(r32[j]);
            }
        } else {
#pragma unroll
            for (int j = 0; j < 32; ++j) o[j] = 0.f;
        }
        if (m < M && C) {
            float* crow = C + (size_t)m * ldc + ncol;
#pragma unroll
            for (int j = 0; j < 32; j += 4)
                *reinterpret_cast<float4*>(crow + j) = make_float4(o[j], o[j+1], o[j+2], o[j+3]);
        }
        if (m < M && Ohi) {
            bf16* hrow = Ohi + (size_t)m * ldo + ncol;
            bf16* lrow = Olo + (size_t)m * ldo + ncol;
#pragma unroll
            for (int j = 0; j < 32; j += 4) {
                __align__(8) bf16 hv[4];
                __align__(8) bf16 lv[4];
#pragma unroll
                for (int t = 0; t < 4; ++t) {
                    bf16 hb_ = __float2bfloat16(o[j + t]);
                    hv[t] = hb_;
                    lv[t] = __float2bfloat16(o[j + t] - __bfloat162float(hb_));
                }
                *reinterpret_cast<uint2*>(hrow + j) = *reinterpret_cast<const uint2*>(hv);
                *reinterpret_cast<uint2*>(lrow + j) = *reinterpret_cast<const uint2*>(lv);
            }
        }
        if (hasT) {
            bf16* th = (bf16*)tsb;
            bf16* tl = (bf16*)(tsb + 65536);
#pragma unroll
            for (int j = 0; j < 32; ++j) {
                const int cidx = colh + qq * 32 + j;
                bf16 hb_ = __float2bfloat16(o[j]);
                th[(size_t)cidx * 128 + mloc] = hb_;
                tl[(size_t)cidx * 128 + mloc] = __float2bfloat16(o[j] - __bfloat162float(hb_));
            }
        }
    }
    if (hasT) {
        __syncthreads();
        const int chunk = tid & 15;
        const int rbase = tid >> 4;
#pragma unroll
        for (int p = 0; p < 16; ++p) {
            const int cidx = p * 16 + rbase;
            uint4 vh = *reinterpret_cast<const uint4*>(tsb + (size_t)cidx * 256 + chunk * 16);
            uint4 vl = *reinterpret_cast<const uint4*>(tsb + 65536 + (size_t)cidx * 256 + chunk * 16);
            *reinterpret_cast<uint4*>(OThi + (size_t)(n0 + cidx) * ldot + m0 + chunk * 8) = vh;
            *reinterpret_cast<uint4*>(OTlo + (size_t)(n0 + cidx) * ldot + m0 + chunk * 8) = vl;
        }
    }
    __syncthreads();
    if (wid == 0) TCGEN05_DEALLOC(tmem, 256);
#undef TCFETCH
#endif
}

// ================= conversion kernels (z-batched; used for initial prep) =====
__global__ void conv_k(const float* __restrict__ src, int ld, int R, int C,
                       bf16* __restrict__ hi, bf16* __restrict__ lo, int Cp,
                       i64 srcZ, i64 dstZ)
{
    const i64 z = blockIdx.z;
    src += z * srcZ; hi += z * dstZ; lo += z * dstZ;
    int c = (blockIdx.x * blockDim.x + threadIdx.x) * 4;
    int r = blockIdx.y;
    if (c >= Cp) return;
    __align__(8) bf16 h4[4];
    __align__(8) bf16 l4[4];
    if (r < R && c < C) {
        float4 fv = *reinterpret_cast<const float4*>(src + (size_t)r * ld + c);
        float vv[4] = {fv.x, fv.y, fv.z, fv.w};
#pragma unroll
        for (int j = 0; j < 4; j++) {
            bf16 h = __float2bfloat16(vv[j]);
            h4[j] = h;
            l4[j] = __float2bfloat16(vv[j] - __bfloat162float(h));
        }
    } else {
#pragma unroll
        for (int j = 0; j < 4; j++) { h4[j] = __float2bfloat16(0.f); l4[j] = h4[j]; }
    }
    size_t o = (size_t)r * Cp + c;
    *reinterpret_cast<uint2*>(hi + o) = *reinterpret_cast<const uint2*>(h4);
    *reinterpret_cast<uint2*>(lo + o) = *reinterpret_cast<const uint2*>(l4);
}

__global__ void convT_k(const float* __restrict__ src, int ld, int R, int C,
                        bf16* __restrict__ hi, bf16* __restrict__ lo, int Rp,
                        i64 srcZ, i64 dstZ)
{
    __shared__ float t[32][33];
    const i64 z = blockIdx.z;
    src += z * srcZ; hi += z * dstZ; lo += z * dstZ;
    int c0 = blockIdx.x * 32;
    int r0 = blockIdx.y * 32;
    int tx = threadIdx.x, ty = threadIdx.y;
#pragma unroll
    for (int j = 0; j < 32; j += 8) {
        int r = r0 + ty + j;
        t[ty + j][tx] = (r < R) ? src[(size_t)r * ld + c0 + tx] : 0.f;
    }
    __syncthreads();
#pragma unroll
    for (int j = 0; j < 32; j += 8) {
        float fv = t[tx][ty + j];
        size_t o = (size_t)(c0 + ty + j) * Rp + r0 + tx;
        bf16 h = __float2bfloat16(fv);
        hi[o] = h;
        lo[o] = __float2bfloat16(fv - __bfloat162float(h));
    }
}

// ============ batched multi-job fp32 -> bf16 hi/lo tile converter ============
struct WJob { const float* src; bf16* hi; bf16* lo; int R; int C; int T; int ldd; };
struct WArgs { WJob j[8]; int tend[8]; };

__global__ void __launch_bounds__(256) wprep_k(WArgs a)
{
    __shared__ float t[32][33];
    int tt = (int)blockIdx.x;
    int ji = 0;
    while (tt >= a.tend[ji]) ++ji;
    const int base = ji ? a.tend[ji - 1] : 0;
    const int lt = tt - base;
    const WJob J = a.j[ji];
    const int tpr = J.C >> 5;
    const int tr = lt / tpr, tcq = lt - tr * tpr;
    const int r0 = tr << 5, c0 = tcq << 5;
    const int tid = threadIdx.x;
    const int lr = tid >> 3;
    const int lc = (tid & 7) << 2;
    float4 v = *reinterpret_cast<const float4*>(J.src + (size_t)(r0 + lr) * J.C + c0 + lc);
    if (!J.T) {
        __align__(8) bf16 h4[4], l4[4];
        float vv[4] = {v.x, v.y, v.z, v.w};
#pragma unroll
        for (int k = 0; k < 4; ++k) {
            bf16 hb = __float2bfloat16(vv[k]);
            h4[k] = hb;
            l4[k] = __float2bfloat16(vv[k] - __bfloat162float(hb));
        }
        size_t o = (size_t)(r0 + lr) * J.ldd + c0 + lc;
        *reinterpret_cast<uint2*>(J.hi + o) = *reinterpret_cast<const uint2*>(h4);
        *reinterpret_cast<uint2*>(J.lo + o) = *reinterpret_cast<const uint2*>(l4);
    } else {
        t[lr][lc] = v.x; t[lr][lc + 1] = v.y; t[lr][lc + 2] = v.z; t[lr][lc + 3] = v.w;
        __syncthreads();
        const int oc  = tid >> 3;
        const int seg = (tid & 7) << 2;
        __align__(8) bf16 h4[4], l4[4];
#pragma unroll
        for (int k = 0; k < 4; ++k) {
            float f = t[seg + k][oc];
            bf16 hb = __float2bfloat16(f);
            h4[k] = hb;
            l4[k] = __float2bfloat16(f - __bfloat162float(hb));
        }
        size_t o = (size_t)(c0 + oc) * J.ldd + r0 + seg;
        *reinterpret_cast<uint2*>(J.hi + o) = *reinterpret_cast<const uint2*>(h4);
        *reinterpret_cast<uint2*>(J.lo + o) = *reinterpret_cast<const uint2*>(l4);
    }
}

// ================= fused activation + transpose kernels (vectorized) =========
__device__ __forceinline__ void split8(const float* v, uint4& hq, uint4& lq)
{
    __align__(16) bf16 hv[8];
    __align__(16) bf16 lv[8];
#pragma unroll
    for (int j = 0; j < 8; ++j) {
        bf16 hb_ = __float2bfloat16(v[j]);
        hv[j] = hb_;
        lv[j] = __float2bfloat16(v[j] - __bfloat162float(hb_));
    }
    hq = *reinterpret_cast<const uint4*>(hv);
    lq = *reinterpret_cast<const uint4*>(lv);
}

__global__ void __launch_bounds__(256) swishT_k(
    const float* __restrict__ kg, const float* __restrict__ kv,
    bf16* __restrict__ hhi, bf16* __restrict__ hlo,
    bf16* __restrict__ thi, bf16* __restrict__ tlo)
{
    __shared__ float t[64][33];
    const int c0 = blockIdx.x * 64;
    const int r0 = blockIdx.y * 32;
    const int tid = threadIdx.x;
    const int cg = tid & 7;
    const int r  = tid >> 3;
    const int row = r0 + r;
    const int col = c0 + cg * 8;

    float h8[8];
    if (row < NTOK) {
        const float* pg = kg + (size_t)row * HIDD + col;
        const float* pv = kv + (size_t)row * HIDD + col;
        float4 g0 = *reinterpret_cast<const float4*>(pg);
        float4 g1 = *reinterpret_cast<const float4*>(pg + 4);
        float4 v0 = *reinterpret_cast<const float4*>(pv);
        float4 v1 = *reinterpret_cast<const float4*>(pv + 4);
        float gs[8] = {g0.x, g0.y, g0.z, g0.w, g1.x, g1.y, g1.z, g1.w};
        float vs[8] = {v0.x, v0.y, v0.z, v0.w, v1.x, v1.y, v1.z, v1.w};
#pragma unroll
        for (int j = 0; j < 8; ++j)
            h8[j] = gs[j] / (1.f + __expf(-gs[j])) * vs[j];
    } else {
#pragma unroll
        for (int j = 0; j < 8; ++j) h8[j] = 0.f;
    }
    {
        uint4 hq, lq;
        split8(h8, hq, lq);
        size_t o = (size_t)row * HIDD + col;
        *reinterpret_cast<uint4*>(hhi + o) = hq;
        *reinterpret_cast<uint4*>(hlo + o) = lq;
    }
    if (thi) {
#pragma unroll
        for (int j = 0; j < 8; ++j) t[cg * 8 + j][r] = h8[j];
        __syncthreads();
        const int orow = tid >> 2;
        const int seg  = tid & 3;
        float v8[8];
#pragma unroll
        for (int j = 0; j < 8; ++j) v8[j] = t[orow][seg * 8 + j];
        uint4 hq, lq;
        split8(v8, hq, lq);
        size_t o = (size_t)(c0 + orow) * MP + r0 + seg * 8;
        *reinterpret_cast<uint4*>(thi + o) = hq;
        *reinterpret_cast<uint4*>(tlo + o) = lq;
    }
}

__global__ void __launch_bounds__(256) bw_ewT_k(
    const float* __restrict__ dh,
    const float* __restrict__ kg, const float* __restrict__ kv,
    bf16* __restrict__ gthi, bf16* __restrict__ gtlo,
    bf16* __restrict__ vthi, bf16* __restrict__ vtlo)
{
    __shared__ float tg[64][33];
    __shared__ float tv[64][33];
    const int c0 = blockIdx.x * 64;
    const int r0 = blockIdx.y * 32;
    const int tid = threadIdx.x;
    const int cg = tid & 7;
    const int r  = tid >> 3;
    const int row = r0 + r;
    const int col = c0 + cg * 8;

    if (row < NTOK) {
        const float* pd = dh + (size_t)row * HIDD + col;
        const float* pg = kg + (size_t)row * HIDD + col;
        const float* pv = kv + (size_t)row * HIDD + col;
        float4 d0 = *reinterpret_cast<const float4*>(pd);
        float4 d1 = *reinterpret_cast<const float4*>(pd + 4);
        float4 g0 = *reinterpret_cast<const float4*>(pg);
        float4 g1 = *reinterpret_cast<const float4*>(pg + 4);
        float4 v0 = *reinterpret_cast<const float4*>(pv);
        float4 v1 = *reinterpret_cast<const float4*>(pv + 4);
        float ds[8] = {d0.x, d0.y, d0.z, d0.w, d1.x, d1.y, d1.z, d1.w};
        float gs[8] = {g0.x, g0.y, g0.z, g0.w, g1.x, g1.y, g1.z, g1.w};
        float vs[8] = {v0.x, v0.y, v0.z, v0.w, v1.x, v1.y, v1.z, v1.w};
#pragma unroll
        for (int j = 0; j < 8; ++j) {
            float s = 1.f / (1.f + __expf(-gs[j]));
            tv[cg * 8 + j][r] = ds[j] * gs[j] * s;
            tg[cg * 8 + j][r] = ds[j] * vs[j] * s * (1.f + gs[j] * (1.f - s));
        }
    } else {
#pragma unroll
        for (int j = 0; j < 8; ++j) { tg[cg * 8 + j][r] = 0.f; tv[cg * 8 + j][r] = 0.f; }
    }
    __syncthreads();
    const int orow = tid >> 2;
    const int seg  = tid & 3;
    const size_t o = (size_t)(c0 + orow) * MP + r0 + seg * 8;
    {
        float v8[8];
#pragma unroll
        for (int j = 0; j < 8; ++j) v8[j] = tg[orow][seg * 8 + j];
        uint4 hq, lq;
        split8(v8, hq, lq);
        *reinterpret_cast<uint4*>(gthi + o) = hq;
        *reinterpret_cast<uint4*>(gtlo + o) = lq;
    }
    {
        float v8[8];
#pragma unroll
        for (int j = 0; j < 8; ++j) v8[j] = tv[orow][seg * 8 + j];
        uint4 hq, lq;
        split8(v8, hq, lq);
        *reinterpret_cast<uint4*>(vthi + o) = hq;
        *reinterpret_cast<uint4*>(vtlo + o) = lq;
    }
}

// ================= elementwise / reductions =================
__global__ void norm_heads_k(float* __restrict__ base,
                             const float* __restrict__ sc, const float* __restrict__ bi)
{
    int w = (blockIdx.x * blockDim.x + threadIdx.x) >> 5;
    int lane = threadIdx.x & 31;
    if (w >= NTOK * 16) return;
    int rowi = w >> 4, head = w & 15;
    float* p = base + (size_t)rowi * (3 * DIMM) + head * 64;
    float x0 = p[lane], x1 = p[lane + 32];
    float ss = x0 * x0 + x1 * x1;
#pragma unroll
    for (int o = 16; o; o >>= 1) ss += __shfl_xor_sync(0xffffffffu, ss, o);
    float inv = 1.f / (sqrtf(ss) + 1e-6f);
    p[lane]      = x0 * inv * sc[lane]      + bi[lane];
    p[lane + 32] = x1 * inv * sc[lane + 32] + bi[lane + 32];
}

__global__ void zero3_k(double* p) { if (threadIdx.x < 3) p[threadIdx.x] = 0.0; }

__global__ void sumsq3_k(const float* __restrict__ x, int n, double* __restrict__ out)
{
    __shared__ double sm[256];
    const int z = blockIdx.y;
    x += (size_t)z * n;
    double a = 0.0;
    for (int i = blockIdx.x * blockDim.x + threadIdx.x; i < n; i += gridDim.x * blockDim.x) {
        float fv = x[i];
        a += (double)fv * (double)fv;
    }
    sm[threadIdx.x] = a;
    __syncthreads();
    for (int s = 128; s; s >>= 1) {
        if (threadIdx.x < s) sm[threadIdx.x] += sm[threadIdx.x + s];
        __syncthreads();
    }
    if (threadIdx.x == 0) atomicAdd(&out[z], sm[0]);
}

__global__ void scale3_k(const float4* __restrict__ g, float4* __restrict__ X, int n4,
                         const double* __restrict__ nrm)
{
    const int z = blockIdx.y;
    int i = blockIdx.x * blockDim.x + threadIdx.x;
    if (i >= n4) return;
    float inv = (float)(1.0 / (sqrt(nrm[z]) + 1e-7));
    float4 fv = g[(size_t)z * n4 + i];
    fv.x *= inv; fv.y *= inv; fv.z *= inv; fv.w *= inv;
    X[(size_t)z * n4 + i] = fv;
}

__global__ void transpose_k(const float* __restrict__ src, float* __restrict__ dst,
                            int R, int C)
{
    __shared__ float t[32][33];
    int c0 = blockIdx.x * 32, r0 = blockIdx.y * 32;
    int x = c0 + threadIdx.x;
#pragma unroll
    for (int j = 0; j < 32; j += 8)
        t[threadIdx.y + j][threadIdx.x] = src[(size_t)(r0 + threadIdx.y + j) * C + x];
    __syncthreads();
    int x2 = r0 + threadIdx.x;
#pragma unroll
    for (int j = 0; j < 32; j += 8)
        dst[(size_t)(c0 + threadIdx.y + j) * R + x2] = t[threadIdx.x][threadIdx.y + j];
}

__global__ void upd_k(float4* __restrict__ p, const float4* __restrict__ x, int n4)
{
    int i = blockIdx.x * blockDim.x + threadIdx.x;
    if (i >= n4) return;
    float4 a = p[i], bb = x[i];
    a.x -= LRATE * bb.x; a.y -= LRATE * bb.y; a.z -= LRATE * bb.z; a.w -= LRATE * bb.w;
    p[i] = a;
}

// ================= host orchestration =================
struct BP { bf16 *hi, *lo; };

static void* symaddr(const void* s) { void* p = nullptr; cudaGetSymbolAddress(&p, s); return p; }

static void tc(BP A, BP B, int Kp, float* C, int ldc, int M, int N,
               float alpha, float beta, const float* E, int ldE,
               int nz = 1, i64 az = 0, i64 bz = 0, i64 cz = 0, i64 ez = 0,
               BP O = {nullptr, nullptr}, int ldo = 0, i64 oz = 0,
               BP OT = {nullptr, nullptr}, int ldot = 0, i64 ozt = 0,
               int terms = 3)
{
    dim3 gr(N / 256, (M + 127) / 128, nz);
    tc_gemm<<<gr, 256, TC_SMEM>>>(A.hi, A.lo, B.hi, B.lo, Kp, C, ldc, E, ldE,
                                  alpha, beta, M, az, bz, cz, ez, O.hi, O.lo, ldo, oz,
                                  OT.hi, OT.lo, ldot, ozt, terms);
}

static void conv(const float* s, int ld, int R, int C, BP d, int Rp, int Cp,
                 int nz = 1, i64 sZ = 0, i64 dZ = 0)
{
    dim3 gr((Cp / 4 + 255) / 256, Rp, nz);
    conv_k<<<gr, 256>>>(s, ld, R, C, d.hi, d.lo, Cp, sZ, dZ);
}

static void convT(const float* s, int ld, int R, int C, BP d, int Rp,
                  int nz = 1, i64 sZ = 0, i64 dZ = 0)
{
    dim3 gr(C / 32, Rp / 32, nz);
    convT_k<<<gr, dim3(32, 8)>>>(s, ld, R, C, d.hi, d.lo, Rp, sZ, dZ);
}

static void wadd(WArgs& a, int& n, int& tot,
                 const float* s, BP d, int R, int C, int T, int ldd)
{
    a.j[n].src = s; a.j[n].hi = d.hi; a.j[n].lo = d.lo;
    a.j[n].R = R; a.j[n].C = C; a.j[n].T = T; a.j[n].ldd = ldd;
    tot += (R >> 5) * (C >> 5);
    a.tend[n] = tot;
    ++n;
}

extern "C" void kernel_launch(void* const* d_in, const int* in_sizes, int n_in,
                              void* d_out, int out_size)
{
    const float* x        = (const float*)d_in[0];
    const float* qkv_w    = (const float*)d_in[1];
    const float* qkv_b    = (const float*)d_in[2];
    const float* qn_s     = (const float*)d_in[3];
    const float* qn_b     = (const float*)d_in[4];
    const float* kn_s     = (const float*)d_in[5];
    const float* kn_b     = (const float*)d_in[6];
    const float* ttt_gate = (const float*)d_in[7];
    const float* ttt_val  = (const float*)d_in[8];
    const float* ttt_proj = (const float*)d_in[9];
    const float* proj_w   = (const float*)d_in[10];
    const float* proj_b   = (const float*)d_in[11];
    float* out = (float*)d_out;

    cudaFuncSetAttribute(tc_gemm, cudaFuncAttributeMaxDynamicSharedMemorySize, TC_SMEM);

    float* qkv  = (float*)symaddr(g_qkv);
    float* kgv  = (float*)symaddr(g_kgv);
    float* h    = (float*)symaddr(g_h);
    float* GV   = (float*)symaddr(g_GV);
    float* P    = (float*)symaddr(g_P);
    float* grad = (float*)symaddr(g_grad);
    float* X1   = (float*)symaddr(g_X1);
    float* X2   = (float*)symaddr(g_X2);
    float* Amat = (float*)symaddr(g_A);
    double* nrm = (double*)symaddr(g_nrm);
    unsigned char* pool = (unsigned char*)symaddr(g_bf);

    auto bp = [&](size_t off, size_t elems) { BP b; b.hi = (bf16*)(pool + off); b.lo = b.hi + elems; return b; };

    BP xb    = bp(O_X, E_TOKD);
    BP kb    = bp(O_K, E_TOKD);
    BP kTb   = bp(O_KT, E_TOKD);
    BP qb    = bp(O_Q, E_TOKD);
    BP rTb   = bp(O_RT, E_TOKD);
    BP hb    = bp(O_H, E_TOKH);
    BP hTb   = bp(O_HT, E_TOKH);
    BP dkgT  = bp(O_DKGT, E_TOKH);
    BP dkvT  = bp(O_DKVT, E_TOKH);
    BP wGt   = bp(O_WGT, E_W);
    BP wP    = bp(O_WP,  E_W);
    BP wPt   = bp(O_WPT, E_W);
    BP qkvwT = bp(O_QKVW, E_QKVW);
    BP projwT = bp(O_PRJW, E_A);
    BP nsX   = bp(O_NSX,  E_W);
    BP nsXTa = bp(O_NSXT, E_W);
    BP nsXTb = bp(O_NSXT2, E_W);
    BP nsA   = bp(O_NSA,  E_A);
    BP nsA2  = bp(O_NSA2, E_A);
    BP NOB   = {nullptr, nullptr};

    const size_t TB = sizeof(float) * E_W;
    cudaMemcpyAsync(GV,       ttt_gate, TB, cudaMemcpyDeviceToDevice, 0);
    cudaMemcpyAsync(GV + E_W, ttt_val,  TB, cudaMemcpyDeviceToDevice, 0);
    cudaMemcpyAsync(P,        ttt_proj, TB, cudaMemcpyDeviceToDevice, 0);

    // ---- qkv = x @ qkv_w + b  (output-path accuracy: full split) ----
    conv (x, DIMM, NTOK, DIMM, xb, MP, DIMM);
    convT(qkv_w, 3 * DIMM, DIMM, 3 * DIMM, qkvwT, DIMM);
    tc(xb, qkvwT, DIMM, qkv, 3 * DIMM, NTOK, 3 * DIMM, 1.f, 1.f, qkv_b, 0);

    {
        int nb = (NTOK * 16 * 32 + 255) / 256;
        norm_heads_k<<<nb, 256>>>(qkv, qn_s, qn_b);
        norm_heads_k<<<nb, 256>>>(qkv + DIMM, kn_s, kn_b);
    }

    const float* kmat = qkv + DIMM;
    const float* vmat = qkv + 2 * DIMM;
    conv (kmat, 3 * DIMM, NTOK, DIMM, kb, MP, DIMM);
    convT(kmat, 3 * DIMM, NTOK, DIMM, kTb, MP);
    conv (qkv, 3 * DIMM, NTOK, DIMM, qb, MP, DIMM);

    const dim3 grTH(HIDD / 64, MP / 32);
    const i64 ZW = 2 * (i64)E_W;
    const i64 ZA = 2 * (i64)E_A;
    const i64 KGV = (i64)NTOK * HIDD;

    for (int step = 0; step < 2; ++step) {
        // ---- merged weight prep: {G^T, V^T, P, P^T} in one launch ----
        {
            WArgs wa{}; int n = 0, tot = 0;
            wadd(wa, n, tot, GV,        wGt, DIMM, HIDD, 1, DIMM);
            wadd(wa, n, tot, GV + E_W,  {wGt.hi + ZW, wGt.lo + ZW}, DIMM, HIDD, 1, DIMM);
            wadd(wa, n, tot, P,         wP,  HIDD, DIMM, 0, DIMM);
            wadd(wa, n, tot, P,         wPt, HIDD, DIMM, 1, HIDD);
            wprep_k<<<tot, 256>>>(wa);
        }

        // kg|kv = k @ {G,V}  (full split — gradient-input path is amplified by NS)
        tc(kb, wGt, DIMM, kgv, HIDD, NTOK, HIDD, 1.f, 0.f, nullptr, 0,
           2, 0, ZW, KGV, 0);
        swishT_k<<<grTH, 256>>>(kgv, kgv + KGV, hb.hi, hb.lo, hTb.hi, hTb.lo);
        // r = h @ P - v : pairs (xb) + transposed pairs (rTb)
        tc(hb, wPt, HIDD, nullptr, 0, NTOK, DIMM, 1.f, -1.f, vmat, 3 * DIMM,
           1, 0, 0, 0, 0, xb, DIMM, 0, rTb, MP, 0);
        // gP^T = r^T @ h
        tc(rTb, hTb, MP, grad + 2 * E_W, HIDD, DIMM, HIDD, 1.f, 0.f, nullptr, 0);
        // dh = r @ P^T  -> h buffer
        tc(xb, wP, DIMM, h, HIDD, NTOK, HIDD, 1.f, 0.f, nullptr, 0);
        bw_ewT_k<<<grTH, 256>>>(h, kgv, kgv + KGV,
                                dkgT.hi, dkgT.lo, dkvT.hi, dkvT.lo);
        // gG|gV = k^T @ {dkg,dkv}
        tc(kTb, dkgT, MP, grad, HIDD, DIMM, HIDD, 1.f, 0.f, nullptr, 0,
           2, 0, 2 * (i64)E_TOKH, (i64)E_W, 0);

        // ---- batched Newton-Schulz over {gG, gV, gP^T} ----
        zero3_k<<<1, 4>>>(nrm);
        sumsq3_k<<<dim3(256, 3), 256>>>(grad, (int)E_W, nrm);
        scale3_k<<<dim3(((int)E_W / 4 + 255) / 256, 3), 256>>>(
            (const float4*)grad, (float4*)X1, (int)E_W / 4, nrm);
        float* X = X1;
        float* Y = X2;
        // merged NS X prep: conv x3 + convT x3 in one launch
        {
            WArgs na{}; int n = 0, tot = 0;
            for (int z = 0; z < 3; ++z)
                wadd(na, n, tot, X + z * E_W,
                     {nsX.hi + z * ZW, nsX.lo + z * ZW}, DIMM, HIDD, 0, HIDD);
            for (int z = 0; z < 3; ++z)
                wadd(na, n, tot, X + z * E_W,
                     {nsXTa.hi + z * ZW, nsXTa.lo + z * ZW}, DIMM, HIDD, 1, DIMM);
            wprep_k<<<tot, 256>>>(na);
        }
        for (int it = 0; it < 5; ++it) {
            BP XTin  = (it & 1) ? nsXTb : nsXTa;
            BP XTout = (it & 1) ? nsXTa : nsXTb;
            // it0-2: hi-only (validated in R14: >=2 subsequent NS steps damp the error);
            // it3-4: full split (R16 showed it3 errors reach theta nearly undamped)
            const int tm = (it < 3) ? 1 : 3;
            tc(nsX, nsX, HIDD, Amat, DIMM, DIMM, DIMM, 1.f, 0.f, nullptr, 0,
               3, ZW, ZW, (i64)E_A, 0, nsA, DIMM, ZA, NOB, 0, 0, tm);
            tc(nsA, nsA, DIMM, nullptr, 0, DIMM, DIMM, NS_C, NS_B, Amat, DIMM,
               3, ZA, ZA, 0, (i64)E_A, nsA2, DIMM, ZA, NOB, 0, 0, tm);
            tc(nsA2, XTin, DIMM, Y, HIDD, DIMM, HIDD, 1.f, NS_A, X, HIDD,
               3, ZA, ZW, (i64)E_W, (i64)E_W, nsX, HIDD, ZW,
               (it < 4) ? XTout : NOB, DIMM, ZW, tm);
            float* t = X; X = Y; Y = t;
        }
        upd_k<<<((int)(2 * E_W / 4) + 255) / 256, 256>>>((float4*)GV, (const float4*)X, (int)(2 * E_W / 4));
        {
            dim3 gr(HIDD / 32, DIMM / 32);
            transpose_k<<<gr, dim3(32, 8)>>>(X + 2 * E_W, Y, DIMM, HIDD);
            upd_k<<<((int)(E_W / 4) + 255) / 256, 256>>>((float4*)P, (const float4*)Y, (int)(E_W / 4));
        }
    }

    // ---- final forward with q (output path: full split) ----
    {
        WArgs fa{}; int n = 0, tot = 0;
        wadd(fa, n, tot, GV,       wGt, DIMM, HIDD, 1, DIMM);
        wadd(fa, n, tot, GV + E_W, {wGt.hi + ZW, wGt.lo + ZW}, DIMM, HIDD, 1, DIMM);
        wadd(fa, n, tot, P,        wPt, HIDD, DIMM, 1, HIDD);
        wprep_k<<<tot, 256>>>(fa);
    }
    tc(qb, wGt, DIMM, kgv, HIDD, NTOK, HIDD, 1.f, 0.f, nullptr, 0,
       2, 0, ZW, KGV, 0);
    swishT_k<<<grTH, 256>>>(kgv, kgv + KGV, hb.hi, hb.lo, nullptr, nullptr);
    tc(hb, wPt, HIDD, nullptr, 0, NTOK, DIMM, 1.f, 0.f, nullptr, 0,
       1, 0, 0, 0, 0, xb, DIMM, 0);
    convT(proj_w, DIMM, DIMM, DIMM, projwT, DIMM);
    tc(xb, projwT, DIMM, out, DIMM, NTOK, DIMM, 1.f, 1.f, proj_b, 0);
}